// round 1
// baseline (speedup 1.0000x reference)
#include <cuda_runtime.h>
#include <math.h>
#include <float.h>

#define NN   50000
#define DD   128
#define NE   800000
#define NE2  (NE + NN)          // 850000 edges incl. self loops
#define TOTF (NN * DD)          // 6,400,000

// ---------------- scratch (static device allocations only) ----------------
__device__ float  g_xw[TOTF];
__device__ float  g_h1[TOTF];
__device__ float  g_h2[TOTF];
__device__ float  g_xl[TOTF];
__device__ float  g_xr[TOTF];
__device__ float  g_score[(size_t)NE2 * 8];
__device__ float  g_dinv[NN];
__device__ int    g_deg[NN];
__device__ float  g_smax[NN * 8];
__device__ float  g_denom[NN * 8];
__device__ double g_red[2];

// ---------------- helpers ----------------
__device__ __forceinline__ float lrelu(float x) { return x > 0.f ? x : 0.2f * x; }

__device__ __forceinline__ void atomicMaxFloat(float* addr, float val) {
    if (val >= 0.f) atomicMax((int*)addr, __float_as_int(val));
    else            atomicMin((unsigned int*)addr, (unsigned int)__float_as_int(val));
}

__device__ __forceinline__ void red_add_v4(float* p, float a, float b, float c, float d) {
    asm volatile("red.global.add.v4.f32 [%0], {%1, %2, %3, %4};"
                 :: "l"(p), "f"(a), "f"(b), "f"(c), "f"(d) : "memory");
}

// ---------------- degree ----------------
__global__ void zero_deg_kernel() {
    int i = blockIdx.x * blockDim.x + threadIdx.x;
    if (i < NN) g_deg[i] = 0;
}
__global__ void count_deg_kernel(const int* __restrict__ dst) {
    int e = blockIdx.x * blockDim.x + threadIdx.x;
    if (e < NE) atomicAdd(&g_deg[dst[e]], 1);
}
__global__ void dinv_kernel() {
    int i = blockIdx.x * blockDim.x + threadIdx.x;
    if (i < NN) g_dinv[i] = rsqrtf((float)(g_deg[i] + 1));  // +1 self loop
}

// ---------------- GEMM: C[M,128] = A[M,128] @ W[128,128] (+bias) ----------------
// 256 threads/block, 64x128 tile, each thread 8x4 outputs.
__global__ void gemm_bias_kernel(const float* __restrict__ A, const float* __restrict__ W,
                                 const float* __restrict__ bias, float* __restrict__ C, int M)
{
    __shared__ float As[16][65];    // k-major, padded
    __shared__ float Bs[16][128];
    int m0  = blockIdx.x * 64;
    int tid = threadIdx.x;
    int ty  = tid >> 5;    // 0..7
    int tx  = tid & 31;    // 0..31
    float acc[8][4];
#pragma unroll
    for (int r = 0; r < 8; r++)
#pragma unroll
        for (int c = 0; c < 4; c++) acc[r][c] = 0.f;

    for (int k0 = 0; k0 < 128; k0 += 16) {
#pragma unroll
        for (int i = 0; i < 4; i++) {
            int idx = tid + i * 256;      // 0..1023
            int m = idx >> 4, k = idx & 15;
            float v = 0.f;
            if (m0 + m < M) v = A[(size_t)(m0 + m) * 128 + k0 + k];
            As[k][m] = v;
        }
#pragma unroll
        for (int i = 0; i < 8; i++) {
            int idx = tid + i * 256;      // 0..2047
            int k = idx >> 7, n = idx & 127;
            Bs[k][n] = W[(size_t)(k0 + k) * 128 + n];
        }
        __syncthreads();
#pragma unroll
        for (int k = 0; k < 16; k++) {
            float b[4];
#pragma unroll
            for (int c = 0; c < 4; c++) b[c] = Bs[k][tx + 32 * c];
#pragma unroll
            for (int r = 0; r < 8; r++) {
                float a = As[k][ty * 8 + r];
#pragma unroll
                for (int c = 0; c < 4; c++) acc[r][c] += a * b[c];
            }
        }
        __syncthreads();
    }
#pragma unroll
    for (int r = 0; r < 8; r++) {
        int m = m0 + ty * 8 + r;
        if (m < M) {
#pragma unroll
            for (int c = 0; c < 4; c++) {
                int n = tx + 32 * c;
                float v = acc[r][c];
                if (bias) v += bias[n];
                C[(size_t)m * 128 + n] = v;
            }
        }
    }
}

// ---------------- GCN ----------------
__global__ void gcn_init_kernel(const float* __restrict__ xw, const float* __restrict__ bias,
                                float* __restrict__ out)
{
    int i = blockIdx.x * blockDim.x + threadIdx.x;
    if (i >= TOTF) return;
    int n = i >> 7;
    float di = g_dinv[n];
    out[i] = bias[i & 127] + xw[i] * di * di;   // bias + self-loop term
}

__global__ void gcn_edge_kernel(const float* __restrict__ xw, const int* __restrict__ src,
                                const int* __restrict__ dst, float* __restrict__ out)
{
    int gid = blockIdx.x * blockDim.x + threadIdx.x;   // NE*32 threads exactly
    int e = gid >> 5;
    if (e >= NE) return;
    int c = (gid & 31) * 4;
    int s = src[e], d = dst[e];
    float nrm = g_dinv[s] * g_dinv[d];
    float4 v = *(const float4*)(xw + (size_t)s * 128 + c);
    red_add_v4(out + (size_t)d * 128 + c, v.x * nrm, v.y * nrm, v.z * nrm, v.w * nrm);
}

// ---------------- GATv2 ----------------
__global__ void gat_init_kernel(float* __restrict__ out, const float* __restrict__ bias, int NH)
{
    int i = blockIdx.x * blockDim.x + threadIdx.x;
    if (i < NH) { g_smax[i] = -FLT_MAX; g_denom[i] = 0.f; }
    if (i < TOTF) out[i] = bias[i & 127];
}

template <int H>
__global__ void gat_score_kernel(const float* __restrict__ xl, const float* __restrict__ xr,
                                 const float* __restrict__ att,
                                 const int* __restrict__ src, const int* __restrict__ dst)
{
    int gid = blockIdx.x * blockDim.x + threadIdx.x;   // NE2*32 threads exactly
    int e = gid >> 5;
    if (e >= NE2) return;
    int lane = gid & 31;
    int s, d;
    if (e < NE) { s = src[e]; d = dst[e]; } else { s = d = e - NE; }
    int c = lane * 4;
    float4 a = *(const float4*)(xl + (size_t)s * 128 + c);
    float4 b = *(const float4*)(xr + (size_t)d * 128 + c);
    float4 w = *(const float4*)(att + c);
    float p = w.x * lrelu(a.x + b.x) + w.y * lrelu(a.y + b.y)
            + w.z * lrelu(a.z + b.z) + w.w * lrelu(a.w + b.w);
    const int LPH = 32 / H;   // lanes per head
#pragma unroll
    for (int off = LPH / 2; off > 0; off >>= 1)
        p += __shfl_xor_sync(0xffffffffu, p, off);
    if ((lane & (LPH - 1)) == 0) {
        int h = lane / LPH;
        g_score[(size_t)e * H + h] = p;
        atomicMaxFloat(&g_smax[d * H + h], p);
    }
}

template <int H>
__global__ void gat_exp_kernel(const int* __restrict__ dst)
{
    int gid = blockIdx.x * blockDim.x + threadIdx.x;
    if (gid >= NE2 * H) return;
    int e = gid / H;
    int h = gid - e * H;
    int d = (e < NE) ? dst[e] : e - NE;
    float a = expf(g_score[gid] - g_smax[d * H + h]);
    g_score[gid] = a;
    atomicAdd(&g_denom[d * H + h], a);
}

template <int H>
__global__ void gat_scatter_kernel(const float* __restrict__ xl,
                                   const int* __restrict__ src, const int* __restrict__ dst,
                                   float* __restrict__ out)
{
    int gid = blockIdx.x * blockDim.x + threadIdx.x;   // NE2*32 threads exactly
    int e = gid >> 5;
    if (e >= NE2) return;
    int lane = gid & 31;
    int s, d;
    if (e < NE) { s = src[e]; d = dst[e]; } else { s = d = e - NE; }
    const int LPH = 32 / H;
    int h = lane / LPH;
    float alpha = g_score[(size_t)e * H + h] / g_denom[d * H + h];
    int c = lane * 4;
    float4 v = *(const float4*)(xl + (size_t)s * 128 + c);
    red_add_v4(out + (size_t)d * 128 + c, v.x * alpha, v.y * alpha, v.z * alpha, v.w * alpha);
}

// ---------------- graph LayerNorm ----------------
__global__ void zero_red_kernel() { g_red[0] = 0.0; g_red[1] = 0.0; }

__global__ void ln_reduce_kernel(const float* __restrict__ x)
{
    float s = 0.f, sq = 0.f;
    for (int i = blockIdx.x * blockDim.x + threadIdx.x; i < TOTF; i += gridDim.x * blockDim.x) {
        float v = x[i];
        s += v; sq += v * v;
    }
    __shared__ float sh[256], shq[256];
    sh[threadIdx.x] = s; shq[threadIdx.x] = sq;
    __syncthreads();
    for (int o = 128; o > 0; o >>= 1) {
        if (threadIdx.x < o) { sh[threadIdx.x] += sh[threadIdx.x + o]; shq[threadIdx.x] += shq[threadIdx.x + o]; }
        __syncthreads();
    }
    if (threadIdx.x == 0) {
        atomicAdd(&g_red[0], (double)sh[0]);
        atomicAdd(&g_red[1], (double)shq[0]);
    }
}

__global__ void ln_norm_kernel(float* __restrict__ x, const float* __restrict__ g,
                               const float* __restrict__ b, int relu)
{
    int i = blockIdx.x * blockDim.x + threadIdx.x;
    if (i >= TOTF) return;
    double m   = g_red[0] / (double)TOTF;
    double var = g_red[1] / (double)TOTF - m * m;
    float stdv = (float)sqrt(fmax(var, 0.0));
    float inv  = 1.f / (stdv + 1e-5f);
    int c = i & 127;
    float y = (x[i] - (float)m) * inv * g[c] + b[c];
    if (relu) y = fmaxf(y, 0.f);
    x[i] = y;
}

// ---------------- host orchestration ----------------
static void run_ln(float* buf, const float* g, const float* b, bool relu)
{
    zero_red_kernel<<<1, 1>>>();
    ln_reduce_kernel<<<2048, 256>>>(buf);
    ln_norm_kernel<<<TOTF / 256, 256>>>(buf, g, b, relu ? 1 : 0);
}

static void run_gcn(const float* h, const float* W, const float* bias,
                    const int* src, const int* dst, float* xw, float* out)
{
    gemm_bias_kernel<<<(NN + 63) / 64, 256>>>(h, W, nullptr, xw, NN);
    gcn_init_kernel<<<TOTF / 256, 256>>>(xw, bias, out);
    gcn_edge_kernel<<<(NE * 32) / 256, 256>>>(xw, src, dst, out);
}

template <int H>
static void run_gat(const float* h, const float* Wl, const float* bl,
                    const float* Wr, const float* br, const float* att, const float* bg,
                    const int* src, const int* dst, float* xl, float* xr, float* out)
{
    gemm_bias_kernel<<<(NN + 63) / 64, 256>>>(h, Wl, bl, xl, NN);
    gemm_bias_kernel<<<(NN + 63) / 64, 256>>>(h, Wr, br, xr, NN);
    gat_init_kernel<<<TOTF / 256, 256>>>(out, bg, NN * H);
    gat_score_kernel<H><<<(NE2 * 32) / 256, 256>>>(xl, xr, att, src, dst);
    gat_exp_kernel<H><<<(NE2 * H + 255) / 256, 256>>>(dst);
    gat_scatter_kernel<H><<<(NE2 * 32) / 256, 256>>>(xl, src, dst, out);
}

extern "C" void kernel_launch(void* const* d_in, const int* in_sizes, int n_in,
                              void* d_out, int out_size)
{
    const float* x    = (const float*)d_in[0];
    const int*   ei   = (const int*)  d_in[1];
    const float* W0   = (const float*)d_in[2];
    const float* b0   = (const float*)d_in[3];
    const float* g0   = (const float*)d_in[4];
    const float* be0  = (const float*)d_in[5];
    const float* Wl1  = (const float*)d_in[6];
    const float* bl1  = (const float*)d_in[7];
    const float* Wr1  = (const float*)d_in[8];
    const float* br1  = (const float*)d_in[9];
    const float* att1 = (const float*)d_in[10];
    const float* bg1  = (const float*)d_in[11];
    const float* g1   = (const float*)d_in[12];
    const float* be1  = (const float*)d_in[13];
    const float* W2   = (const float*)d_in[14];
    const float* b2   = (const float*)d_in[15];
    const float* g2   = (const float*)d_in[16];
    const float* be2  = (const float*)d_in[17];
    const float* Wl3  = (const float*)d_in[18];
    const float* bl3  = (const float*)d_in[19];
    const float* Wr3  = (const float*)d_in[20];
    const float* br3  = (const float*)d_in[21];
    const float* att3 = (const float*)d_in[22];
    const float* bg3  = (const float*)d_in[23];
    const float* g3   = (const float*)d_in[24];
    const float* be3  = (const float*)d_in[25];

    const int* src = ei;          // edge_index[0]
    const int* dst = ei + NE;     // edge_index[1]
    float* out = (float*)d_out;

    float *xw, *h1, *h2, *xl, *xr;
    cudaGetSymbolAddress((void**)&xw, g_xw);
    cudaGetSymbolAddress((void**)&h1, g_h1);
    cudaGetSymbolAddress((void**)&h2, g_h2);
    cudaGetSymbolAddress((void**)&xl, g_xl);
    cudaGetSymbolAddress((void**)&xr, g_xr);

    // degrees (with self loops)
    zero_deg_kernel<<<(NN + 255) / 256, 256>>>();
    count_deg_kernel<<<NE / 256, 256>>>(dst);
    dinv_kernel<<<(NN + 255) / 256, 256>>>();

    // layer 0: GCN -> LN -> relu     (x -> h1)
    run_gcn(x, W0, b0, src, dst, xw, h1);
    run_ln(h1, g0, be0, true);

    // layer 1: GATv2 H=8 concat -> LN -> relu   (h1 -> h2)
    run_gat<8>(h1, Wl1, bl1, Wr1, br1, att1, bg1, src, dst, xl, xr, h2);
    run_ln(h2, g1, be1, true);

    // layer 2: GCN -> LN -> relu     (h2 -> h1)
    run_gcn(h2, W2, b2, src, dst, xw, h1);
    run_ln(h1, g2, be2, true);

    // layer 3: GATv2 H=1 mean -> LN  (h1 -> out)
    run_gat<1>(h1, Wl3, bl3, Wr3, br3, att3, bg3, src, dst, xl, xr, out);
    run_ln(out, g3, be3, false);
}

// round 2
// speedup vs baseline: 2.1781x; 2.1781x over previous
#include <cuda_runtime.h>
#include <math.h>
#include <float.h>

#define NN   50000
#define DD   128
#define NE   800000
#define TOTF (NN * DD)          // 6,400,000
#define NBLK 196                // ceil(NN/256)

// ---------------- scratch (static device globals only) ----------------
__device__ float  g_xw[TOTF];
__device__ float  g_h1[TOTF];
__device__ float  g_h2[TOTF];
__device__ float  g_xl[TOTF];
__device__ float  g_xr[TOTF];
__device__ float  g_dinv[NN];
__device__ int    g_cnt[NN];
__device__ int    g_ptr[NN + 1];
__device__ int    g_ptr2[NN];
__device__ int    g_csr_src[NE];
__device__ int    g_bsum[NBLK];
__device__ int    g_bsum2[NBLK];
__device__ double g_red[2];

// ---------------- helpers ----------------
__device__ __forceinline__ float lrelu(float x) { return x > 0.f ? x : 0.2f * x; }

__device__ __forceinline__ unsigned f2tf(float x) {
    unsigned u; asm("cvt.rna.tf32.f32 %0, %1;" : "=r"(u) : "f"(x)); return u;
}

__device__ __forceinline__ void mma_tf32(float* d, const unsigned* a, const unsigned* b) {
    asm volatile("mma.sync.aligned.m16n8k8.row.col.f32.tf32.tf32.f32 "
                 "{%0,%1,%2,%3}, {%4,%5,%6,%7}, {%8,%9}, {%0,%1,%2,%3};"
                 : "+f"(d[0]), "+f"(d[1]), "+f"(d[2]), "+f"(d[3])
                 : "r"(a[0]), "r"(a[1]), "r"(a[2]), "r"(a[3]),
                   "r"(b[0]), "r"(b[1]));
}

// ---------------- CSR build ----------------
__global__ void zero_cnt_kernel() {
    int i = blockIdx.x * blockDim.x + threadIdx.x;
    if (i < NN) g_cnt[i] = 0;
}
__global__ void hist_kernel(const int* __restrict__ dst) {
    int e = blockIdx.x * blockDim.x + threadIdx.x;
    if (e < NE) atomicAdd(&g_cnt[dst[e]], 1);
}
__global__ void dinv_kernel() {
    int i = blockIdx.x * blockDim.x + threadIdx.x;
    if (i < NN) g_dinv[i] = rsqrtf((float)(g_cnt[i] + 1));  // +1 self loop
}
// block-wise exclusive scan of g_cnt -> g_ptr, block sums -> g_bsum
__global__ void scan1_kernel() {
    __shared__ int sh[256];
    int i = blockIdx.x * 256 + threadIdx.x;
    int v = (i < NN) ? g_cnt[i] : 0;
    sh[threadIdx.x] = v;
    __syncthreads();
#pragma unroll
    for (int off = 1; off < 256; off <<= 1) {
        int t = (threadIdx.x >= off) ? sh[threadIdx.x - off] : 0;
        __syncthreads();
        sh[threadIdx.x] += t;
        __syncthreads();
    }
    if (i < NN) g_ptr[i] = sh[threadIdx.x] - v;   // exclusive
    if (threadIdx.x == 255) g_bsum[blockIdx.x] = sh[255];
}
__global__ void scan2_kernel() {
    __shared__ int sh[256];
    int t = threadIdx.x;
    int v = (t < NBLK) ? g_bsum[t] : 0;
    sh[t] = v;
    __syncthreads();
#pragma unroll
    for (int off = 1; off < 256; off <<= 1) {
        int tv = (t >= off) ? sh[t - off] : 0;
        __syncthreads();
        sh[t] += tv;
        __syncthreads();
    }
    if (t < NBLK) g_bsum2[t] = sh[t] - v;         // exclusive
}
__global__ void scan3_kernel() {
    int i = blockIdx.x * blockDim.x + threadIdx.x;
    if (i < NN) {
        int p = g_ptr[i] + g_bsum2[i >> 8];
        g_ptr[i] = p;
        g_ptr2[i] = p;
    }
    if (i == 0) g_ptr[NN] = NE;
}
__global__ void scatter_kernel(const int* __restrict__ src, const int* __restrict__ dst) {
    int e = blockIdx.x * blockDim.x + threadIdx.x;
    if (e >= NE) return;
    int d = dst[e];
    int pos = atomicAdd(&g_ptr2[d], 1);
    g_csr_src[pos] = src[e];
}

// ---------------- TF32 GEMM: C[M,128] = A[M,128] @ W[128,128] (+bias) ----------------
// 256 threads, 128xM tile, warps 4x2 over (M=32, N=64) each.
__global__ void gemm_tf32_kernel(const float* __restrict__ A, const float* __restrict__ W,
                                 const float* __restrict__ bias, float* __restrict__ C, int M)
{
    __shared__ unsigned As[128][40];   // [row][k], pad to 40
    __shared__ unsigned Bs[32][132];   // [k][col], pad to 132
    int tid  = threadIdx.x;
    int wid  = tid >> 5, lane = tid & 31;
    int wm   = wid & 3, wn = wid >> 2;
    int m0   = blockIdx.x * 128;

    float acc[2][8][4];
#pragma unroll
    for (int i = 0; i < 2; i++)
#pragma unroll
        for (int j = 0; j < 8; j++)
#pragma unroll
            for (int q = 0; q < 4; q++) acc[i][j][q] = 0.f;

    for (int k0 = 0; k0 < 128; k0 += 32) {
#pragma unroll
        for (int i = 0; i < 4; i++) {
            int lin = tid + i * 256;            // 0..1023
            int r = lin >> 3, q = (lin & 7) * 4;
            float4 v = make_float4(0.f, 0.f, 0.f, 0.f);
            if (m0 + r < M) v = *(const float4*)(A + (size_t)(m0 + r) * 128 + k0 + q);
            As[r][q + 0] = f2tf(v.x); As[r][q + 1] = f2tf(v.y);
            As[r][q + 2] = f2tf(v.z); As[r][q + 3] = f2tf(v.w);
        }
#pragma unroll
        for (int i = 0; i < 4; i++) {
            int lin = tid + i * 256;            // 0..1023
            int r = lin >> 5, q = (lin & 31) * 4;
            float4 v = *(const float4*)(W + (size_t)(k0 + r) * 128 + q);
            Bs[r][q + 0] = f2tf(v.x); Bs[r][q + 1] = f2tf(v.y);
            Bs[r][q + 2] = f2tf(v.z); Bs[r][q + 3] = f2tf(v.w);
        }
        __syncthreads();
#pragma unroll
        for (int kk = 0; kk < 32; kk += 8) {
            unsigned a[2][4], b[8][2];
            int ar = wm * 32 + (lane >> 2);
            int ak = kk + (lane & 3);
            a[0][0] = As[ar][ak];      a[0][1] = As[ar + 8][ak];
            a[0][2] = As[ar][ak + 4];  a[0][3] = As[ar + 8][ak + 4];
            a[1][0] = As[ar + 16][ak];     a[1][1] = As[ar + 24][ak];
            a[1][2] = As[ar + 16][ak + 4]; a[1][3] = As[ar + 24][ak + 4];
#pragma unroll
            for (int j = 0; j < 8; j++) {
                int col = wn * 64 + j * 8 + (lane >> 2);
                b[j][0] = Bs[kk + (lane & 3)][col];
                b[j][1] = Bs[kk + 4 + (lane & 3)][col];
            }
#pragma unroll
            for (int i = 0; i < 2; i++)
#pragma unroll
                for (int j = 0; j < 8; j++) mma_tf32(acc[i][j], a[i], b[j]);
        }
        __syncthreads();
    }

#pragma unroll
    for (int i = 0; i < 2; i++) {
#pragma unroll
        for (int j = 0; j < 8; j++) {
            int r0 = m0 + wm * 32 + i * 16 + (lane >> 2);
            int cc = wn * 64 + j * 8 + (lane & 3) * 2;
            float b0 = bias ? bias[cc] : 0.f;
            float b1 = bias ? bias[cc + 1] : 0.f;
            if (r0 < M) {
                C[(size_t)r0 * 128 + cc]     = acc[i][j][0] + b0;
                C[(size_t)r0 * 128 + cc + 1] = acc[i][j][1] + b1;
            }
            if (r0 + 8 < M) {
                C[(size_t)(r0 + 8) * 128 + cc]     = acc[i][j][2] + b0;
                C[(size_t)(r0 + 8) * 128 + cc + 1] = acc[i][j][3] + b1;
            }
        }
    }
}

// ---------------- GCN gather (warp per node) ----------------
__global__ void gcn_gather_kernel(const float* __restrict__ xw, const float* __restrict__ bias,
                                  float* __restrict__ out)
{
    int warp = (blockIdx.x * blockDim.x + threadIdx.x) >> 5;
    if (warp >= NN) return;
    int lane = threadIdx.x & 31;
    int n = warp;
    int c = lane * 4;
    float dn = g_dinv[n];
    float4 acc = *(const float4*)(xw + (size_t)n * 128 + c);
    float w0 = dn * dn;
    acc.x *= w0; acc.y *= w0; acc.z *= w0; acc.w *= w0;   // self loop

    int e = g_ptr[n], end = g_ptr[n + 1];
    for (; e + 1 < end; e += 2) {
        int s0 = g_csr_src[e], s1 = g_csr_src[e + 1];
        float w1 = g_dinv[s0] * dn, w2 = g_dinv[s1] * dn;
        float4 v0 = *(const float4*)(xw + (size_t)s0 * 128 + c);
        float4 v1 = *(const float4*)(xw + (size_t)s1 * 128 + c);
        acc.x += w1 * v0.x + w2 * v1.x;
        acc.y += w1 * v0.y + w2 * v1.y;
        acc.z += w1 * v0.z + w2 * v1.z;
        acc.w += w1 * v0.w + w2 * v1.w;
    }
    if (e < end) {
        int s0 = g_csr_src[e];
        float w1 = g_dinv[s0] * dn;
        float4 v0 = *(const float4*)(xw + (size_t)s0 * 128 + c);
        acc.x += w1 * v0.x; acc.y += w1 * v0.y;
        acc.z += w1 * v0.z; acc.w += w1 * v0.w;
    }
    float4 bv = *(const float4*)(bias + c);
    acc.x += bv.x; acc.y += bv.y; acc.z += bv.z; acc.w += bv.w;
    *(float4*)(out + (size_t)n * 128 + c) = acc;
}

// ---------------- fused GATv2 gather with online softmax (warp per node) ----------------
template <int H>
__global__ void gat_gather_kernel(const float* __restrict__ xl, const float* __restrict__ xr,
                                  const float* __restrict__ att, const float* __restrict__ bg,
                                  float* __restrict__ out)
{
    int warp = (blockIdx.x * blockDim.x + threadIdx.x) >> 5;
    if (warp >= NN) return;
    int lane = threadIdx.x & 31;
    int n = warp;
    int c = lane * 4;

    float4 xrd = *(const float4*)(xr + (size_t)n * 128 + c);
    float4 w4  = *(const float4*)(att + c);

    float m = -FLT_MAX, ssum = 0.f;
    float4 acc = make_float4(0.f, 0.f, 0.f, 0.f);

    int beg = g_ptr[n], end = g_ptr[n + 1];
    for (int e = beg - 1; e < end; e++) {          // e == beg-1 -> self loop
        int s = (e < beg) ? n : g_csr_src[e];
        float4 v = *(const float4*)(xl + (size_t)s * 128 + c);
        float p = w4.x * lrelu(v.x + xrd.x) + w4.y * lrelu(v.y + xrd.y)
                + w4.z * lrelu(v.z + xrd.z) + w4.w * lrelu(v.w + xrd.w);
#pragma unroll
        for (int off = 1; off < 32 / H; off <<= 1)
            p += __shfl_xor_sync(0xffffffffu, p, off);
        float mn = fmaxf(m, p);
        float sc = __expf(m - mn);
        float wg = __expf(p - mn);
        ssum = ssum * sc + wg;
        acc.x = acc.x * sc + wg * v.x;
        acc.y = acc.y * sc + wg * v.y;
        acc.z = acc.z * sc + wg * v.z;
        acc.w = acc.w * sc + wg * v.w;
        m = mn;
    }
    float inv = 1.f / ssum;
    float4 bv = *(const float4*)(bg + c);
    float4 o;
    o.x = acc.x * inv + bv.x;
    o.y = acc.y * inv + bv.y;
    o.z = acc.z * inv + bv.z;
    o.w = acc.w * inv + bv.w;
    *(float4*)(out + (size_t)n * 128 + c) = o;
}

// ---------------- graph LayerNorm ----------------
__global__ void zero_red_kernel() { g_red[0] = 0.0; g_red[1] = 0.0; }

__global__ void ln_reduce_kernel(const float* __restrict__ x)
{
    float s = 0.f, sq = 0.f;
    for (int i = blockIdx.x * blockDim.x + threadIdx.x; i < TOTF; i += gridDim.x * blockDim.x) {
        float v = x[i];
        s += v; sq += v * v;
    }
    __shared__ float sh[256], shq[256];
    sh[threadIdx.x] = s; shq[threadIdx.x] = sq;
    __syncthreads();
    for (int o = 128; o > 0; o >>= 1) {
        if (threadIdx.x < o) { sh[threadIdx.x] += sh[threadIdx.x + o]; shq[threadIdx.x] += shq[threadIdx.x + o]; }
        __syncthreads();
    }
    if (threadIdx.x == 0) {
        atomicAdd(&g_red[0], (double)sh[0]);
        atomicAdd(&g_red[1], (double)shq[0]);
    }
}

__global__ void ln_norm_kernel(float* __restrict__ x, const float* __restrict__ g,
                               const float* __restrict__ b, int relu)
{
    int i = blockIdx.x * blockDim.x + threadIdx.x;
    if (i >= TOTF) return;
    double m   = g_red[0] / (double)TOTF;
    double var = g_red[1] / (double)TOTF - m * m;
    float stdv = (float)sqrt(fmax(var, 0.0));
    float inv  = 1.f / (stdv + 1e-5f);
    int c = i & 127;
    float y = (x[i] - (float)m) * inv * g[c] + b[c];
    if (relu) y = fmaxf(y, 0.f);
    x[i] = y;
}

// ---------------- host orchestration ----------------
static void run_ln(float* buf, const float* g, const float* b, bool relu)
{
    zero_red_kernel<<<1, 1>>>();
    ln_reduce_kernel<<<2048, 256>>>(buf);
    ln_norm_kernel<<<TOTF / 256, 256>>>(buf, g, b, relu ? 1 : 0);
}

extern "C" void kernel_launch(void* const* d_in, const int* in_sizes, int n_in,
                              void* d_out, int out_size)
{
    const float* x    = (const float*)d_in[0];
    const int*   ei   = (const int*)  d_in[1];
    const float* W0   = (const float*)d_in[2];
    const float* b0   = (const float*)d_in[3];
    const float* g0   = (const float*)d_in[4];
    const float* be0  = (const float*)d_in[5];
    const float* Wl1  = (const float*)d_in[6];
    const float* bl1  = (const float*)d_in[7];
    const float* Wr1  = (const float*)d_in[8];
    const float* br1  = (const float*)d_in[9];
    const float* att1 = (const float*)d_in[10];
    const float* bg1  = (const float*)d_in[11];
    const float* g1   = (const float*)d_in[12];
    const float* be1  = (const float*)d_in[13];
    const float* W2   = (const float*)d_in[14];
    const float* b2   = (const float*)d_in[15];
    const float* g2   = (const float*)d_in[16];
    const float* be2  = (const float*)d_in[17];
    const float* Wl3  = (const float*)d_in[18];
    const float* bl3  = (const float*)d_in[19];
    const float* Wr3  = (const float*)d_in[20];
    const float* br3  = (const float*)d_in[21];
    const float* att3 = (const float*)d_in[22];
    const float* bg3  = (const float*)d_in[23];
    const float* g3   = (const float*)d_in[24];
    const float* be3  = (const float*)d_in[25];

    const int* src = ei;          // edge_index[0]
    const int* dst = ei + NE;     // edge_index[1]
    float* out = (float*)d_out;

    float *xw, *h1, *h2, *xl, *xr;
    cudaGetSymbolAddress((void**)&xw, g_xw);
    cudaGetSymbolAddress((void**)&h1, g_h1);
    cudaGetSymbolAddress((void**)&h2, g_h2);
    cudaGetSymbolAddress((void**)&xl, g_xl);
    cudaGetSymbolAddress((void**)&xr, g_xr);

    const int GEMM_GRID = (NN + 127) / 128;
    const int WARP_GRID = (NN + 7) / 8;          // 8 warps per 256-thread block

    // --- CSR build + degrees ---
    zero_cnt_kernel<<<(NN + 255) / 256, 256>>>();
    hist_kernel<<<NE / 256, 256>>>(dst);
    dinv_kernel<<<(NN + 255) / 256, 256>>>();
    scan1_kernel<<<NBLK, 256>>>();
    scan2_kernel<<<1, 256>>>();
    scan3_kernel<<<(NN + 255) / 256, 256>>>();
    scatter_kernel<<<NE / 256, 256>>>(src, dst);

    // layer 0: GCN -> LN -> relu     (x -> h1)
    gemm_tf32_kernel<<<GEMM_GRID, 256>>>(x, W0, nullptr, xw, NN);
    gcn_gather_kernel<<<WARP_GRID, 256>>>(xw, b0, h1);
    run_ln(h1, g0, be0, true);

    // layer 1: GATv2 H=8 concat -> LN -> relu   (h1 -> h2)
    gemm_tf32_kernel<<<GEMM_GRID, 256>>>(h1, Wl1, bl1, xl, NN);
    gemm_tf32_kernel<<<GEMM_GRID, 256>>>(h1, Wr1, br1, xr, NN);
    gat_gather_kernel<8><<<WARP_GRID, 256>>>(xl, xr, att1, bg1, h2);
    run_ln(h2, g1, be1, true);

    // layer 2: GCN -> LN -> relu     (h2 -> h1)
    gemm_tf32_kernel<<<GEMM_GRID, 256>>>(h2, W2, nullptr, xw, NN);
    gcn_gather_kernel<<<WARP_GRID, 256>>>(xw, b2, h1);
    run_ln(h1, g2, be2, true);

    // layer 3: GATv2 H=1 mean -> LN  (h1 -> out)
    gemm_tf32_kernel<<<GEMM_GRID, 256>>>(h1, Wl3, bl3, xl, NN);
    gemm_tf32_kernel<<<GEMM_GRID, 256>>>(h1, Wr3, br3, xr, NN);
    gat_gather_kernel<1><<<WARP_GRID, 256>>>(xl, xr, att3, bg3, out);
    run_ln(out, g3, be3, false);
}

// round 3
// speedup vs baseline: 2.5687x; 1.1793x over previous
#include <cuda_runtime.h>
#include <math.h>
#include <float.h>

#define NN   50000
#define DD   128
#define NE   800000
#define TOTF (NN * DD)          // 6,400,000
#define NBLK 196                // ceil(NN/256)
#define NSLOT 32

// ---------------- scratch (static device globals only) ----------------
__device__ float  g_xw[TOTF];
__device__ float  g_h1[TOTF];
__device__ float  g_h2[TOTF];
__device__ float  g_xl[TOTF];
__device__ float  g_xr[TOTF];
__device__ float  g_dinv[NN];
__device__ int    g_cnt[NN];
__device__ int    g_ptr[NN + 1];
__device__ int    g_ptr2[NN];
__device__ int    g_csr_src[NE];
__device__ int    g_bsum[NBLK];
__device__ int    g_bsum2[NBLK];
__device__ double g_stats[4][NSLOT * 2];   // per-LN striped (sum, sumsq) slots

// ---------------- helpers ----------------
__device__ __forceinline__ float lrelu(float x) { return x > 0.f ? x : 0.2f * x; }

__device__ __forceinline__ unsigned f2tf(float x) {
    unsigned u; asm("cvt.rna.tf32.f32 %0, %1;" : "=r"(u) : "f"(x)); return u;
}

__device__ __forceinline__ void mma_tf32(float* d, const unsigned* a, const unsigned* b) {
    asm volatile("mma.sync.aligned.m16n8k8.row.col.f32.tf32.tf32.f32 "
                 "{%0,%1,%2,%3}, {%4,%5,%6,%7}, {%8,%9}, {%0,%1,%2,%3};"
                 : "+f"(d[0]), "+f"(d[1]), "+f"(d[2]), "+f"(d[3])
                 : "r"(a[0]), "r"(a[1]), "r"(a[2]), "r"(a[3]),
                   "r"(b[0]), "r"(b[1]));
}

__device__ __forceinline__ void stats_from_slots(const double* slot, float* mi) {
    double s = 0.0, sq = 0.0;
#pragma unroll
    for (int i = 0; i < NSLOT; i++) { s += slot[2 * i]; sq += slot[2 * i + 1]; }
    double m   = s / (double)TOTF;
    double var = sq / (double)TOTF - m * m;
    mi[0] = (float)m;
    mi[1] = 1.f / ((float)sqrt(fmax(var, 0.0)) + 1e-5f);
}

// ---------------- init: zero counters + stats ----------------
__global__ void init_zero_kernel() {
    int i = blockIdx.x * blockDim.x + threadIdx.x;
    if (i < NN) g_cnt[i] = 0;
    if (i < 4 * NSLOT * 2) ((double*)g_stats)[i] = 0.0;
}
__global__ void hist_kernel(const int* __restrict__ dst) {
    int e = blockIdx.x * blockDim.x + threadIdx.x;
    if (e < NE) atomicAdd(&g_cnt[dst[e]], 1);
}
// block-wise exclusive scan of g_cnt -> g_ptr, block sums -> g_bsum
__global__ void scan1_kernel() {
    __shared__ int sh[256];
    int i = blockIdx.x * 256 + threadIdx.x;
    int v = (i < NN) ? g_cnt[i] : 0;
    sh[threadIdx.x] = v;
    __syncthreads();
#pragma unroll
    for (int off = 1; off < 256; off <<= 1) {
        int t = (threadIdx.x >= off) ? sh[threadIdx.x - off] : 0;
        __syncthreads();
        sh[threadIdx.x] += t;
        __syncthreads();
    }
    if (i < NN) g_ptr[i] = sh[threadIdx.x] - v;   // exclusive
    if (threadIdx.x == 255) g_bsum[blockIdx.x] = sh[255];
}
__global__ void scan2_kernel() {
    __shared__ int sh[256];
    int t = threadIdx.x;
    int v = (t < NBLK) ? g_bsum[t] : 0;
    sh[t] = v;
    __syncthreads();
#pragma unroll
    for (int off = 1; off < 256; off <<= 1) {
        int tv = (t >= off) ? sh[t - off] : 0;
        __syncthreads();
        sh[t] += tv;
        __syncthreads();
    }
    if (t < NBLK) g_bsum2[t] = sh[t] - v;         // exclusive
}
__global__ void scan3_kernel() {
    int i = blockIdx.x * blockDim.x + threadIdx.x;
    if (i < NN) {
        int p = g_ptr[i] + g_bsum2[i >> 8];
        g_ptr[i] = p;
        g_ptr2[i] = p;
        g_dinv[i] = rsqrtf((float)(g_cnt[i] + 1));   // +1 self loop
    }
    if (i == 0) g_ptr[NN] = NE;
}
__global__ void scatter_kernel(const int* __restrict__ src, const int* __restrict__ dst) {
    int e = blockIdx.x * blockDim.x + threadIdx.x;
    if (e >= NE) return;
    int d = dst[e];
    int pos = atomicAdd(&g_ptr2[d], 1);
    g_csr_src[pos] = src[e];
}

// ---------------- TF32 GEMM: C = norm_relu(A) @ W (+bias) ----------------
// If slot != null: A elements get y = relu((a-mean)*inv*gamma[c] + beta[c]) on load.
__global__ void gemm_tf32_kernel(const float* __restrict__ A, const float* __restrict__ W,
                                 const float* __restrict__ bias, float* __restrict__ C, int M,
                                 const float* __restrict__ gamma, const float* __restrict__ beta,
                                 const double* __restrict__ slot)
{
    __shared__ unsigned As[128][40];   // [row][k], padded
    __shared__ unsigned Bs[32][132];   // [k][col], padded
    __shared__ float s_mi[2];
    int tid  = threadIdx.x;
    int wid  = tid >> 5, lane = tid & 31;
    int wm   = wid & 3, wn = wid >> 2;
    int m0   = blockIdx.x * 128;

    if (slot && tid == 0) stats_from_slots(slot, s_mi);
    __syncthreads();
    float mu  = slot ? s_mi[0] : 0.f;
    float inv = slot ? s_mi[1] : 1.f;

    float acc[2][8][4];
#pragma unroll
    for (int i = 0; i < 2; i++)
#pragma unroll
        for (int j = 0; j < 8; j++)
#pragma unroll
            for (int q = 0; q < 4; q++) acc[i][j][q] = 0.f;

    for (int k0 = 0; k0 < 128; k0 += 32) {
#pragma unroll
        for (int i = 0; i < 4; i++) {
            int lin = tid + i * 256;            // 0..1023
            int r = lin >> 3, q = (lin & 7) * 4;
            float4 v = make_float4(0.f, 0.f, 0.f, 0.f);
            if (m0 + r < M) v = *(const float4*)(A + (size_t)(m0 + r) * 128 + k0 + q);
            if (slot) {
                float4 gv = *(const float4*)(gamma + k0 + q);
                float4 bv = *(const float4*)(beta + k0 + q);
                v.x = fmaxf((v.x - mu) * inv * gv.x + bv.x, 0.f);
                v.y = fmaxf((v.y - mu) * inv * gv.y + bv.y, 0.f);
                v.z = fmaxf((v.z - mu) * inv * gv.z + bv.z, 0.f);
                v.w = fmaxf((v.w - mu) * inv * gv.w + bv.w, 0.f);
            }
            As[r][q + 0] = f2tf(v.x); As[r][q + 1] = f2tf(v.y);
            As[r][q + 2] = f2tf(v.z); As[r][q + 3] = f2tf(v.w);
        }
#pragma unroll
        for (int i = 0; i < 4; i++) {
            int lin = tid + i * 256;            // 0..1023
            int r = lin >> 5, q = (lin & 31) * 4;
            float4 v = *(const float4*)(W + (size_t)(k0 + r) * 128 + q);
            Bs[r][q + 0] = f2tf(v.x); Bs[r][q + 1] = f2tf(v.y);
            Bs[r][q + 2] = f2tf(v.z); Bs[r][q + 3] = f2tf(v.w);
        }
        __syncthreads();
#pragma unroll
        for (int kk = 0; kk < 32; kk += 8) {
            unsigned a[2][4], b[8][2];
            int ar = wm * 32 + (lane >> 2);
            int ak = kk + (lane & 3);
            a[0][0] = As[ar][ak];      a[0][1] = As[ar + 8][ak];
            a[0][2] = As[ar][ak + 4];  a[0][3] = As[ar + 8][ak + 4];
            a[1][0] = As[ar + 16][ak];     a[1][1] = As[ar + 24][ak];
            a[1][2] = As[ar + 16][ak + 4]; a[1][3] = As[ar + 24][ak + 4];
#pragma unroll
            for (int j = 0; j < 8; j++) {
                int col = wn * 64 + j * 8 + (lane >> 2);
                b[j][0] = Bs[kk + (lane & 3)][col];
                b[j][1] = Bs[kk + 4 + (lane & 3)][col];
            }
#pragma unroll
            for (int i = 0; i < 2; i++)
#pragma unroll
                for (int j = 0; j < 8; j++) mma_tf32(acc[i][j], a[i], b[j]);
        }
        __syncthreads();
    }

#pragma unroll
    for (int i = 0; i < 2; i++) {
#pragma unroll
        for (int j = 0; j < 8; j++) {
            int r0 = m0 + wm * 32 + i * 16 + (lane >> 2);
            int cc = wn * 64 + j * 8 + (lane & 3) * 2;
            float b0 = bias ? bias[cc] : 0.f;
            float b1 = bias ? bias[cc + 1] : 0.f;
            if (r0 < M) {
                C[(size_t)r0 * 128 + cc]     = acc[i][j][0] + b0;
                C[(size_t)r0 * 128 + cc + 1] = acc[i][j][1] + b1;
            }
            if (r0 + 8 < M) {
                C[(size_t)(r0 + 8) * 128 + cc]     = acc[i][j][2] + b0;
                C[(size_t)(r0 + 8) * 128 + cc + 1] = acc[i][j][3] + b1;
            }
        }
    }
}

// ---------------- block stat reduce (call with full block, no early exits) -------
__device__ __forceinline__ void accum_stats(float4 o, int lane, int tid, double* slot)
{
    float s  = o.x + o.y + o.z + o.w;
    float sq = o.x * o.x + o.y * o.y + o.z * o.z + o.w * o.w;
#pragma unroll
    for (int off = 16; off > 0; off >>= 1) {
        s  += __shfl_xor_sync(0xffffffffu, s,  off);
        sq += __shfl_xor_sync(0xffffffffu, sq, off);
    }
    __shared__ float bs[2];
    if (tid == 0) { bs[0] = 0.f; bs[1] = 0.f; }
    __syncthreads();
    if (lane == 0) { atomicAdd(&bs[0], s); atomicAdd(&bs[1], sq); }
    __syncthreads();
    if (tid == 0) {
        int sl = blockIdx.x & (NSLOT - 1);
        atomicAdd(&slot[2 * sl],     (double)bs[0]);
        atomicAdd(&slot[2 * sl + 1], (double)bs[1]);
    }
}

// ---------------- GCN gather (warp per node) + LN stats ----------------
__global__ void gcn_gather_kernel(const float* __restrict__ xw, const float* __restrict__ bias,
                                  float* __restrict__ out, double* __restrict__ slot)
{
    int tid  = threadIdx.x;
    int lane = tid & 31;
    int n = (blockIdx.x * blockDim.x + tid) >> 5;   // grid sized exactly: NN/8 blocks
    int c = lane * 4;
    float dn = g_dinv[n];
    float4 acc = *(const float4*)(xw + (size_t)n * 128 + c);
    float w0 = dn * dn;
    acc.x *= w0; acc.y *= w0; acc.z *= w0; acc.w *= w0;   // self loop

    int e = g_ptr[n], end = g_ptr[n + 1];
    for (; e + 1 < end; e += 2) {
        int s0 = g_csr_src[e], s1 = g_csr_src[e + 1];
        float w1 = g_dinv[s0] * dn, w2 = g_dinv[s1] * dn;
        float4 v0 = *(const float4*)(xw + (size_t)s0 * 128 + c);
        float4 v1 = *(const float4*)(xw + (size_t)s1 * 128 + c);
        acc.x += w1 * v0.x + w2 * v1.x;
        acc.y += w1 * v0.y + w2 * v1.y;
        acc.z += w1 * v0.z + w2 * v1.z;
        acc.w += w1 * v0.w + w2 * v1.w;
    }
    if (e < end) {
        int s0 = g_csr_src[e];
        float w1 = g_dinv[s0] * dn;
        float4 v0 = *(const float4*)(xw + (size_t)s0 * 128 + c);
        acc.x += w1 * v0.x; acc.y += w1 * v0.y;
        acc.z += w1 * v0.z; acc.w += w1 * v0.w;
    }
    float4 bv = *(const float4*)(bias + c);
    acc.x += bv.x; acc.y += bv.y; acc.z += bv.z; acc.w += bv.w;
    *(float4*)(out + (size_t)n * 128 + c) = acc;
    accum_stats(acc, lane, tid, slot);
}

// ---------------- fused GATv2 gather, online softmax + LN stats ----------------
template <int H>
__global__ void gat_gather_kernel(const float* __restrict__ xl, const float* __restrict__ xr,
                                  const float* __restrict__ att, const float* __restrict__ bg,
                                  float* __restrict__ out, double* __restrict__ slot)
{
    int tid  = threadIdx.x;
    int lane = tid & 31;
    int n = (blockIdx.x * blockDim.x + tid) >> 5;
    int c = lane * 4;

    float4 xrd = *(const float4*)(xr + (size_t)n * 128 + c);
    float4 w4  = *(const float4*)(att + c);

    float m = -FLT_MAX, ssum = 0.f;
    float4 acc = make_float4(0.f, 0.f, 0.f, 0.f);

    int beg = g_ptr[n], end = g_ptr[n + 1];
    for (int e = beg - 1; e < end; e++) {          // e == beg-1 -> self loop
        int s = (e < beg) ? n : g_csr_src[e];
        float4 v = *(const float4*)(xl + (size_t)s * 128 + c);
        float p = w4.x * lrelu(v.x + xrd.x) + w4.y * lrelu(v.y + xrd.y)
                + w4.z * lrelu(v.z + xrd.z) + w4.w * lrelu(v.w + xrd.w);
#pragma unroll
        for (int off = 1; off < 32 / H; off <<= 1)
            p += __shfl_xor_sync(0xffffffffu, p, off);
        float mn = fmaxf(m, p);
        float sc = __expf(m - mn);
        float wg = __expf(p - mn);
        ssum = ssum * sc + wg;
        acc.x = acc.x * sc + wg * v.x;
        acc.y = acc.y * sc + wg * v.y;
        acc.z = acc.z * sc + wg * v.z;
        acc.w = acc.w * sc + wg * v.w;
        m = mn;
    }
    float inv = 1.f / ssum;
    float4 bv = *(const float4*)(bg + c);
    float4 o;
    o.x = acc.x * inv + bv.x;
    o.y = acc.y * inv + bv.y;
    o.z = acc.z * inv + bv.z;
    o.w = acc.w * inv + bv.w;
    *(float4*)(out + (size_t)n * 128 + c) = o;
    accum_stats(o, lane, tid, slot);
}

// ---------------- final LayerNorm (in place, vectorized) ----------------
__global__ void ln_final_kernel(float* __restrict__ x, const float* __restrict__ g,
                                const float* __restrict__ b, const double* __restrict__ slot)
{
    __shared__ float s_mi[2];
    if (threadIdx.x == 0) stats_from_slots(slot, s_mi);
    __syncthreads();
    float mu = s_mi[0], inv = s_mi[1];
    int i = (blockIdx.x * blockDim.x + threadIdx.x) * 4;   // grid covers TOTF/4
    int c = i & 127;
    float4 v  = *(const float4*)(x + i);
    float4 gv = *(const float4*)(g + c);
    float4 bv = *(const float4*)(b + c);
    v.x = (v.x - mu) * inv * gv.x + bv.x;
    v.y = (v.y - mu) * inv * gv.y + bv.y;
    v.z = (v.z - mu) * inv * gv.z + bv.z;
    v.w = (v.w - mu) * inv * gv.w + bv.w;
    *(float4*)(x + i) = v;
}

// ---------------- host orchestration ----------------
extern "C" void kernel_launch(void* const* d_in, const int* in_sizes, int n_in,
                              void* d_out, int out_size)
{
    const float* x    = (const float*)d_in[0];
    const int*   ei   = (const int*)  d_in[1];
    const float* W0   = (const float*)d_in[2];
    const float* b0   = (const float*)d_in[3];
    const float* g0   = (const float*)d_in[4];
    const float* be0  = (const float*)d_in[5];
    const float* Wl1  = (const float*)d_in[6];
    const float* bl1  = (const float*)d_in[7];
    const float* Wr1  = (const float*)d_in[8];
    const float* br1  = (const float*)d_in[9];
    const float* att1 = (const float*)d_in[10];
    const float* bg1  = (const float*)d_in[11];
    const float* g1   = (const float*)d_in[12];
    const float* be1  = (const float*)d_in[13];
    const float* W2   = (const float*)d_in[14];
    const float* b2   = (const float*)d_in[15];
    const float* g2   = (const float*)d_in[16];
    const float* be2  = (const float*)d_in[17];
    const float* Wl3  = (const float*)d_in[18];
    const float* bl3  = (const float*)d_in[19];
    const float* Wr3  = (const float*)d_in[20];
    const float* br3  = (const float*)d_in[21];
    const float* att3 = (const float*)d_in[22];
    const float* bg3  = (const float*)d_in[23];
    const float* g3   = (const float*)d_in[24];
    const float* be3  = (const float*)d_in[25];

    const int* src = ei;          // edge_index[0]
    const int* dst = ei + NE;     // edge_index[1]
    float* out = (float*)d_out;

    float *xw, *h1, *h2, *xl, *xr;
    double* st;
    cudaGetSymbolAddress((void**)&xw, g_xw);
    cudaGetSymbolAddress((void**)&h1, g_h1);
    cudaGetSymbolAddress((void**)&h2, g_h2);
    cudaGetSymbolAddress((void**)&xl, g_xl);
    cudaGetSymbolAddress((void**)&xr, g_xr);
    cudaGetSymbolAddress((void**)&st, g_stats);
    double* s0 = st;
    double* s1 = st + NSLOT * 2;
    double* s2 = st + NSLOT * 4;
    double* s3 = st + NSLOT * 6;

    const int GEMM_GRID = (NN + 127) / 128;
    const int WARP_GRID = NN / 8;                 // exact: 6250 blocks, no remainder

    // --- CSR build + degrees + zero stats ---
    init_zero_kernel<<<(NN + 255) / 256, 256>>>();
    hist_kernel<<<NE / 256, 256>>>(dst);
    scan1_kernel<<<NBLK, 256>>>();
    scan2_kernel<<<1, 256>>>();
    scan3_kernel<<<(NN + 255) / 256, 256>>>();
    scatter_kernel<<<NE / 256, 256>>>(src, dst);

    // layer 0: GCN (x raw) -> stats s0
    gemm_tf32_kernel<<<GEMM_GRID, 256>>>(x, W0, nullptr, xw, NN, nullptr, nullptr, nullptr);
    gcn_gather_kernel<<<WARP_GRID, 256>>>(xw, b0, h1, s0);

    // layer 1: GATv2 H=8 (norm s0 + relu on A) -> stats s1
    gemm_tf32_kernel<<<GEMM_GRID, 256>>>(h1, Wl1, bl1, xl, NN, g0, be0, s0);
    gemm_tf32_kernel<<<GEMM_GRID, 256>>>(h1, Wr1, br1, xr, NN, g0, be0, s0);
    gat_gather_kernel<8><<<WARP_GRID, 256>>>(xl, xr, att1, bg1, h2, s1);

    // layer 2: GCN (norm s1 + relu on A) -> stats s2
    gemm_tf32_kernel<<<GEMM_GRID, 256>>>(h2, W2, nullptr, xw, NN, g1, be1, s1);
    gcn_gather_kernel<<<WARP_GRID, 256>>>(xw, b2, h1, s2);

    // layer 3: GATv2 H=1 (norm s2 + relu on A) -> stats s3 -> final LN
    gemm_tf32_kernel<<<GEMM_GRID, 256>>>(h1, Wl3, bl3, xl, NN, g2, be2, s2);
    gemm_tf32_kernel<<<GEMM_GRID, 256>>>(h1, Wr3, br3, xr, NN, g2, be2, s2);
    gat_gather_kernel<1><<<WARP_GRID, 256>>>(xl, xr, att3, bg3, out, s3);
    ln_final_kernel<<<TOTF / 1024, 256>>>(out, g3, be3, s3);
}

// round 4
// speedup vs baseline: 2.6479x; 1.0308x over previous
#include <cuda_runtime.h>
#include <math.h>
#include <float.h>

#define NN   50000
#define DD   128
#define NE   800000
#define TOTF (NN * DD)          // 6,400,000
#define NBLK 196                // ceil(NN/256)
#define NSLOT 32

#define GEMM_SMEM ((2*128*36 + 2*32*132) * 4)   // 70656 bytes

// ---------------- scratch (static device globals only) ----------------
__device__ float  g_xw[TOTF];
__device__ float  g_h1[TOTF];
__device__ float  g_h2[TOTF];
__device__ float  g_xl[TOTF];
__device__ float  g_xr[TOTF];
__device__ float  g_dinv[NN];
__device__ int    g_cnt[NN];
__device__ int    g_ptr[NN + 1];
__device__ int    g_ptr2[NN];
__device__ int    g_csr_src[NE];
__device__ int    g_bsum[NBLK];
__device__ int    g_arrive;
__device__ double g_stats[4][NSLOT * 2];   // per-LN striped (sum, sumsq) slots

// ---------------- helpers ----------------
__device__ __forceinline__ float lrelu(float x) { return x > 0.f ? x : 0.2f * x; }

__device__ __forceinline__ unsigned f2tf(float x) {
    unsigned u; asm("cvt.rna.tf32.f32 %0, %1;" : "=r"(u) : "f"(x)); return u;
}

__device__ __forceinline__ void mma_tf32(float* d, const unsigned* a, const unsigned* b) {
    asm volatile("mma.sync.aligned.m16n8k8.row.col.f32.tf32.tf32.f32 "
                 "{%0,%1,%2,%3}, {%4,%5,%6,%7}, {%8,%9}, {%0,%1,%2,%3};"
                 : "+f"(d[0]), "+f"(d[1]), "+f"(d[2]), "+f"(d[3])
                 : "r"(a[0]), "r"(a[1]), "r"(a[2]), "r"(a[3]),
                   "r"(b[0]), "r"(b[1]));
}

__device__ __forceinline__ void stats_from_slots(const double* slot, float* mi) {
    double s = 0.0, sq = 0.0;
#pragma unroll
    for (int i = 0; i < NSLOT; i++) { s += slot[2 * i]; sq += slot[2 * i + 1]; }
    double m   = s / (double)TOTF;
    double var = sq / (double)TOTF - m * m;
    mi[0] = (float)m;
    mi[1] = 1.f / ((float)sqrt(fmax(var, 0.0)) + 1e-5f);
}

// ---------------- init: zero counters + stats ----------------
__global__ void init_zero_kernel() {
    int i = blockIdx.x * blockDim.x + threadIdx.x;
    if (i < NN) g_cnt[i] = 0;
    if (i < 4 * NSLOT * 2) ((double*)g_stats)[i] = 0.0;
    if (i == 0) g_arrive = 0;
}
__global__ void hist_kernel(const int* __restrict__ dst) {
    int e = blockIdx.x * blockDim.x + threadIdx.x;
    if (e < NE) atomicAdd(&g_cnt[dst[e]], 1);
}

// single-pass scan: local scan + publish totals + all-arrive barrier + prefix
__global__ void scan_fused_kernel() {
    __shared__ int sh[256];
    int b = blockIdx.x;
    int i = b * 256 + threadIdx.x;
    int cnt = (i < NN) ? g_cnt[i] : 0;
    sh[threadIdx.x] = cnt;
    __syncthreads();
#pragma unroll
    for (int off = 1; off < 256; off <<= 1) {
        int t = (threadIdx.x >= off) ? sh[threadIdx.x - off] : 0;
        __syncthreads();
        sh[threadIdx.x] += t;
        __syncthreads();
    }
    int incl = sh[threadIdx.x];
    if (threadIdx.x == 0) {
        g_bsum[b] = sh[255];
        __threadfence();
        atomicAdd(&g_arrive, 1);
        while (atomicAdd(&g_arrive, 0) < NBLK) { }   // all blocks resident: safe
    }
    __syncthreads();
    // sum of block totals before b
    int p = 0;
    for (int j = threadIdx.x; j < b; j += 256) p += g_bsum[j];
    sh[threadIdx.x] = p;
    __syncthreads();
#pragma unroll
    for (int o = 128; o > 0; o >>= 1) {
        if (threadIdx.x < o) sh[threadIdx.x] += sh[threadIdx.x + o];
        __syncthreads();
    }
    int base = sh[0];
    if (i < NN) {
        int excl = base + incl - cnt;
        g_ptr[i]  = excl;
        g_ptr2[i] = excl;
        g_dinv[i] = rsqrtf((float)(cnt + 1));   // +1 self loop
    }
    if (i == 0) g_ptr[NN] = NE;
}

__global__ void scatter_kernel(const int* __restrict__ src, const int* __restrict__ dst) {
    int e = blockIdx.x * blockDim.x + threadIdx.x;
    if (e >= NE) return;
    int d = dst[e];
    int pos = atomicAdd(&g_ptr2[d], 1);
    g_csr_src[pos] = src[e];
}

// ---------------- TF32 GEMM (double-buffered): C = norm_relu(A) @ W (+bias) -------
__global__ __launch_bounds__(256, 2)
void gemm_tf32_kernel(const float* __restrict__ A, const float* __restrict__ W,
                      const float* __restrict__ bias, float* __restrict__ C, int M,
                      const float* __restrict__ gamma, const float* __restrict__ beta,
                      const double* __restrict__ slot)
{
    extern __shared__ unsigned smem_raw[];
    unsigned (*As)[128][36] = (unsigned (*)[128][36])smem_raw;
    unsigned (*Bs)[32][132] = (unsigned (*)[32][132])(smem_raw + 2 * 128 * 36);
    __shared__ float s_mi[2];

    int tid  = threadIdx.x;
    int wid  = tid >> 5, lane = tid & 31;
    int wm   = wid & 3, wn = wid >> 2;
    int m0   = blockIdx.x * 128;

    if (tid == 0) {
        if (slot) stats_from_slots(slot, s_mi);
        else { s_mi[0] = 0.f; s_mi[1] = 1.f; }
    }
    __syncthreads();
    float mu = s_mi[0], inv = s_mi[1];
    bool donorm = (slot != nullptr);

    float acc[2][8][4];
#pragma unroll
    for (int i = 0; i < 2; i++)
#pragma unroll
        for (int j = 0; j < 8; j++)
#pragma unroll
            for (int q = 0; q < 4; q++) acc[i][j][q] = 0.f;

    int Ar[4], Aq[4], Br[4], Bq[4];
#pragma unroll
    for (int i = 0; i < 4; i++) {
        int lin = tid + i * 256;
        Ar[i] = lin >> 3;  Aq[i] = (lin & 7) * 4;
        Br[i] = lin >> 5;  Bq[i] = (lin & 31) * 4;
    }

    float4 ra[4], rb[4];

#define LOAD_TILE(k0)                                                              \
    {                                                                              \
        _Pragma("unroll")                                                          \
        for (int i = 0; i < 4; i++) {                                              \
            ra[i] = (m0 + Ar[i] < M)                                               \
                ? *(const float4*)(A + (size_t)(m0 + Ar[i]) * 128 + (k0) + Aq[i])  \
                : make_float4(0.f, 0.f, 0.f, 0.f);                                 \
            rb[i] = *(const float4*)(W + (size_t)((k0) + Br[i]) * 128 + Bq[i]);    \
        }                                                                          \
    }

#define STORE_TILE(buf, k0)                                                        \
    {                                                                              \
        _Pragma("unroll")                                                          \
        for (int i = 0; i < 4; i++) {                                              \
            float4 v = ra[i];                                                      \
            if (donorm) {                                                          \
                float4 gv = *(const float4*)(gamma + (k0) + Aq[i]);                \
                float4 bv = *(const float4*)(beta  + (k0) + Aq[i]);                \
                v.x = fmaxf((v.x - mu) * inv * gv.x + bv.x, 0.f);                  \
                v.y = fmaxf((v.y - mu) * inv * gv.y + bv.y, 0.f);                  \
                v.z = fmaxf((v.z - mu) * inv * gv.z + bv.z, 0.f);                  \
                v.w = fmaxf((v.w - mu) * inv * gv.w + bv.w, 0.f);                  \
            }                                                                      \
            As[buf][Ar[i]][Aq[i] + 0] = f2tf(v.x);                                 \
            As[buf][Ar[i]][Aq[i] + 1] = f2tf(v.y);                                 \
            As[buf][Ar[i]][Aq[i] + 2] = f2tf(v.z);                                 \
            As[buf][Ar[i]][Aq[i] + 3] = f2tf(v.w);                                 \
            Bs[buf][Br[i]][Bq[i] + 0] = f2tf(rb[i].x);                             \
            Bs[buf][Br[i]][Bq[i] + 1] = f2tf(rb[i].y);                             \
            Bs[buf][Br[i]][Bq[i] + 2] = f2tf(rb[i].z);                             \
            Bs[buf][Br[i]][Bq[i] + 3] = f2tf(rb[i].w);                             \
        }                                                                          \
    }

#define COMPUTE(buf)                                                               \
    {                                                                              \
        _Pragma("unroll")                                                          \
        for (int kk = 0; kk < 32; kk += 8) {                                       \
            unsigned a[2][4], b[8][2];                                             \
            int ar = wm * 32 + (lane >> 2);                                        \
            int ak = kk + (lane & 3);                                              \
            a[0][0] = As[buf][ar][ak];          a[0][1] = As[buf][ar + 8][ak];     \
            a[0][2] = As[buf][ar][ak + 4];      a[0][3] = As[buf][ar + 8][ak + 4]; \
            a[1][0] = As[buf][ar + 16][ak];     a[1][1] = As[buf][ar + 24][ak];    \
            a[1][2] = As[buf][ar + 16][ak + 4]; a[1][3] = As[buf][ar + 24][ak + 4];\
            _Pragma("unroll")                                                      \
            for (int j = 0; j < 8; j++) {                                          \
                int col = wn * 64 + j * 8 + (lane >> 2);                           \
                b[j][0] = Bs[buf][kk + (lane & 3)][col];                           \
                b[j][1] = Bs[buf][kk + 4 + (lane & 3)][col];                       \
            }                                                                      \
            _Pragma("unroll")                                                      \
            for (int i = 0; i < 2; i++)                                            \
                _Pragma("unroll")                                                  \
                for (int j = 0; j < 8; j++) mma_tf32(acc[i][j], a[i], b[j]);       \
        }                                                                          \
    }

    LOAD_TILE(0);
    STORE_TILE(0, 0);
    __syncthreads();
#pragma unroll
    for (int t = 0; t < 4; t++) {
        if (t < 3) LOAD_TILE((t + 1) * 32);
        COMPUTE(t & 1);
        if (t < 3) {
            STORE_TILE((t + 1) & 1, (t + 1) * 32);
            __syncthreads();
        }
    }

#pragma unroll
    for (int i = 0; i < 2; i++) {
#pragma unroll
        for (int j = 0; j < 8; j++) {
            int r0 = m0 + wm * 32 + i * 16 + (lane >> 2);
            int cc = wn * 64 + j * 8 + (lane & 3) * 2;
            float b0 = bias ? bias[cc] : 0.f;
            float b1 = bias ? bias[cc + 1] : 0.f;
            if (r0 < M) {
                C[(size_t)r0 * 128 + cc]     = acc[i][j][0] + b0;
                C[(size_t)r0 * 128 + cc + 1] = acc[i][j][1] + b1;
            }
            if (r0 + 8 < M) {
                C[(size_t)(r0 + 8) * 128 + cc]     = acc[i][j][2] + b0;
                C[(size_t)(r0 + 8) * 128 + cc + 1] = acc[i][j][3] + b1;
            }
        }
    }
#undef LOAD_TILE
#undef STORE_TILE
#undef COMPUTE
}

// ---------------- block stat reduce (full block, no early exits) -------
__device__ __forceinline__ void accum_stats(float4 o, int lane, int tid, double* slot)
{
    float s  = o.x + o.y + o.z + o.w;
    float sq = o.x * o.x + o.y * o.y + o.z * o.z + o.w * o.w;
#pragma unroll
    for (int off = 16; off > 0; off >>= 1) {
        s  += __shfl_xor_sync(0xffffffffu, s,  off);
        sq += __shfl_xor_sync(0xffffffffu, sq, off);
    }
    __shared__ float bs[2];
    if (tid == 0) { bs[0] = 0.f; bs[1] = 0.f; }
    __syncthreads();
    if (lane == 0) { atomicAdd(&bs[0], s); atomicAdd(&bs[1], sq); }
    __syncthreads();
    if (tid == 0) {
        int sl = blockIdx.x & (NSLOT - 1);
        atomicAdd(&slot[2 * sl],     (double)bs[0]);
        atomicAdd(&slot[2 * sl + 1], (double)bs[1]);
    }
}

// ---------------- GCN gather (warp per node) + LN stats ----------------
__global__ void gcn_gather_kernel(const float* __restrict__ xw, const float* __restrict__ bias,
                                  float* __restrict__ out, double* __restrict__ slot)
{
    int tid  = threadIdx.x;
    int lane = tid & 31;
    int n = (blockIdx.x * blockDim.x + tid) >> 5;   // grid exact: NN/8 blocks
    int c = lane * 4;
    float dn = g_dinv[n];
    float4 acc = *(const float4*)(xw + (size_t)n * 128 + c);
    float w0 = dn * dn;
    acc.x *= w0; acc.y *= w0; acc.z *= w0; acc.w *= w0;   // self loop

    int e = g_ptr[n], end = g_ptr[n + 1];
    for (; e + 3 < end; e += 4) {
        int s0 = g_csr_src[e],     s1 = g_csr_src[e + 1];
        int s2 = g_csr_src[e + 2], s3 = g_csr_src[e + 3];
        float w1 = g_dinv[s0] * dn, w2 = g_dinv[s1] * dn;
        float w3 = g_dinv[s2] * dn, w4 = g_dinv[s3] * dn;
        float4 v0 = *(const float4*)(xw + (size_t)s0 * 128 + c);
        float4 v1 = *(const float4*)(xw + (size_t)s1 * 128 + c);
        float4 v2 = *(const float4*)(xw + (size_t)s2 * 128 + c);
        float4 v3 = *(const float4*)(xw + (size_t)s3 * 128 + c);
        acc.x += w1 * v0.x + w2 * v1.x + w3 * v2.x + w4 * v3.x;
        acc.y += w1 * v0.y + w2 * v1.y + w3 * v2.y + w4 * v3.y;
        acc.z += w1 * v0.z + w2 * v1.z + w3 * v2.z + w4 * v3.z;
        acc.w += w1 * v0.w + w2 * v1.w + w3 * v2.w + w4 * v3.w;
    }
    for (; e < end; e++) {
        int s0 = g_csr_src[e];
        float w1 = g_dinv[s0] * dn;
        float4 v0 = *(const float4*)(xw + (size_t)s0 * 128 + c);
        acc.x += w1 * v0.x; acc.y += w1 * v0.y;
        acc.z += w1 * v0.z; acc.w += w1 * v0.w;
    }
    float4 bv = *(const float4*)(bias + c);
    acc.x += bv.x; acc.y += bv.y; acc.z += bv.z; acc.w += bv.w;
    *(float4*)(out + (size_t)n * 128 + c) = acc;
    accum_stats(acc, lane, tid, slot);
}

// ---------------- fused GATv2 gather, online softmax + LN stats ----------------
template <int H>
__global__ void gat_gather_kernel(const float* __restrict__ xl, const float* __restrict__ xr,
                                  const float* __restrict__ att, const float* __restrict__ bg,
                                  float* __restrict__ out, double* __restrict__ slot)
{
    int tid  = threadIdx.x;
    int lane = tid & 31;
    int n = (blockIdx.x * blockDim.x + tid) >> 5;
    int c = lane * 4;

    float4 xrd = *(const float4*)(xr + (size_t)n * 128 + c);
    float4 w4  = *(const float4*)(att + c);

    float m = -FLT_MAX, ssum = 0.f;
    float4 acc = make_float4(0.f, 0.f, 0.f, 0.f);

    int beg = g_ptr[n], end = g_ptr[n + 1];
    for (int e = beg - 1; e < end; e++) {          // e == beg-1 -> self loop
        int s = (e < beg) ? n : g_csr_src[e];
        float4 v = *(const float4*)(xl + (size_t)s * 128 + c);
        float p = w4.x * lrelu(v.x + xrd.x) + w4.y * lrelu(v.y + xrd.y)
                + w4.z * lrelu(v.z + xrd.z) + w4.w * lrelu(v.w + xrd.w);
#pragma unroll
        for (int off = 1; off < 32 / H; off <<= 1)
            p += __shfl_xor_sync(0xffffffffu, p, off);
        float mn = fmaxf(m, p);
        float sc = __expf(m - mn);
        float wg = __expf(p - mn);
        ssum = ssum * sc + wg;
        acc.x = acc.x * sc + wg * v.x;
        acc.y = acc.y * sc + wg * v.y;
        acc.z = acc.z * sc + wg * v.z;
        acc.w = acc.w * sc + wg * v.w;
        m = mn;
    }
    float inv = 1.f / ssum;
    float4 bv = *(const float4*)(bg + c);
    float4 o;
    o.x = acc.x * inv + bv.x;
    o.y = acc.y * inv + bv.y;
    o.z = acc.z * inv + bv.z;
    o.w = acc.w * inv + bv.w;
    *(float4*)(out + (size_t)n * 128 + c) = o;
    accum_stats(o, lane, tid, slot);
}

// ---------------- final LayerNorm (in place, vectorized) ----------------
__global__ void ln_final_kernel(float* __restrict__ x, const float* __restrict__ g,
                                const float* __restrict__ b, const double* __restrict__ slot)
{
    __shared__ float s_mi[2];
    if (threadIdx.x == 0) stats_from_slots(slot, s_mi);
    __syncthreads();
    float mu = s_mi[0], inv = s_mi[1];
    int i = (blockIdx.x * blockDim.x + threadIdx.x) * 4;   // grid covers TOTF/4
    int c = i & 127;
    float4 v  = *(const float4*)(x + i);
    float4 gv = *(const float4*)(g + c);
    float4 bv = *(const float4*)(b + c);
    v.x = (v.x - mu) * inv * gv.x + bv.x;
    v.y = (v.y - mu) * inv * gv.y + bv.y;
    v.z = (v.z - mu) * inv * gv.z + bv.z;
    v.w = (v.w - mu) * inv * gv.w + bv.w;
    *(float4*)(x + i) = v;
}

// ---------------- host orchestration ----------------
extern "C" void kernel_launch(void* const* d_in, const int* in_sizes, int n_in,
                              void* d_out, int out_size)
{
    const float* x    = (const float*)d_in[0];
    const int*   ei   = (const int*)  d_in[1];
    const float* W0   = (const float*)d_in[2];
    const float* b0   = (const float*)d_in[3];
    const float* g0   = (const float*)d_in[4];
    const float* be0  = (const float*)d_in[5];
    const float* Wl1  = (const float*)d_in[6];
    const float* bl1  = (const float*)d_in[7];
    const float* Wr1  = (const float*)d_in[8];
    const float* br1  = (const float*)d_in[9];
    const float* att1 = (const float*)d_in[10];
    const float* bg1  = (const float*)d_in[11];
    const float* g1   = (const float*)d_in[12];
    const float* be1  = (const float*)d_in[13];
    const float* W2   = (const float*)d_in[14];
    const float* b2   = (const float*)d_in[15];
    const float* g2   = (const float*)d_in[16];
    const float* be2  = (const float*)d_in[17];
    const float* Wl3  = (const float*)d_in[18];
    const float* bl3  = (const float*)d_in[19];
    const float* Wr3  = (const float*)d_in[20];
    const float* br3  = (const float*)d_in[21];
    const float* att3 = (const float*)d_in[22];
    const float* bg3  = (const float*)d_in[23];
    const float* g3   = (const float*)d_in[24];
    const float* be3  = (const float*)d_in[25];

    const int* src = ei;          // edge_index[0]
    const int* dst = ei + NE;     // edge_index[1]
    float* out = (float*)d_out;

    float *xw, *h1, *h2, *xl, *xr;
    double* st;
    cudaGetSymbolAddress((void**)&xw, g_xw);
    cudaGetSymbolAddress((void**)&h1, g_h1);
    cudaGetSymbolAddress((void**)&h2, g_h2);
    cudaGetSymbolAddress((void**)&xl, g_xl);
    cudaGetSymbolAddress((void**)&xr, g_xr);
    cudaGetSymbolAddress((void**)&st, g_stats);
    double* s0 = st;
    double* s1 = st + NSLOT * 2;
    double* s2 = st + NSLOT * 4;
    double* s3 = st + NSLOT * 6;

    cudaFuncSetAttribute(gemm_tf32_kernel,
                         cudaFuncAttributeMaxDynamicSharedMemorySize, GEMM_SMEM);

    const int GEMM_GRID = (NN + 127) / 128;
    const int WARP_GRID = NN / 8;                 // exact: 6250 blocks

    // --- CSR build + degrees + zero stats ---
    init_zero_kernel<<<(NN + 255) / 256, 256>>>();
    hist_kernel<<<NE / 256, 256>>>(dst);
    scan_fused_kernel<<<NBLK, 256>>>();
    scatter_kernel<<<NE / 256, 256>>>(src, dst);

    // layer 0: GCN (x raw) -> stats s0
    gemm_tf32_kernel<<<GEMM_GRID, 256, GEMM_SMEM>>>(x, W0, nullptr, xw, NN, nullptr, nullptr, nullptr);
    gcn_gather_kernel<<<WARP_GRID, 256>>>(xw, b0, h1, s0);

    // layer 1: GATv2 H=8 (norm s0 + relu on A) -> stats s1
    gemm_tf32_kernel<<<GEMM_GRID, 256, GEMM_SMEM>>>(h1, Wl1, bl1, xl, NN, g0, be0, s0);
    gemm_tf32_kernel<<<GEMM_GRID, 256, GEMM_SMEM>>>(h1, Wr1, br1, xr, NN, g0, be0, s0);
    gat_gather_kernel<8><<<WARP_GRID, 256>>>(xl, xr, att1, bg1, h2, s1);

    // layer 2: GCN (norm s1 + relu on A) -> stats s2
    gemm_tf32_kernel<<<GEMM_GRID, 256, GEMM_SMEM>>>(h2, W2, nullptr, xw, NN, g1, be1, s1);
    gcn_gather_kernel<<<WARP_GRID, 256>>>(xw, b2, h1, s2);

    // layer 3: GATv2 H=1 (norm s2 + relu on A) -> stats s3 -> final LN
    gemm_tf32_kernel<<<GEMM_GRID, 256, GEMM_SMEM>>>(h1, Wl3, bl3, xl, NN, g2, be2, s2);
    gemm_tf32_kernel<<<GEMM_GRID, 256, GEMM_SMEM>>>(h1, Wr3, br3, xr, NN, g2, be2, s2);
    gat_gather_kernel<1><<<WARP_GRID, 256>>>(xl, xr, att3, bg3, out, s3);
    ln_final_kernel<<<TOTF / 1024, 256>>>(out, g3, be3, s3);
}

// round 5
// speedup vs baseline: 3.0516x; 1.1525x over previous
#include <cuda_runtime.h>
#include <math.h>
#include <float.h>

#define NN   50000
#define DD   128
#define NE   800000
#define TOTF (NN * DD)          // 6,400,000
#define NBLK 196                // ceil(NN/256)
#define NSLOT 32

#define GEMM_SMEM  ((2*128*36 + 2*32*132) * 4)   // 70656 bytes
#define GEMM2_SMEM ((2*128*36 + 2*32*260) * 4)   // 103424 bytes

// ---------------- scratch (static device globals only) ----------------
__device__ float  g_xw[TOTF];
__device__ float  g_h1[TOTF];
__device__ float  g_h2[TOTF];
__device__ float  g_xl[TOTF];
__device__ float  g_xr[TOTF];
__device__ float  g_dinv[NN];
__device__ int    g_cnt[NN];
__device__ int    g_ptr[NN + 1];
__device__ int    g_ptr2[NN];
__device__ int    g_csr_src[NE];
__device__ int    g_bsum[NBLK];
__device__ int    g_arrive;
__device__ double g_stats[4][NSLOT * 2];

// ---------------- helpers ----------------
__device__ __forceinline__ float lrelu(float x) { return x > 0.f ? x : 0.2f * x; }

__device__ __forceinline__ unsigned f2tf(float x) {
    unsigned u; asm("cvt.rna.tf32.f32 %0, %1;" : "=r"(u) : "f"(x)); return u;
}

__device__ __forceinline__ void mma_tf32(float* d, const unsigned* a, const unsigned* b) {
    asm volatile("mma.sync.aligned.m16n8k8.row.col.f32.tf32.tf32.f32 "
                 "{%0,%1,%2,%3}, {%4,%5,%6,%7}, {%8,%9}, {%0,%1,%2,%3};"
                 : "+f"(d[0]), "+f"(d[1]), "+f"(d[2]), "+f"(d[3])
                 : "r"(a[0]), "r"(a[1]), "r"(a[2]), "r"(a[3]),
                   "r"(b[0]), "r"(b[1]));
}

__device__ __forceinline__ void stats_from_slots(const double* slot, float* mi) {
    double s = 0.0, sq = 0.0;
#pragma unroll
    for (int i = 0; i < NSLOT; i++) { s += slot[2 * i]; sq += slot[2 * i + 1]; }
    double m   = s / (double)TOTF;
    double var = sq / (double)TOTF - m * m;
    mi[0] = (float)m;
    mi[1] = 1.f / ((float)sqrt(fmax(var, 0.0)) + 1e-5f);
}

// ---------------- init / CSR ----------------
__global__ void init_zero_kernel() {
    int i = blockIdx.x * blockDim.x + threadIdx.x;
    if (i < NN) g_cnt[i] = 0;
    if (i < 4 * NSLOT * 2) ((double*)g_stats)[i] = 0.0;
    if (i == 0) g_arrive = 0;
}
__global__ void hist_kernel(const int* __restrict__ dst) {
    int e = blockIdx.x * blockDim.x + threadIdx.x;
    if (e < NE) atomicAdd(&g_cnt[dst[e]], 1);
}
__global__ void scan_fused_kernel() {
    __shared__ int sh[256];
    int b = blockIdx.x;
    int i = b * 256 + threadIdx.x;
    int cnt = (i < NN) ? g_cnt[i] : 0;
    sh[threadIdx.x] = cnt;
    __syncthreads();
#pragma unroll
    for (int off = 1; off < 256; off <<= 1) {
        int t = (threadIdx.x >= off) ? sh[threadIdx.x - off] : 0;
        __syncthreads();
        sh[threadIdx.x] += t;
        __syncthreads();
    }
    int incl = sh[threadIdx.x];
    if (threadIdx.x == 0) {
        g_bsum[b] = sh[255];
        __threadfence();
        atomicAdd(&g_arrive, 1);
        while (atomicAdd(&g_arrive, 0) < NBLK) { }
    }
    __syncthreads();
    int p = 0;
    for (int j = threadIdx.x; j < b; j += 256) p += g_bsum[j];
    sh[threadIdx.x] = p;
    __syncthreads();
#pragma unroll
    for (int o = 128; o > 0; o >>= 1) {
        if (threadIdx.x < o) sh[threadIdx.x] += sh[threadIdx.x + o];
        __syncthreads();
    }
    int base = sh[0];
    if (i < NN) {
        int excl = base + incl - cnt;
        g_ptr[i]  = excl;
        g_ptr2[i] = excl;
        g_dinv[i] = rsqrtf((float)(cnt + 1));
    }
    if (i == 0) g_ptr[NN] = NE;
}
__global__ void scatter_kernel(const int* __restrict__ src, const int* __restrict__ dst) {
    int e = blockIdx.x * blockDim.x + threadIdx.x;
    if (e >= NE) return;
    int pos = atomicAdd(&g_ptr2[dst[e]], 1);
    g_csr_src[pos] = src[e];
}

// ---------------- TF32 GEMM N=128: C = rowscale(r) * (norm_relu(A) @ W) -------
__global__ __launch_bounds__(256, 2)
void gemm_tf32_kernel(const float* __restrict__ A, const float* __restrict__ W,
                      float* __restrict__ C, int M,
                      const float* __restrict__ gamma, const float* __restrict__ beta,
                      const double* __restrict__ slot, const float* __restrict__ rowscale)
{
    extern __shared__ unsigned smem_raw[];
    unsigned (*As)[128][36] = (unsigned (*)[128][36])smem_raw;
    unsigned (*Bs)[32][132] = (unsigned (*)[32][132])(smem_raw + 2 * 128 * 36);
    __shared__ float s_mi[2];

    int tid  = threadIdx.x;
    int wid  = tid >> 5, lane = tid & 31;
    int wm   = wid & 3, wn = wid >> 2;
    int m0   = blockIdx.x * 128;

    if (tid == 0) {
        if (slot) stats_from_slots(slot, s_mi);
        else { s_mi[0] = 0.f; s_mi[1] = 1.f; }
    }
    __syncthreads();
    float mu = s_mi[0], inv = s_mi[1];
    bool donorm = (slot != nullptr);

    float acc[2][8][4];
#pragma unroll
    for (int i = 0; i < 2; i++)
#pragma unroll
        for (int j = 0; j < 8; j++)
#pragma unroll
            for (int q = 0; q < 4; q++) acc[i][j][q] = 0.f;

    int Ar[4], Aq[4], Br[4], Bq[4];
#pragma unroll
    for (int i = 0; i < 4; i++) {
        int lin = tid + i * 256;
        Ar[i] = lin >> 3;  Aq[i] = (lin & 7) * 4;
        Br[i] = lin >> 5;  Bq[i] = (lin & 31) * 4;
    }
    float4 ra[4], rb[4];

#define LOAD_TILE(k0)                                                              \
    {                                                                              \
        _Pragma("unroll")                                                          \
        for (int i = 0; i < 4; i++) {                                              \
            ra[i] = (m0 + Ar[i] < M)                                               \
                ? *(const float4*)(A + (size_t)(m0 + Ar[i]) * 128 + (k0) + Aq[i])  \
                : make_float4(0.f, 0.f, 0.f, 0.f);                                 \
            rb[i] = *(const float4*)(W + (size_t)((k0) + Br[i]) * 128 + Bq[i]);    \
        }                                                                          \
    }
#define STORE_TILE(buf, k0)                                                        \
    {                                                                              \
        _Pragma("unroll")                                                          \
        for (int i = 0; i < 4; i++) {                                              \
            float4 v = ra[i];                                                      \
            if (donorm) {                                                          \
                float4 gv = *(const float4*)(gamma + (k0) + Aq[i]);                \
                float4 bv = *(const float4*)(beta  + (k0) + Aq[i]);                \
                v.x = fmaxf((v.x - mu) * inv * gv.x + bv.x, 0.f);                  \
                v.y = fmaxf((v.y - mu) * inv * gv.y + bv.y, 0.f);                  \
                v.z = fmaxf((v.z - mu) * inv * gv.z + bv.z, 0.f);                  \
                v.w = fmaxf((v.w - mu) * inv * gv.w + bv.w, 0.f);                  \
            }                                                                      \
            As[buf][Ar[i]][Aq[i] + 0] = f2tf(v.x);                                 \
            As[buf][Ar[i]][Aq[i] + 1] = f2tf(v.y);                                 \
            As[buf][Ar[i]][Aq[i] + 2] = f2tf(v.z);                                 \
            As[buf][Ar[i]][Aq[i] + 3] = f2tf(v.w);                                 \
            Bs[buf][Br[i]][Bq[i] + 0] = f2tf(rb[i].x);                             \
            Bs[buf][Br[i]][Bq[i] + 1] = f2tf(rb[i].y);                             \
            Bs[buf][Br[i]][Bq[i] + 2] = f2tf(rb[i].z);                             \
            Bs[buf][Br[i]][Bq[i] + 3] = f2tf(rb[i].w);                             \
        }                                                                          \
    }
#define COMPUTE(buf)                                                               \
    {                                                                              \
        _Pragma("unroll")                                                          \
        for (int kk = 0; kk < 32; kk += 8) {                                       \
            unsigned a[2][4], b[8][2];                                             \
            int ar = wm * 32 + (lane >> 2);                                        \
            int ak = kk + (lane & 3);                                              \
            a[0][0] = As[buf][ar][ak];          a[0][1] = As[buf][ar + 8][ak];     \
            a[0][2] = As[buf][ar][ak + 4];      a[0][3] = As[buf][ar + 8][ak + 4]; \
            a[1][0] = As[buf][ar + 16][ak];     a[1][1] = As[buf][ar + 24][ak];    \
            a[1][2] = As[buf][ar + 16][ak + 4]; a[1][3] = As[buf][ar + 24][ak + 4];\
            _Pragma("unroll")                                                      \
            for (int j = 0; j < 8; j++) {                                          \
                int col = wn * 64 + j * 8 + (lane >> 2);                           \
                b[j][0] = Bs[buf][kk + (lane & 3)][col];                           \
                b[j][1] = Bs[buf][kk + 4 + (lane & 3)][col];                       \
            }                                                                      \
            _Pragma("unroll")                                                      \
            for (int i = 0; i < 2; i++)                                            \
                _Pragma("unroll")                                                  \
                for (int j = 0; j < 8; j++) mma_tf32(acc[i][j], a[i], b[j]);       \
        }                                                                          \
    }

    LOAD_TILE(0);
    STORE_TILE(0, 0);
    __syncthreads();
#pragma unroll
    for (int t = 0; t < 4; t++) {
        if (t < 3) LOAD_TILE((t + 1) * 32);
        COMPUTE(t & 1);
        if (t < 3) { STORE_TILE((t + 1) & 1, (t + 1) * 32); __syncthreads(); }
    }

#pragma unroll
    for (int i = 0; i < 2; i++) {
#pragma unroll
        for (int j = 0; j < 8; j++) {
            int r0 = m0 + wm * 32 + i * 16 + (lane >> 2);
            int cc = wn * 64 + j * 8 + (lane & 3) * 2;
            if (r0 < M) {
                float sc = rowscale ? rowscale[r0] : 1.f;
                C[(size_t)r0 * 128 + cc]     = acc[i][j][0] * sc;
                C[(size_t)r0 * 128 + cc + 1] = acc[i][j][1] * sc;
            }
            if (r0 + 8 < M) {
                float sc = rowscale ? rowscale[r0 + 8] : 1.f;
                C[(size_t)(r0 + 8) * 128 + cc]     = acc[i][j][2] * sc;
                C[(size_t)(r0 + 8) * 128 + cc + 1] = acc[i][j][3] * sc;
            }
        }
    }
#undef LOAD_TILE
#undef STORE_TILE
#undef COMPUTE
}

// ---------------- merged GAT GEMM N=256: xl = nr(A)@Wl+bl, xr = nr(A)@Wr+br ----
__global__ __launch_bounds__(512, 1)
void gemm_gat_kernel(const float* __restrict__ A,
                     const float* __restrict__ Wl, const float* __restrict__ bl,
                     const float* __restrict__ Wr, const float* __restrict__ br,
                     float* __restrict__ XL, float* __restrict__ XR, int M,
                     const float* __restrict__ gamma, const float* __restrict__ beta,
                     const double* __restrict__ slot)
{
    extern __shared__ unsigned smem_raw[];
    unsigned (*As)[128][36] = (unsigned (*)[128][36])smem_raw;
    unsigned (*Bs)[32][260] = (unsigned (*)[32][260])(smem_raw + 2 * 128 * 36);
    __shared__ float s_mi[2];

    int tid  = threadIdx.x;
    int wid  = tid >> 5, lane = tid & 31;
    int wm   = wid & 3, wn = wid >> 2;      // wn 0..3 over 256 cols
    int m0   = blockIdx.x * 128;

    if (tid == 0) {
        if (slot) stats_from_slots(slot, s_mi);
        else { s_mi[0] = 0.f; s_mi[1] = 1.f; }
    }
    __syncthreads();
    float mu = s_mi[0], inv = s_mi[1];
    bool donorm = (slot != nullptr);

    float acc[2][8][4];
#pragma unroll
    for (int i = 0; i < 2; i++)
#pragma unroll
        for (int j = 0; j < 8; j++)
#pragma unroll
            for (int q = 0; q < 4; q++) acc[i][j][q] = 0.f;

    int Ar[2], Aq[2], Br[4], Bc[4];
#pragma unroll
    for (int i = 0; i < 2; i++) {
        int lin = tid + i * 512;
        Ar[i] = lin >> 3;  Aq[i] = (lin & 7) * 4;
    }
#pragma unroll
    for (int i = 0; i < 4; i++) {
        int lin = tid + i * 512;
        Br[i] = lin >> 6;  Bc[i] = (lin & 63) * 4;
    }
    float4 ra[2], rb[4];

#define LOAD_TILE2(k0)                                                             \
    {                                                                              \
        _Pragma("unroll")                                                          \
        for (int i = 0; i < 2; i++)                                                \
            ra[i] = (m0 + Ar[i] < M)                                               \
                ? *(const float4*)(A + (size_t)(m0 + Ar[i]) * 128 + (k0) + Aq[i])  \
                : make_float4(0.f, 0.f, 0.f, 0.f);                                 \
        _Pragma("unroll")                                                          \
        for (int i = 0; i < 4; i++)                                                \
            rb[i] = (Bc[i] < 128)                                                  \
                ? *(const float4*)(Wl + (size_t)((k0) + Br[i]) * 128 + Bc[i])      \
                : *(const float4*)(Wr + (size_t)((k0) + Br[i]) * 128 + Bc[i] - 128);\
    }
#define STORE_TILE2(buf, k0)                                                       \
    {                                                                              \
        _Pragma("unroll")                                                          \
        for (int i = 0; i < 2; i++) {                                              \
            float4 v = ra[i];                                                      \
            if (donorm) {                                                          \
                float4 gv = *(const float4*)(gamma + (k0) + Aq[i]);                \
                float4 bv = *(const float4*)(beta  + (k0) + Aq[i]);                \
                v.x = fmaxf((v.x - mu) * inv * gv.x + bv.x, 0.f);                  \
                v.y = fmaxf((v.y - mu) * inv * gv.y + bv.y, 0.f);                  \
                v.z = fmaxf((v.z - mu) * inv * gv.z + bv.z, 0.f);                  \
                v.w = fmaxf((v.w - mu) * inv * gv.w + bv.w, 0.f);                  \
            }                                                                      \
            As[buf][Ar[i]][Aq[i] + 0] = f2tf(v.x);                                 \
            As[buf][Ar[i]][Aq[i] + 1] = f2tf(v.y);                                 \
            As[buf][Ar[i]][Aq[i] + 2] = f2tf(v.z);                                 \
            As[buf][Ar[i]][Aq[i] + 3] = f2tf(v.w);                                 \
        }                                                                          \
        _Pragma("unroll")                                                          \
        for (int i = 0; i < 4; i++) {                                              \
            Bs[buf][Br[i]][Bc[i] + 0] = f2tf(rb[i].x);                             \
            Bs[buf][Br[i]][Bc[i] + 1] = f2tf(rb[i].y);                             \
            Bs[buf][Br[i]][Bc[i] + 2] = f2tf(rb[i].z);                             \
            Bs[buf][Br[i]][Bc[i] + 3] = f2tf(rb[i].w);                             \
        }                                                                          \
    }
#define COMPUTE2(buf)                                                              \
    {                                                                              \
        _Pragma("unroll")                                                          \
        for (int kk = 0; kk < 32; kk += 8) {                                       \
            unsigned a[2][4], b[8][2];                                             \
            int ar = wm * 32 + (lane >> 2);                                        \
            int ak = kk + (lane & 3);                                              \
            a[0][0] = As[buf][ar][ak];          a[0][1] = As[buf][ar + 8][ak];     \
            a[0][2] = As[buf][ar][ak + 4];      a[0][3] = As[buf][ar + 8][ak + 4]; \
            a[1][0] = As[buf][ar + 16][ak];     a[1][1] = As[buf][ar + 24][ak];    \
            a[1][2] = As[buf][ar + 16][ak + 4]; a[1][3] = As[buf][ar + 24][ak + 4];\
            _Pragma("unroll")                                                      \
            for (int j = 0; j < 8; j++) {                                          \
                int col = wn * 64 + j * 8 + (lane >> 2);                           \
                b[j][0] = Bs[buf][kk + (lane & 3)][col];                           \
                b[j][1] = Bs[buf][kk + 4 + (lane & 3)][col];                       \
            }                                                                      \
            _Pragma("unroll")                                                      \
            for (int i = 0; i < 2; i++)                                            \
                _Pragma("unroll")                                                  \
                for (int j = 0; j < 8; j++) mma_tf32(acc[i][j], a[i], b[j]);       \
        }                                                                          \
    }

    LOAD_TILE2(0);
    STORE_TILE2(0, 0);
    __syncthreads();
#pragma unroll
    for (int t = 0; t < 4; t++) {
        if (t < 3) LOAD_TILE2((t + 1) * 32);
        COMPUTE2(t & 1);
        if (t < 3) { STORE_TILE2((t + 1) & 1, (t + 1) * 32); __syncthreads(); }
    }

#pragma unroll
    for (int i = 0; i < 2; i++) {
#pragma unroll
        for (int j = 0; j < 8; j++) {
            int r0 = m0 + wm * 32 + i * 16 + (lane >> 2);
            int cc = wn * 64 + j * 8 + (lane & 3) * 2;
            float* O = (cc < 128) ? XL : XR;
            int c2 = cc & 127;
            const float* bb = (cc < 128) ? bl : br;
            float b0 = bb[c2], b1 = bb[c2 + 1];
            if (r0 < M) {
                O[(size_t)r0 * 128 + c2]     = acc[i][j][0] + b0;
                O[(size_t)r0 * 128 + c2 + 1] = acc[i][j][1] + b1;
            }
            if (r0 + 8 < M) {
                O[(size_t)(r0 + 8) * 128 + c2]     = acc[i][j][2] + b0;
                O[(size_t)(r0 + 8) * 128 + c2 + 1] = acc[i][j][3] + b1;
            }
        }
    }
#undef LOAD_TILE2
#undef STORE_TILE2
#undef COMPUTE2
}

// ---------------- block stat reduce (full block, no early exits) -------
__device__ __forceinline__ void accum_stats(float4 o, int lane, int tid, double* slot)
{
    float s  = o.x + o.y + o.z + o.w;
    float sq = o.x * o.x + o.y * o.y + o.z * o.z + o.w * o.w;
#pragma unroll
    for (int off = 16; off > 0; off >>= 1) {
        s  += __shfl_xor_sync(0xffffffffu, s,  off);
        sq += __shfl_xor_sync(0xffffffffu, sq, off);
    }
    __shared__ float bs[2];
    if (tid == 0) { bs[0] = 0.f; bs[1] = 0.f; }
    __syncthreads();
    if (lane == 0) { atomicAdd(&bs[0], s); atomicAdd(&bs[1], sq); }
    __syncthreads();
    if (tid == 0) {
        int sl = blockIdx.x & (NSLOT - 1);
        atomicAdd(&slot[2 * sl],     (double)bs[0]);
        atomicAdd(&slot[2 * sl + 1], (double)bs[1]);
    }
}

// ---------------- GCN gather (pure sum; xw pre-scaled by dinv[row]) ----------
__global__ void gcn_gather_kernel(const float* __restrict__ xw, const float* __restrict__ bias,
                                  float* __restrict__ out, double* __restrict__ slot)
{
    int tid  = threadIdx.x;
    int lane = tid & 31;
    int n = (blockIdx.x * blockDim.x + tid) >> 5;   // grid exact: NN/8 blocks
    int c = lane * 4;
    float4 acc = *(const float4*)(xw + (size_t)n * 128 + c);  // self (pre-scaled)

    int e = g_ptr[n], end = g_ptr[n + 1];
    for (; e + 3 < end; e += 4) {
        int s0 = g_csr_src[e],     s1 = g_csr_src[e + 1];
        int s2 = g_csr_src[e + 2], s3 = g_csr_src[e + 3];
        float4 v0 = *(const float4*)(xw + (size_t)s0 * 128 + c);
        float4 v1 = *(const float4*)(xw + (size_t)s1 * 128 + c);
        float4 v2 = *(const float4*)(xw + (size_t)s2 * 128 + c);
        float4 v3 = *(const float4*)(xw + (size_t)s3 * 128 + c);
        acc.x += (v0.x + v1.x) + (v2.x + v3.x);
        acc.y += (v0.y + v1.y) + (v2.y + v3.y);
        acc.z += (v0.z + v1.z) + (v2.z + v3.z);
        acc.w += (v0.w + v1.w) + (v2.w + v3.w);
    }
    for (; e < end; e++) {
        int s0 = g_csr_src[e];
        float4 v0 = *(const float4*)(xw + (size_t)s0 * 128 + c);
        acc.x += v0.x; acc.y += v0.y; acc.z += v0.z; acc.w += v0.w;
    }
    float dn = g_dinv[n];
    float4 bv = *(const float4*)(bias + c);
    acc.x = acc.x * dn + bv.x;
    acc.y = acc.y * dn + bv.y;
    acc.z = acc.z * dn + bv.z;
    acc.w = acc.w * dn + bv.w;
    *(float4*)(out + (size_t)n * 128 + c) = acc;
    accum_stats(acc, lane, tid, slot);
}

// ---------------- fused GATv2 gather, online softmax, unroll-2 ----------------
template <int H>
__global__ void gat_gather_kernel(const float* __restrict__ xl, const float* __restrict__ xr,
                                  const float* __restrict__ att, const float* __restrict__ bg,
                                  float* __restrict__ out, double* __restrict__ slot)
{
    int tid  = threadIdx.x;
    int lane = tid & 31;
    int n = (blockIdx.x * blockDim.x + tid) >> 5;
    int c = lane * 4;

    float4 xrd = *(const float4*)(xr + (size_t)n * 128 + c);
    float4 w4  = *(const float4*)(att + c);

    float m = -FLT_MAX, ssum = 0.f;
    float4 acc = make_float4(0.f, 0.f, 0.f, 0.f);

#define GAT_PROC(v)                                                                \
    {                                                                              \
        float p = w4.x * lrelu((v).x + xrd.x) + w4.y * lrelu((v).y + xrd.y)        \
                + w4.z * lrelu((v).z + xrd.z) + w4.w * lrelu((v).w + xrd.w);       \
        _Pragma("unroll")                                                          \
        for (int off = 1; off < 32 / H; off <<= 1)                                 \
            p += __shfl_xor_sync(0xffffffffu, p, off);                             \
        float mn = fmaxf(m, p);                                                    \
        float sc = __expf(m - mn);                                                 \
        float wg = __expf(p - mn);                                                 \
        ssum = ssum * sc + wg;                                                     \
        acc.x = acc.x * sc + wg * (v).x;                                           \
        acc.y = acc.y * sc + wg * (v).y;                                           \
        acc.z = acc.z * sc + wg * (v).z;                                           \
        acc.w = acc.w * sc + wg * (v).w;                                           \
        m = mn;                                                                    \
    }

    // self loop first
    {
        float4 v = *(const float4*)(xl + (size_t)n * 128 + c);
        GAT_PROC(v);
    }
    int e = g_ptr[n], end = g_ptr[n + 1];
    for (; e + 1 < end; e += 2) {
        int s0 = g_csr_src[e], s1 = g_csr_src[e + 1];
        float4 v0 = *(const float4*)(xl + (size_t)s0 * 128 + c);
        float4 v1 = *(const float4*)(xl + (size_t)s1 * 128 + c);
        GAT_PROC(v0);
        GAT_PROC(v1);
    }
    if (e < end) {
        int s0 = g_csr_src[e];
        float4 v0 = *(const float4*)(xl + (size_t)s0 * 128 + c);
        GAT_PROC(v0);
    }
#undef GAT_PROC

    float inv = 1.f / ssum;
    float4 bv = *(const float4*)(bg + c);
    float4 o;
    o.x = acc.x * inv + bv.x;
    o.y = acc.y * inv + bv.y;
    o.z = acc.z * inv + bv.z;
    o.w = acc.w * inv + bv.w;
    *(float4*)(out + (size_t)n * 128 + c) = o;
    accum_stats(o, lane, tid, slot);
}

// ---------------- final LayerNorm ----------------
__global__ void ln_final_kernel(float* __restrict__ x, const float* __restrict__ g,
                                const float* __restrict__ b, const double* __restrict__ slot)
{
    __shared__ float s_mi[2];
    if (threadIdx.x == 0) stats_from_slots(slot, s_mi);
    __syncthreads();
    float mu = s_mi[0], inv = s_mi[1];
    int i = (blockIdx.x * blockDim.x + threadIdx.x) * 4;
    int c = i & 127;
    float4 v  = *(const float4*)(x + i);
    float4 gv = *(const float4*)(g + c);
    float4 bv = *(const float4*)(b + c);
    v.x = (v.x - mu) * inv * gv.x + bv.x;
    v.y = (v.y - mu) * inv * gv.y + bv.y;
    v.z = (v.z - mu) * inv * gv.z + bv.z;
    v.w = (v.w - mu) * inv * gv.w + bv.w;
    *(float4*)(x + i) = v;
}

// ---------------- host orchestration ----------------
extern "C" void kernel_launch(void* const* d_in, const int* in_sizes, int n_in,
                              void* d_out, int out_size)
{
    const float* x    = (const float*)d_in[0];
    const int*   ei   = (const int*)  d_in[1];
    const float* W0   = (const float*)d_in[2];
    const float* b0   = (const float*)d_in[3];
    const float* g0   = (const float*)d_in[4];
    const float* be0  = (const float*)d_in[5];
    const float* Wl1  = (const float*)d_in[6];
    const float* bl1  = (const float*)d_in[7];
    const float* Wr1  = (const float*)d_in[8];
    const float* br1  = (const float*)d_in[9];
    const float* att1 = (const float*)d_in[10];
    const float* bg1  = (const float*)d_in[11];
    const float* g1   = (const float*)d_in[12];
    const float* be1  = (const float*)d_in[13];
    const float* W2   = (const float*)d_in[14];
    const float* b2   = (const float*)d_in[15];
    const float* g2   = (const float*)d_in[16];
    const float* be2  = (const float*)d_in[17];
    const float* Wl3  = (const float*)d_in[18];
    const float* bl3  = (const float*)d_in[19];
    const float* Wr3  = (const float*)d_in[20];
    const float* br3  = (const float*)d_in[21];
    const float* att3 = (const float*)d_in[22];
    const float* bg3  = (const float*)d_in[23];
    const float* g3   = (const float*)d_in[24];
    const float* be3  = (const float*)d_in[25];

    const int* src = ei;
    const int* dst = ei + NE;
    float* out = (float*)d_out;

    float *xw, *h1, *h2, *xl, *xr, *dinv;
    double* st;
    cudaGetSymbolAddress((void**)&xw, g_xw);
    cudaGetSymbolAddress((void**)&h1, g_h1);
    cudaGetSymbolAddress((void**)&h2, g_h2);
    cudaGetSymbolAddress((void**)&xl, g_xl);
    cudaGetSymbolAddress((void**)&xr, g_xr);
    cudaGetSymbolAddress((void**)&dinv, g_dinv);
    cudaGetSymbolAddress((void**)&st, g_stats);
    double* s0 = st;
    double* s1 = st + NSLOT * 2;
    double* s2 = st + NSLOT * 4;
    double* s3 = st + NSLOT * 6;

    cudaFuncSetAttribute(gemm_tf32_kernel,
                         cudaFuncAttributeMaxDynamicSharedMemorySize, GEMM_SMEM);
    cudaFuncSetAttribute(gemm_gat_kernel,
                         cudaFuncAttributeMaxDynamicSharedMemorySize, GEMM2_SMEM);

    const int GEMM_GRID = (NN + 127) / 128;
    const int WARP_GRID = NN / 8;

    // --- CSR build + degrees + zero stats ---
    init_zero_kernel<<<(NN + 255) / 256, 256>>>();
    hist_kernel<<<NE / 256, 256>>>(dst);
    scan_fused_kernel<<<NBLK, 256>>>();
    scatter_kernel<<<NE / 256, 256>>>(src, dst);

    // layer 0: GCN (x raw), xw pre-scaled by dinv -> stats s0
    gemm_tf32_kernel<<<GEMM_GRID, 256, GEMM_SMEM>>>(x, W0, xw, NN, nullptr, nullptr, nullptr, dinv);
    gcn_gather_kernel<<<WARP_GRID, 256>>>(xw, b0, h1, s0);

    // layer 1: GATv2 H=8 (norm s0 + relu on A), merged xl/xr GEMM -> stats s1
    gemm_gat_kernel<<<GEMM_GRID, 512, GEMM2_SMEM>>>(h1, Wl1, bl1, Wr1, br1, xl, xr, NN, g0, be0, s0);
    gat_gather_kernel<8><<<WARP_GRID, 256>>>(xl, xr, att1, bg1, h2, s1);

    // layer 2: GCN (norm s1 + relu on A) -> stats s2
    gemm_tf32_kernel<<<GEMM_GRID, 256, GEMM_SMEM>>>(h2, W2, xw, NN, g1, be1, s1, dinv);
    gcn_gather_kernel<<<WARP_GRID, 256>>>(xw, b2, h1, s2);

    // layer 3: GATv2 H=1 (norm s2 + relu on A) -> stats s3 -> final LN
    gemm_gat_kernel<<<GEMM_GRID, 512, GEMM2_SMEM>>>(h1, Wl3, bl3, Wr3, br3, xl, xr, NN, g2, be2, s2);
    gat_gather_kernel<1><<<WARP_GRID, 256>>>(xl, xr, att3, bg3, out, s3);
    ln_final_kernel<<<TOTF / 1024, 256>>>(out, g3, be3, s3);
}

// round 6
// speedup vs baseline: 3.1156x; 1.0210x over previous
#include <cuda_runtime.h>
#include <math.h>
#include <float.h>

#define NN   50000
#define DD   128
#define NE   800000
#define TOTF (NN * DD)          // 6,400,000
#define NBLK 196                // ceil(NN/256)
#define NSLOT 32

#define GEMM_SMEM  ((2*128*36 + 2*32*132) * 4)   // 70656 bytes
#define GEMM2_SMEM ((2*128*36 + 2*32*260) * 4)   // 103424 bytes

// ---------------- scratch (static device globals only) ----------------
__device__ float  g_xw[TOTF];
__device__ float  g_h1[TOTF];
__device__ float  g_h2[TOTF];
__device__ float  g_xl[TOTF];
__device__ float  g_xr[TOTF];
__device__ float  g_dinv[NN];
__device__ int    g_cnt[NN];
__device__ int    g_ptr[NN + 1];
__device__ int    g_ptr2[NN];
__device__ int    g_csr_src[NE];
__device__ int    g_bsum[NBLK];
__device__ int    g_arrive;
__device__ double g_stats[4][NSLOT * 2];

// ---------------- helpers ----------------
__device__ __forceinline__ float lrelu(float x) { return x > 0.f ? x : 0.2f * x; }

__device__ __forceinline__ unsigned f2tf(float x) {
    unsigned u; asm("cvt.rna.tf32.f32 %0, %1;" : "=r"(u) : "f"(x)); return u;
}

__device__ __forceinline__ void mma_tf32(float* d, const unsigned* a, const unsigned* b) {
    asm volatile("mma.sync.aligned.m16n8k8.row.col.f32.tf32.tf32.f32 "
                 "{%0,%1,%2,%3}, {%4,%5,%6,%7}, {%8,%9}, {%0,%1,%2,%3};"
                 : "+f"(d[0]), "+f"(d[1]), "+f"(d[2]), "+f"(d[3])
                 : "r"(a[0]), "r"(a[1]), "r"(a[2]), "r"(a[3]),
                   "r"(b[0]), "r"(b[1]));
}

__device__ __forceinline__ void stats_from_slots(const double* slot, float* mi) {
    double s = 0.0, sq = 0.0;
#pragma unroll
    for (int i = 0; i < NSLOT; i++) { s += slot[2 * i]; sq += slot[2 * i + 1]; }
    double m   = s / (double)TOTF;
    double var = sq / (double)TOTF - m * m;
    mi[0] = (float)m;
    mi[1] = 1.f / ((float)sqrt(fmax(var, 0.0)) + 1e-5f);
}

// ---------------- init / CSR ----------------
__global__ void init_zero_kernel() {
    int i = blockIdx.x * blockDim.x + threadIdx.x;
    if (i < NN) g_cnt[i] = 0;
    if (i < 4 * NSLOT * 2) ((double*)g_stats)[i] = 0.0;
    if (i == 0) g_arrive = 0;
}
__global__ void hist_kernel(const int* __restrict__ dst) {
    int e = blockIdx.x * blockDim.x + threadIdx.x;
    if (e < NE) atomicAdd(&g_cnt[dst[e]], 1);
}
__global__ void scan_fused_kernel() {
    __shared__ int sh[256];
    int b = blockIdx.x;
    int i = b * 256 + threadIdx.x;
    int cnt = (i < NN) ? g_cnt[i] : 0;
    sh[threadIdx.x] = cnt;
    __syncthreads();
#pragma unroll
    for (int off = 1; off < 256; off <<= 1) {
        int t = (threadIdx.x >= off) ? sh[threadIdx.x - off] : 0;
        __syncthreads();
        sh[threadIdx.x] += t;
        __syncthreads();
    }
    int incl = sh[threadIdx.x];
    if (threadIdx.x == 0) {
        g_bsum[b] = sh[255];
        __threadfence();
        atomicAdd(&g_arrive, 1);
        while (atomicAdd(&g_arrive, 0) < NBLK) { }
    }
    __syncthreads();
    int p = 0;
    for (int j = threadIdx.x; j < b; j += 256) p += g_bsum[j];
    sh[threadIdx.x] = p;
    __syncthreads();
#pragma unroll
    for (int o = 128; o > 0; o >>= 1) {
        if (threadIdx.x < o) sh[threadIdx.x] += sh[threadIdx.x + o];
        __syncthreads();
    }
    int base = sh[0];
    if (i < NN) {
        int excl = base + incl - cnt;
        g_ptr[i]  = excl;
        g_ptr2[i] = excl;
        g_dinv[i] = rsqrtf((float)(cnt + 1));
    }
    if (i == 0) g_ptr[NN] = NE;
}
__global__ void scatter_kernel(const int* __restrict__ src, const int* __restrict__ dst) {
    int e = blockIdx.x * blockDim.x + threadIdx.x;
    if (e >= NE) return;
    int pos = atomicAdd(&g_ptr2[dst[e]], 1);
    g_csr_src[pos] = src[e];
}

// ---------------- TF32 GEMM N=128: C = rowscale(r) * (norm_relu(A) @ W) -------
__global__ __launch_bounds__(256, 2)
void gemm_tf32_kernel(const float* __restrict__ A, const float* __restrict__ W,
                      float* __restrict__ C, int M,
                      const float* __restrict__ gamma, const float* __restrict__ beta,
                      const double* __restrict__ slot, const float* __restrict__ rowscale)
{
    extern __shared__ unsigned smem_raw[];
    unsigned (*As)[128][36] = (unsigned (*)[128][36])smem_raw;
    unsigned (*Bs)[32][132] = (unsigned (*)[32][132])(smem_raw + 2 * 128 * 36);
    __shared__ float s_mi[2];

    int tid  = threadIdx.x;
    int wid  = tid >> 5, lane = tid & 31;
    int wm   = wid & 3, wn = wid >> 2;
    int m0   = blockIdx.x * 128;

    if (tid == 0) {
        if (slot) stats_from_slots(slot, s_mi);
        else { s_mi[0] = 0.f; s_mi[1] = 1.f; }
    }
    __syncthreads();
    float mu = s_mi[0], inv = s_mi[1];
    bool donorm = (slot != nullptr);

    float acc[2][8][4];
#pragma unroll
    for (int i = 0; i < 2; i++)
#pragma unroll
        for (int j = 0; j < 8; j++)
#pragma unroll
            for (int q = 0; q < 4; q++) acc[i][j][q] = 0.f;

    int Ar[4], Aq[4], Br[4], Bq[4];
#pragma unroll
    for (int i = 0; i < 4; i++) {
        int lin = tid + i * 256;
        Ar[i] = lin >> 3;  Aq[i] = (lin & 7) * 4;
        Br[i] = lin >> 5;  Bq[i] = (lin & 31) * 4;
    }
    float4 ra[4], rb[4];

#define LOAD_TILE(k0)                                                              \
    {                                                                              \
        _Pragma("unroll")                                                          \
        for (int i = 0; i < 4; i++) {                                              \
            ra[i] = (m0 + Ar[i] < M)                                               \
                ? *(const float4*)(A + (size_t)(m0 + Ar[i]) * 128 + (k0) + Aq[i])  \
                : make_float4(0.f, 0.f, 0.f, 0.f);                                 \
            rb[i] = *(const float4*)(W + (size_t)((k0) + Br[i]) * 128 + Bq[i]);    \
        }                                                                          \
    }
#define STORE_TILE(buf, k0)                                                        \
    {                                                                              \
        _Pragma("unroll")                                                          \
        for (int i = 0; i < 4; i++) {                                              \
            float4 v = ra[i];                                                      \
            if (donorm) {                                                          \
                float4 gv = *(const float4*)(gamma + (k0) + Aq[i]);                \
                float4 bv = *(const float4*)(beta  + (k0) + Aq[i]);                \
                v.x = fmaxf((v.x - mu) * inv * gv.x + bv.x, 0.f);                  \
                v.y = fmaxf((v.y - mu) * inv * gv.y + bv.y, 0.f);                  \
                v.z = fmaxf((v.z - mu) * inv * gv.z + bv.z, 0.f);                  \
                v.w = fmaxf((v.w - mu) * inv * gv.w + bv.w, 0.f);                  \
            }                                                                      \
            As[buf][Ar[i]][Aq[i] + 0] = f2tf(v.x);                                 \
            As[buf][Ar[i]][Aq[i] + 1] = f2tf(v.y);                                 \
            As[buf][Ar[i]][Aq[i] + 2] = f2tf(v.z);                                 \
            As[buf][Ar[i]][Aq[i] + 3] = f2tf(v.w);                                 \
            Bs[buf][Br[i]][Bq[i] + 0] = f2tf(rb[i].x);                             \
            Bs[buf][Br[i]][Bq[i] + 1] = f2tf(rb[i].y);                             \
            Bs[buf][Br[i]][Bq[i] + 2] = f2tf(rb[i].z);                             \
            Bs[buf][Br[i]][Bq[i] + 3] = f2tf(rb[i].w);                             \
        }                                                                          \
    }
#define COMPUTE(buf)                                                               \
    {                                                                              \
        _Pragma("unroll")                                                          \
        for (int kk = 0; kk < 32; kk += 8) {                                       \
            unsigned a[2][4], b[8][2];                                             \
            int ar = wm * 32 + (lane >> 2);                                        \
            int ak = kk + (lane & 3);                                              \
            a[0][0] = As[buf][ar][ak];          a[0][1] = As[buf][ar + 8][ak];     \
            a[0][2] = As[buf][ar][ak + 4];      a[0][3] = As[buf][ar + 8][ak + 4]; \
            a[1][0] = As[buf][ar + 16][ak];     a[1][1] = As[buf][ar + 24][ak];    \
            a[1][2] = As[buf][ar + 16][ak + 4]; a[1][3] = As[buf][ar + 24][ak + 4];\
            _Pragma("unroll")                                                      \
            for (int j = 0; j < 8; j++) {                                          \
                int col = wn * 64 + j * 8 + (lane >> 2);                           \
                b[j][0] = Bs[buf][kk + (lane & 3)][col];                           \
                b[j][1] = Bs[buf][kk + 4 + (lane & 3)][col];                       \
            }                                                                      \
            _Pragma("unroll")                                                      \
            for (int i = 0; i < 2; i++)                                            \
                _Pragma("unroll")                                                  \
                for (int j = 0; j < 8; j++) mma_tf32(acc[i][j], a[i], b[j]);       \
        }                                                                          \
    }

    LOAD_TILE(0);
    STORE_TILE(0, 0);
    __syncthreads();
#pragma unroll
    for (int t = 0; t < 4; t++) {
        if (t < 3) LOAD_TILE((t + 1) * 32);
        COMPUTE(t & 1);
        if (t < 3) { STORE_TILE((t + 1) & 1, (t + 1) * 32); __syncthreads(); }
    }

#pragma unroll
    for (int i = 0; i < 2; i++) {
#pragma unroll
        for (int j = 0; j < 8; j++) {
            int r0 = m0 + wm * 32 + i * 16 + (lane >> 2);
            int cc = wn * 64 + j * 8 + (lane & 3) * 2;
            if (r0 < M) {
                float sc = rowscale ? rowscale[r0] : 1.f;
                C[(size_t)r0 * 128 + cc]     = acc[i][j][0] * sc;
                C[(size_t)r0 * 128 + cc + 1] = acc[i][j][1] * sc;
            }
            if (r0 + 8 < M) {
                float sc = rowscale ? rowscale[r0 + 8] : 1.f;
                C[(size_t)(r0 + 8) * 128 + cc]     = acc[i][j][2] * sc;
                C[(size_t)(r0 + 8) * 128 + cc + 1] = acc[i][j][3] * sc;
            }
        }
    }
#undef LOAD_TILE
#undef STORE_TILE
#undef COMPUTE
}

// ---------------- merged GAT GEMM N=256: xl = nr(A)@Wl+bl, xr = nr(A)@Wr+br ----
__global__ __launch_bounds__(512, 1)
void gemm_gat_kernel(const float* __restrict__ A,
                     const float* __restrict__ Wl, const float* __restrict__ bl,
                     const float* __restrict__ Wr, const float* __restrict__ br,
                     float* __restrict__ XL, float* __restrict__ XR, int M,
                     const float* __restrict__ gamma, const float* __restrict__ beta,
                     const double* __restrict__ slot)
{
    extern __shared__ unsigned smem_raw[];
    unsigned (*As)[128][36] = (unsigned (*)[128][36])smem_raw;
    unsigned (*Bs)[32][260] = (unsigned (*)[32][260])(smem_raw + 2 * 128 * 36);
    __shared__ float s_mi[2];

    int tid  = threadIdx.x;
    int wid  = tid >> 5, lane = tid & 31;
    int wm   = wid & 3, wn = wid >> 2;      // wn 0..3 over 256 cols
    int m0   = blockIdx.x * 128;

    if (tid == 0) {
        if (slot) stats_from_slots(slot, s_mi);
        else { s_mi[0] = 0.f; s_mi[1] = 1.f; }
    }
    __syncthreads();
    float mu = s_mi[0], inv = s_mi[1];
    bool donorm = (slot != nullptr);

    float acc[2][8][4];
#pragma unroll
    for (int i = 0; i < 2; i++)
#pragma unroll
        for (int j = 0; j < 8; j++)
#pragma unroll
            for (int q = 0; q < 4; q++) acc[i][j][q] = 0.f;

    int Ar[2], Aq[2], Br[4], Bc[4];
#pragma unroll
    for (int i = 0; i < 2; i++) {
        int lin = tid + i * 512;
        Ar[i] = lin >> 3;  Aq[i] = (lin & 7) * 4;
    }
#pragma unroll
    for (int i = 0; i < 4; i++) {
        int lin = tid + i * 512;
        Br[i] = lin >> 6;  Bc[i] = (lin & 63) * 4;
    }
    float4 ra[2], rb[4];

#define LOAD_TILE2(k0)                                                             \
    {                                                                              \
        _Pragma("unroll")                                                          \
        for (int i = 0; i < 2; i++)                                                \
            ra[i] = (m0 + Ar[i] < M)                                               \
                ? *(const float4*)(A + (size_t)(m0 + Ar[i]) * 128 + (k0) + Aq[i])  \
                : make_float4(0.f, 0.f, 0.f, 0.f);                                 \
        _Pragma("unroll")                                                          \
        for (int i = 0; i < 4; i++)                                                \
            rb[i] = (Bc[i] < 128)                                                  \
                ? *(const float4*)(Wl + (size_t)((k0) + Br[i]) * 128 + Bc[i])      \
                : *(const float4*)(Wr + (size_t)((k0) + Br[i]) * 128 + Bc[i] - 128);\
    }
#define STORE_TILE2(buf, k0)                                                       \
    {                                                                              \
        _Pragma("unroll")                                                          \
        for (int i = 0; i < 2; i++) {                                              \
            float4 v = ra[i];                                                      \
            if (donorm) {                                                          \
                float4 gv = *(const float4*)(gamma + (k0) + Aq[i]);                \
                float4 bv = *(const float4*)(beta  + (k0) + Aq[i]);                \
                v.x = fmaxf((v.x - mu) * inv * gv.x + bv.x, 0.f);                  \
                v.y = fmaxf((v.y - mu) * inv * gv.y + bv.y, 0.f);                  \
                v.z = fmaxf((v.z - mu) * inv * gv.z + bv.z, 0.f);                  \
                v.w = fmaxf((v.w - mu) * inv * gv.w + bv.w, 0.f);                  \
            }                                                                      \
            As[buf][Ar[i]][Aq[i] + 0] = f2tf(v.x);                                 \
            As[buf][Ar[i]][Aq[i] + 1] = f2tf(v.y);                                 \
            As[buf][Ar[i]][Aq[i] + 2] = f2tf(v.z);                                 \
            As[buf][Ar[i]][Aq[i] + 3] = f2tf(v.w);                                 \
        }                                                                          \
        _Pragma("unroll")                                                          \
        for (int i = 0; i < 4; i++) {                                              \
            Bs[buf][Br[i]][Bc[i] + 0] = f2tf(rb[i].x);                             \
            Bs[buf][Br[i]][Bc[i] + 1] = f2tf(rb[i].y);                             \
            Bs[buf][Br[i]][Bc[i] + 2] = f2tf(rb[i].z);                             \
            Bs[buf][Br[i]][Bc[i] + 3] = f2tf(rb[i].w);                             \
        }                                                                          \
    }
#define COMPUTE2(buf)                                                              \
    {                                                                              \
        _Pragma("unroll")                                                          \
        for (int kk = 0; kk < 32; kk += 8) {                                       \
            unsigned a[2][4], b[8][2];                                             \
            int ar = wm * 32 + (lane >> 2);                                        \
            int ak = kk + (lane & 3);                                              \
            a[0][0] = As[buf][ar][ak];          a[0][1] = As[buf][ar + 8][ak];     \
            a[0][2] = As[buf][ar][ak + 4];      a[0][3] = As[buf][ar + 8][ak + 4]; \
            a[1][0] = As[buf][ar + 16][ak];     a[1][1] = As[buf][ar + 24][ak];    \
            a[1][2] = As[buf][ar + 16][ak + 4]; a[1][3] = As[buf][ar + 24][ak + 4];\
            _Pragma("unroll")                                                      \
            for (int j = 0; j < 8; j++) {                                          \
                int col = wn * 64 + j * 8 + (lane >> 2);                           \
                b[j][0] = Bs[buf][kk + (lane & 3)][col];                           \
                b[j][1] = Bs[buf][kk + 4 + (lane & 3)][col];                       \
            }                                                                      \
            _Pragma("unroll")                                                      \
            for (int i = 0; i < 2; i++)                                            \
                _Pragma("unroll")                                                  \
                for (int j = 0; j < 8; j++) mma_tf32(acc[i][j], a[i], b[j]);       \
        }                                                                          \
    }

    LOAD_TILE2(0);
    STORE_TILE2(0, 0);
    __syncthreads();
#pragma unroll
    for (int t = 0; t < 4; t++) {
        if (t < 3) LOAD_TILE2((t + 1) * 32);
        COMPUTE2(t & 1);
        if (t < 3) { STORE_TILE2((t + 1) & 1, (t + 1) * 32); __syncthreads(); }
    }

#pragma unroll
    for (int i = 0; i < 2; i++) {
#pragma unroll
        for (int j = 0; j < 8; j++) {
            int r0 = m0 + wm * 32 + i * 16 + (lane >> 2);
            int cc = wn * 64 + j * 8 + (lane & 3) * 2;
            float* O = (cc < 128) ? XL : XR;
            int c2 = cc & 127;
            const float* bb = (cc < 128) ? bl : br;
            float b0 = bb[c2], b1 = bb[c2 + 1];
            if (r0 < M) {
                O[(size_t)r0 * 128 + c2]     = acc[i][j][0] + b0;
                O[(size_t)r0 * 128 + c2 + 1] = acc[i][j][1] + b1;
            }
            if (r0 + 8 < M) {
                O[(size_t)(r0 + 8) * 128 + c2]     = acc[i][j][2] + b0;
                O[(size_t)(r0 + 8) * 128 + c2 + 1] = acc[i][j][3] + b1;
            }
        }
    }
#undef LOAD_TILE2
#undef STORE_TILE2
#undef COMPUTE2
}

// ---------------- block stat reduce (full block, no early exits) -------
__device__ __forceinline__ void accum_stats(float4 o, int lane, int tid, double* slot)
{
    float s  = o.x + o.y + o.z + o.w;
    float sq = o.x * o.x + o.y * o.y + o.z * o.z + o.w * o.w;
#pragma unroll
    for (int off = 16; off > 0; off >>= 1) {
        s  += __shfl_xor_sync(0xffffffffu, s,  off);
        sq += __shfl_xor_sync(0xffffffffu, sq, off);
    }
    __shared__ float bs[2];
    if (tid == 0) { bs[0] = 0.f; bs[1] = 0.f; }
    __syncthreads();
    if (lane == 0) { atomicAdd(&bs[0], s); atomicAdd(&bs[1], sq); }
    __syncthreads();
    if (tid == 0) {
        int sl = blockIdx.x & (NSLOT - 1);
        atomicAdd(&slot[2 * sl],     (double)bs[0]);
        atomicAdd(&slot[2 * sl + 1], (double)bs[1]);
    }
}

// ---------------- GCN gather (pure sum; xw pre-scaled by dinv[row]) ----------
__global__ void gcn_gather_kernel(const float* __restrict__ xw, const float* __restrict__ bias,
                                  float* __restrict__ out, double* __restrict__ slot)
{
    int tid  = threadIdx.x;
    int lane = tid & 31;
    int n = (blockIdx.x * blockDim.x + tid) >> 5;   // grid exact: NN/8 blocks
    int c = lane * 4;
    float4 acc = *(const float4*)(xw + (size_t)n * 128 + c);  // self (pre-scaled)

    int e = g_ptr[n], end = g_ptr[n + 1];
    for (; e + 7 < end; e += 8) {
        int s[8];
#pragma unroll
        for (int i = 0; i < 8; i++) s[i] = g_csr_src[e + i];
        float4 v[8];
#pragma unroll
        for (int i = 0; i < 8; i++)
            v[i] = *(const float4*)(xw + (size_t)s[i] * 128 + c);
#pragma unroll
        for (int i = 0; i < 8; i++) {
            acc.x += v[i].x; acc.y += v[i].y; acc.z += v[i].z; acc.w += v[i].w;
        }
    }
    for (; e + 3 < end; e += 4) {
        int s0 = g_csr_src[e],     s1 = g_csr_src[e + 1];
        int s2 = g_csr_src[e + 2], s3 = g_csr_src[e + 3];
        float4 v0 = *(const float4*)(xw + (size_t)s0 * 128 + c);
        float4 v1 = *(const float4*)(xw + (size_t)s1 * 128 + c);
        float4 v2 = *(const float4*)(xw + (size_t)s2 * 128 + c);
        float4 v3 = *(const float4*)(xw + (size_t)s3 * 128 + c);
        acc.x += (v0.x + v1.x) + (v2.x + v3.x);
        acc.y += (v0.y + v1.y) + (v2.y + v3.y);
        acc.z += (v0.z + v1.z) + (v2.z + v3.z);
        acc.w += (v0.w + v1.w) + (v2.w + v3.w);
    }
    for (; e < end; e++) {
        int s0 = g_csr_src[e];
        float4 v0 = *(const float4*)(xw + (size_t)s0 * 128 + c);
        acc.x += v0.x; acc.y += v0.y; acc.z += v0.z; acc.w += v0.w;
    }
    float dn = g_dinv[n];
    float4 bv = *(const float4*)(bias + c);
    acc.x = acc.x * dn + bv.x;
    acc.y = acc.y * dn + bv.y;
    acc.z = acc.z * dn + bv.z;
    acc.w = acc.w * dn + bv.w;
    *(float4*)(out + (size_t)n * 128 + c) = acc;
    accum_stats(acc, lane, tid, slot);
}

// ---------------- fused GATv2 gather, batched online softmax (4 edges/iter) ---
template <int H>
__global__ void gat_gather_kernel(const float* __restrict__ xl, const float* __restrict__ xr,
                                  const float* __restrict__ att, const float* __restrict__ bg,
                                  float* __restrict__ out, double* __restrict__ slot)
{
    int tid  = threadIdx.x;
    int lane = tid & 31;
    int n = (blockIdx.x * blockDim.x + tid) >> 5;
    int c = lane * 4;

    float4 xrd = *(const float4*)(xr + (size_t)n * 128 + c);
    float4 w4  = *(const float4*)(att + c);

    float m = -FLT_MAX, ssum = 0.f;
    float4 acc = make_float4(0.f, 0.f, 0.f, 0.f);

#define GAT_SCORE(v, p)                                                            \
    p = w4.x * lrelu((v).x + xrd.x) + w4.y * lrelu((v).y + xrd.y)                  \
      + w4.z * lrelu((v).z + xrd.z) + w4.w * lrelu((v).w + xrd.w);

#define GAT_PROC1(v)                                                               \
    {                                                                              \
        float p; GAT_SCORE(v, p);                                                  \
        _Pragma("unroll")                                                          \
        for (int off = 1; off < 32 / H; off <<= 1)                                 \
            p += __shfl_xor_sync(0xffffffffu, p, off);                             \
        float mn = fmaxf(m, p);                                                    \
        float sc = __expf(m - mn);                                                 \
        float wg = __expf(p - mn);                                                 \
        ssum = ssum * sc + wg;                                                     \
        acc.x = acc.x * sc + wg * (v).x;                                           \
        acc.y = acc.y * sc + wg * (v).y;                                           \
        acc.z = acc.z * sc + wg * (v).z;                                           \
        acc.w = acc.w * sc + wg * (v).w;                                           \
        m = mn;                                                                    \
    }

    // self loop first
    {
        float4 v = *(const float4*)(xl + (size_t)n * 128 + c);
        GAT_PROC1(v);
    }
    int e = g_ptr[n], end = g_ptr[n + 1];
    // batched: 4 edges per iteration, one accumulator rescale per batch
    for (; e + 3 < end; e += 4) {
        int s0 = g_csr_src[e],     s1 = g_csr_src[e + 1];
        int s2 = g_csr_src[e + 2], s3 = g_csr_src[e + 3];
        float4 v0 = *(const float4*)(xl + (size_t)s0 * 128 + c);
        float4 v1 = *(const float4*)(xl + (size_t)s1 * 128 + c);
        float4 v2 = *(const float4*)(xl + (size_t)s2 * 128 + c);
        float4 v3 = *(const float4*)(xl + (size_t)s3 * 128 + c);
        float p0, p1, p2, p3;
        GAT_SCORE(v0, p0); GAT_SCORE(v1, p1); GAT_SCORE(v2, p2); GAT_SCORE(v3, p3);
#pragma unroll
        for (int off = 1; off < 32 / H; off <<= 1) {   // 4 interleaved trees
            p0 += __shfl_xor_sync(0xffffffffu, p0, off);
            p1 += __shfl_xor_sync(0xffffffffu, p1, off);
            p2 += __shfl_xor_sync(0xffffffffu, p2, off);
            p3 += __shfl_xor_sync(0xffffffffu, p3, off);
        }
        float bm = fmaxf(fmaxf(p0, p1), fmaxf(p2, p3));
        float mn = fmaxf(m, bm);
        float sc = __expf(m - mn);
        float w0 = __expf(p0 - mn), w1 = __expf(p1 - mn);
        float w2 = __expf(p2 - mn), w3 = __expf(p3 - mn);
        ssum = ssum * sc + ((w0 + w1) + (w2 + w3));
        acc.x = acc.x * sc + (w0 * v0.x + w1 * v1.x) + (w2 * v2.x + w3 * v3.x);
        acc.y = acc.y * sc + (w0 * v0.y + w1 * v1.y) + (w2 * v2.y + w3 * v3.y);
        acc.z = acc.z * sc + (w0 * v0.z + w1 * v1.z) + (w2 * v2.z + w3 * v3.z);
        acc.w = acc.w * sc + (w0 * v0.w + w1 * v1.w) + (w2 * v2.w + w3 * v3.w);
        m = mn;
    }
    for (; e < end; e++) {
        int s0 = g_csr_src[e];
        float4 v0 = *(const float4*)(xl + (size_t)s0 * 128 + c);
        GAT_PROC1(v0);
    }
#undef GAT_PROC1
#undef GAT_SCORE

    float inv = 1.f / ssum;
    float4 bv = *(const float4*)(bg + c);
    float4 o;
    o.x = acc.x * inv + bv.x;
    o.y = acc.y * inv + bv.y;
    o.z = acc.z * inv + bv.z;
    o.w = acc.w * inv + bv.w;
    *(float4*)(out + (size_t)n * 128 + c) = o;
    accum_stats(o, lane, tid, slot);
}

// ---------------- final LayerNorm ----------------
__global__ void ln_final_kernel(float* __restrict__ x, const float* __restrict__ g,
                                const float* __restrict__ b, const double* __restrict__ slot)
{
    __shared__ float s_mi[2];
    if (threadIdx.x == 0) stats_from_slots(slot, s_mi);
    __syncthreads();
    float mu = s_mi[0], inv = s_mi[1];
    int i = (blockIdx.x * blockDim.x + threadIdx.x) * 4;
    int c = i & 127;
    float4 v  = *(const float4*)(x + i);
    float4 gv = *(const float4*)(g + c);
    float4 bv = *(const float4*)(b + c);
    v.x = (v.x - mu) * inv * gv.x + bv.x;
    v.y = (v.y - mu) * inv * gv.y + bv.y;
    v.z = (v.z - mu) * inv * gv.z + bv.z;
    v.w = (v.w - mu) * inv * gv.w + bv.w;
    *(float4*)(x + i) = v;
}

// ---------------- host orchestration ----------------
extern "C" void kernel_launch(void* const* d_in, const int* in_sizes, int n_in,
                              void* d_out, int out_size)
{
    const float* x    = (const float*)d_in[0];
    const int*   ei   = (const int*)  d_in[1];
    const float* W0   = (const float*)d_in[2];
    const float* b0   = (const float*)d_in[3];
    const float* g0   = (const float*)d_in[4];
    const float* be0  = (const float*)d_in[5];
    const float* Wl1  = (const float*)d_in[6];
    const float* bl1  = (const float*)d_in[7];
    const float* Wr1  = (const float*)d_in[8];
    const float* br1  = (const float*)d_in[9];
    const float* att1 = (const float*)d_in[10];
    const float* bg1  = (const float*)d_in[11];
    const float* g1   = (const float*)d_in[12];
    const float* be1  = (const float*)d_in[13];
    const float* W2   = (const float*)d_in[14];
    const float* b2   = (const float*)d_in[15];
    const float* g2   = (const float*)d_in[16];
    const float* be2  = (const float*)d_in[17];
    const float* Wl3  = (const float*)d_in[18];
    const float* bl3  = (const float*)d_in[19];
    const float* Wr3  = (const float*)d_in[20];
    const float* br3  = (const float*)d_in[21];
    const float* att3 = (const float*)d_in[22];
    const float* bg3  = (const float*)d_in[23];
    const float* g3   = (const float*)d_in[24];
    const float* be3  = (const float*)d_in[25];

    const int* src = ei;
    const int* dst = ei + NE;
    float* out = (float*)d_out;

    float *xw, *h1, *h2, *xl, *xr, *dinv;
    double* st;
    cudaGetSymbolAddress((void**)&xw, g_xw);
    cudaGetSymbolAddress((void**)&h1, g_h1);
    cudaGetSymbolAddress((void**)&h2, g_h2);
    cudaGetSymbolAddress((void**)&xl, g_xl);
    cudaGetSymbolAddress((void**)&xr, g_xr);
    cudaGetSymbolAddress((void**)&dinv, g_dinv);
    cudaGetSymbolAddress((void**)&st, g_stats);
    double* s0 = st;
    double* s1 = st + NSLOT * 2;
    double* s2 = st + NSLOT * 4;
    double* s3 = st + NSLOT * 6;

    cudaFuncSetAttribute(gemm_tf32_kernel,
                         cudaFuncAttributeMaxDynamicSharedMemorySize, GEMM_SMEM);
    cudaFuncSetAttribute(gemm_gat_kernel,
                         cudaFuncAttributeMaxDynamicSharedMemorySize, GEMM2_SMEM);

    const int GEMM_GRID = (NN + 127) / 128;
    const int WARP_GRID = NN / 8;

    // --- CSR build + degrees + zero stats ---
    init_zero_kernel<<<(NN + 255) / 256, 256>>>();
    hist_kernel<<<NE / 256, 256>>>(dst);
    scan_fused_kernel<<<NBLK, 256>>>();
    scatter_kernel<<<NE / 256, 256>>>(src, dst);

    // layer 0: GCN (x raw), xw pre-scaled by dinv -> stats s0
    gemm_tf32_kernel<<<GEMM_GRID, 256, GEMM_SMEM>>>(x, W0, xw, NN, nullptr, nullptr, nullptr, dinv);
    gcn_gather_kernel<<<WARP_GRID, 256>>>(xw, b0, h1, s0);

    // layer 1: GATv2 H=8 (norm s0 + relu on A), merged xl/xr GEMM -> stats s1
    gemm_gat_kernel<<<GEMM_GRID, 512, GEMM2_SMEM>>>(h1, Wl1, bl1, Wr1, br1, xl, xr, NN, g0, be0, s0);
    gat_gather_kernel<8><<<WARP_GRID, 256>>>(xl, xr, att1, bg1, h2, s1);

    // layer 2: GCN (norm s1 + relu on A) -> stats s2
    gemm_tf32_kernel<<<GEMM_GRID, 256, GEMM_SMEM>>>(h2, W2, xw, NN, g1, be1, s1, dinv);
    gcn_gather_kernel<<<WARP_GRID, 256>>>(xw, b2, h1, s2);

    // layer 3: GATv2 H=1 (norm s2 + relu on A) -> stats s3 -> final LN
    gemm_gat_kernel<<<GEMM_GRID, 512, GEMM2_SMEM>>>(h1, Wl3, bl3, Wr3, br3, xl, xr, NN, g2, be2, s2);
    gat_gather_kernel<1><<<WARP_GRID, 256>>>(xl, xr, att3, bg3, out, s3);
    ln_final_kernel<<<TOTF / 1024, 256>>>(out, g3, be3, s3);
}

// round 7
// speedup vs baseline: 3.3140x; 1.0637x over previous
#include <cuda_runtime.h>
#include <cuda_bf16.h>
#include <math.h>
#include <float.h>

#define NN   50000
#define DD   128
#define NE   800000
#define TOTF (NN * DD)          // 6,400,000
#define NBLK 196                // ceil(NN/256)
#define NSLOT 32

#define GEMM_SMEM  ((2*128*36 + 2*32*132) * 4)   // 70656 bytes
#define GEMM2_SMEM ((2*128*36 + 2*32*260) * 4)   // 103424 bytes

// ---------------- scratch (static device globals only) ----------------
__device__ uint2  g_xwb[TOTF / 4];   // bf16x4 per uint2: GCN gathered features
__device__ uint2  g_xlb[TOTF / 4];   // bf16x4 per uint2: GAT xl features
__device__ float  g_h1[TOTF];
__device__ float  g_h2[TOTF];
__device__ float  g_xr[TOTF];
__device__ float  g_dinv[NN];
__device__ int    g_cnt[NN];
__device__ int    g_ptr[NN + 1];
__device__ int    g_ptr2[NN];
__device__ int    g_csr_src[NE];
__device__ int    g_bsum[NBLK];
__device__ int    g_arrive;
__device__ double g_stats[4][NSLOT * 2];

// ---------------- helpers ----------------
__device__ __forceinline__ float lrelu(float x) { return x > 0.f ? x : 0.2f * x; }

__device__ __forceinline__ unsigned f2tf(float x) {
    unsigned u; asm("cvt.rna.tf32.f32 %0, %1;" : "=r"(u) : "f"(x)); return u;
}

__device__ __forceinline__ unsigned pack_bf2(float a, float b) {
    __nv_bfloat162 h = __floats2bfloat162_rn(a, b);
    return *(unsigned*)&h;
}

__device__ __forceinline__ float4 bf4_to_f4(uint2 u) {
    __nv_bfloat162 a = *(__nv_bfloat162*)&u.x;
    __nv_bfloat162 b = *(__nv_bfloat162*)&u.y;
    return make_float4(__low2float(a), __high2float(a), __low2float(b), __high2float(b));
}

__device__ __forceinline__ void mma_tf32(float* d, const unsigned* a, const unsigned* b) {
    asm volatile("mma.sync.aligned.m16n8k8.row.col.f32.tf32.tf32.f32 "
                 "{%0,%1,%2,%3}, {%4,%5,%6,%7}, {%8,%9}, {%0,%1,%2,%3};"
                 : "+f"(d[0]), "+f"(d[1]), "+f"(d[2]), "+f"(d[3])
                 : "r"(a[0]), "r"(a[1]), "r"(a[2]), "r"(a[3]),
                   "r"(b[0]), "r"(b[1]));
}

__device__ __forceinline__ void stats_from_slots(const double* slot, float* mi) {
    double s = 0.0, sq = 0.0;
#pragma unroll
    for (int i = 0; i < NSLOT; i++) { s += slot[2 * i]; sq += slot[2 * i + 1]; }
    double m   = s / (double)TOTF;
    double var = sq / (double)TOTF - m * m;
    mi[0] = (float)m;
    mi[1] = 1.f / ((float)sqrt(fmax(var, 0.0)) + 1e-5f);
}

// ---------------- init / CSR ----------------
__global__ void init_zero_kernel() {
    int i = blockIdx.x * blockDim.x + threadIdx.x;
    if (i < NN) g_cnt[i] = 0;
    if (i < 4 * NSLOT * 2) ((double*)g_stats)[i] = 0.0;
    if (i == 0) g_arrive = 0;
}
__global__ void hist_kernel(const int* __restrict__ dst) {
    int e = blockIdx.x * blockDim.x + threadIdx.x;
    if (e < NE) atomicAdd(&g_cnt[dst[e]], 1);
}
__global__ void scan_fused_kernel() {
    __shared__ int sh[256];
    int b = blockIdx.x;
    int i = b * 256 + threadIdx.x;
    int cnt = (i < NN) ? g_cnt[i] : 0;
    sh[threadIdx.x] = cnt;
    __syncthreads();
#pragma unroll
    for (int off = 1; off < 256; off <<= 1) {
        int t = (threadIdx.x >= off) ? sh[threadIdx.x - off] : 0;
        __syncthreads();
        sh[threadIdx.x] += t;
        __syncthreads();
    }
    int incl = sh[threadIdx.x];
    if (threadIdx.x == 0) {
        g_bsum[b] = sh[255];
        __threadfence();
        atomicAdd(&g_arrive, 1);
        while (atomicAdd(&g_arrive, 0) < NBLK) { }
    }
    __syncthreads();
    int p = 0;
    for (int j = threadIdx.x; j < b; j += 256) p += g_bsum[j];
    sh[threadIdx.x] = p;
    __syncthreads();
#pragma unroll
    for (int o = 128; o > 0; o >>= 1) {
        if (threadIdx.x < o) sh[threadIdx.x] += sh[threadIdx.x + o];
        __syncthreads();
    }
    int base = sh[0];
    if (i < NN) {
        int excl = base + incl - cnt;
        g_ptr[i]  = excl;
        g_ptr2[i] = excl;
        g_dinv[i] = rsqrtf((float)(cnt + 1));
    }
    if (i == 0) g_ptr[NN] = NE;
}
__global__ void scatter_kernel(const int* __restrict__ src, const int* __restrict__ dst) {
    int e = blockIdx.x * blockDim.x + threadIdx.x;
    if (e >= NE) return;
    int pos = atomicAdd(&g_ptr2[dst[e]], 1);
    g_csr_src[pos] = src[e];
}

// ---------------- TF32 GEMM N=128: Cbf16 = rowscale(r) * (norm_relu(A) @ W) ----
__global__ __launch_bounds__(256, 2)
void gemm_tf32_kernel(const float* __restrict__ A, const float* __restrict__ W,
                      unsigned* __restrict__ Cb, int M,
                      const float* __restrict__ gamma, const float* __restrict__ beta,
                      const double* __restrict__ slot, const float* __restrict__ rowscale)
{
    extern __shared__ unsigned smem_raw[];
    unsigned (*As)[128][36] = (unsigned (*)[128][36])smem_raw;
    unsigned (*Bs)[32][132] = (unsigned (*)[32][132])(smem_raw + 2 * 128 * 36);
    __shared__ float s_mi[2];

    int tid  = threadIdx.x;
    int wid  = tid >> 5, lane = tid & 31;
    int wm   = wid & 3, wn = wid >> 2;
    int m0   = blockIdx.x * 128;

    if (tid == 0) {
        if (slot) stats_from_slots(slot, s_mi);
        else { s_mi[0] = 0.f; s_mi[1] = 1.f; }
    }
    __syncthreads();
    float mu = s_mi[0], inv = s_mi[1];
    bool donorm = (slot != nullptr);

    float acc[2][8][4];
#pragma unroll
    for (int i = 0; i < 2; i++)
#pragma unroll
        for (int j = 0; j < 8; j++)
#pragma unroll
            for (int q = 0; q < 4; q++) acc[i][j][q] = 0.f;

    int Ar[4], Aq[4], Br[4], Bq[4];
#pragma unroll
    for (int i = 0; i < 4; i++) {
        int lin = tid + i * 256;
        Ar[i] = lin >> 3;  Aq[i] = (lin & 7) * 4;
        Br[i] = lin >> 5;  Bq[i] = (lin & 31) * 4;
    }
    float4 ra[4], rb[4];

#define LOAD_TILE(k0)                                                              \
    {                                                                              \
        _Pragma("unroll")                                                          \
        for (int i = 0; i < 4; i++) {                                              \
            ra[i] = (m0 + Ar[i] < M)                                               \
                ? *(const float4*)(A + (size_t)(m0 + Ar[i]) * 128 + (k0) + Aq[i])  \
                : make_float4(0.f, 0.f, 0.f, 0.f);                                 \
            rb[i] = *(const float4*)(W + (size_t)((k0) + Br[i]) * 128 + Bq[i]);    \
        }                                                                          \
    }
#define STORE_TILE(buf, k0)                                                        \
    {                                                                              \
        _Pragma("unroll")                                                          \
        for (int i = 0; i < 4; i++) {                                              \
            float4 v = ra[i];                                                      \
            if (donorm) {                                                          \
                float4 gv = *(const float4*)(gamma + (k0) + Aq[i]);                \
                float4 bv = *(const float4*)(beta  + (k0) + Aq[i]);                \
                v.x = fmaxf((v.x - mu) * inv * gv.x + bv.x, 0.f);                  \
                v.y = fmaxf((v.y - mu) * inv * gv.y + bv.y, 0.f);                  \
                v.z = fmaxf((v.z - mu) * inv * gv.z + bv.z, 0.f);                  \
                v.w = fmaxf((v.w - mu) * inv * gv.w + bv.w, 0.f);                  \
            }                                                                      \
            As[buf][Ar[i]][Aq[i] + 0] = f2tf(v.x);                                 \
            As[buf][Ar[i]][Aq[i] + 1] = f2tf(v.y);                                 \
            As[buf][Ar[i]][Aq[i] + 2] = f2tf(v.z);                                 \
            As[buf][Ar[i]][Aq[i] + 3] = f2tf(v.w);                                 \
            Bs[buf][Br[i]][Bq[i] + 0] = f2tf(rb[i].x);                             \
            Bs[buf][Br[i]][Bq[i] + 1] = f2tf(rb[i].y);                             \
            Bs[buf][Br[i]][Bq[i] + 2] = f2tf(rb[i].z);                             \
            Bs[buf][Br[i]][Bq[i] + 3] = f2tf(rb[i].w);                             \
        }                                                                          \
    }
#define COMPUTE(buf)                                                               \
    {                                                                              \
        _Pragma("unroll")                                                          \
        for (int kk = 0; kk < 32; kk += 8) {                                       \
            unsigned a[2][4], b[8][2];                                             \
            int ar = wm * 32 + (lane >> 2);                                        \
            int ak = kk + (lane & 3);                                              \
            a[0][0] = As[buf][ar][ak];          a[0][1] = As[buf][ar + 8][ak];     \
            a[0][2] = As[buf][ar][ak + 4];      a[0][3] = As[buf][ar + 8][ak + 4]; \
            a[1][0] = As[buf][ar + 16][ak];     a[1][1] = As[buf][ar + 24][ak];    \
            a[1][2] = As[buf][ar + 16][ak + 4]; a[1][3] = As[buf][ar + 24][ak + 4];\
            _Pragma("unroll")                                                      \
            for (int j = 0; j < 8; j++) {                                          \
                int col = wn * 64 + j * 8 + (lane >> 2);                           \
                b[j][0] = Bs[buf][kk + (lane & 3)][col];                           \
                b[j][1] = Bs[buf][kk + 4 + (lane & 3)][col];                       \
            }                                                                      \
            _Pragma("unroll")                                                      \
            for (int i = 0; i < 2; i++)                                            \
                _Pragma("unroll")                                                  \
                for (int j = 0; j < 8; j++) mma_tf32(acc[i][j], a[i], b[j]);       \
        }                                                                          \
    }

    LOAD_TILE(0);
    STORE_TILE(0, 0);
    __syncthreads();
#pragma unroll
    for (int t = 0; t < 4; t++) {
        if (t < 3) LOAD_TILE((t + 1) * 32);
        COMPUTE(t & 1);
        if (t < 3) { STORE_TILE((t + 1) & 1, (t + 1) * 32); __syncthreads(); }
    }

#pragma unroll
    for (int i = 0; i < 2; i++) {
#pragma unroll
        for (int j = 0; j < 8; j++) {
            int r0 = m0 + wm * 32 + i * 16 + (lane >> 2);
            int cc = wn * 64 + j * 8 + (lane & 3) * 2;
            if (r0 < M) {
                float sc = rowscale[r0];
                Cb[(size_t)r0 * 64 + (cc >> 1)] = pack_bf2(acc[i][j][0] * sc, acc[i][j][1] * sc);
            }
            if (r0 + 8 < M) {
                float sc = rowscale[r0 + 8];
                Cb[(size_t)(r0 + 8) * 64 + (cc >> 1)] = pack_bf2(acc[i][j][2] * sc, acc[i][j][3] * sc);
            }
        }
    }
#undef LOAD_TILE
#undef STORE_TILE
#undef COMPUTE
}

// ---------------- merged GAT GEMM N=256: xl(bf16) = nr(A)@Wl+bl, xr(f32) = nr(A)@Wr+br
__global__ __launch_bounds__(512, 1)
void gemm_gat_kernel(const float* __restrict__ A,
                     const float* __restrict__ Wl, const float* __restrict__ bl,
                     const float* __restrict__ Wr, const float* __restrict__ br,
                     unsigned* __restrict__ XLb, float* __restrict__ XR, int M,
                     const float* __restrict__ gamma, const float* __restrict__ beta,
                     const double* __restrict__ slot)
{
    extern __shared__ unsigned smem_raw[];
    unsigned (*As)[128][36] = (unsigned (*)[128][36])smem_raw;
    unsigned (*Bs)[32][260] = (unsigned (*)[32][260])(smem_raw + 2 * 128 * 36);
    __shared__ float s_mi[2];

    int tid  = threadIdx.x;
    int wid  = tid >> 5, lane = tid & 31;
    int wm   = wid & 3, wn = wid >> 2;      // wn 0..3 over 256 cols
    int m0   = blockIdx.x * 128;

    if (tid == 0) {
        if (slot) stats_from_slots(slot, s_mi);
        else { s_mi[0] = 0.f; s_mi[1] = 1.f; }
    }
    __syncthreads();
    float mu = s_mi[0], inv = s_mi[1];
    bool donorm = (slot != nullptr);

    float acc[2][8][4];
#pragma unroll
    for (int i = 0; i < 2; i++)
#pragma unroll
        for (int j = 0; j < 8; j++)
#pragma unroll
            for (int q = 0; q < 4; q++) acc[i][j][q] = 0.f;

    int Ar[2], Aq[2], Br[4], Bc[4];
#pragma unroll
    for (int i = 0; i < 2; i++) {
        int lin = tid + i * 512;
        Ar[i] = lin >> 3;  Aq[i] = (lin & 7) * 4;
    }
#pragma unroll
    for (int i = 0; i < 4; i++) {
        int lin = tid + i * 512;
        Br[i] = lin >> 6;  Bc[i] = (lin & 63) * 4;
    }
    float4 ra[2], rb[4];

#define LOAD_TILE2(k0)                                                             \
    {                                                                              \
        _Pragma("unroll")                                                          \
        for (int i = 0; i < 2; i++)                                                \
            ra[i] = (m0 + Ar[i] < M)                                               \
                ? *(const float4*)(A + (size_t)(m0 + Ar[i]) * 128 + (k0) + Aq[i])  \
                : make_float4(0.f, 0.f, 0.f, 0.f);                                 \
        _Pragma("unroll")                                                          \
        for (int i = 0; i < 4; i++)                                                \
            rb[i] = (Bc[i] < 128)                                                  \
                ? *(const float4*)(Wl + (size_t)((k0) + Br[i]) * 128 + Bc[i])      \
                : *(const float4*)(Wr + (size_t)((k0) + Br[i]) * 128 + Bc[i] - 128);\
    }
#define STORE_TILE2(buf, k0)                                                       \
    {                                                                              \
        _Pragma("unroll")                                                          \
        for (int i = 0; i < 2; i++) {                                              \
            float4 v = ra[i];                                                      \
            if (donorm) {                                                          \
                float4 gv = *(const float4*)(gamma + (k0) + Aq[i]);                \
                float4 bv = *(const float4*)(beta  + (k0) + Aq[i]);                \
                v.x = fmaxf((v.x - mu) * inv * gv.x + bv.x, 0.f);                  \
                v.y = fmaxf((v.y - mu) * inv * gv.y + bv.y, 0.f);                  \
                v.z = fmaxf((v.z - mu) * inv * gv.z + bv.z, 0.f);                  \
                v.w = fmaxf((v.w - mu) * inv * gv.w + bv.w, 0.f);                  \
            }                                                                      \
            As[buf][Ar[i]][Aq[i] + 0] = f2tf(v.x);                                 \
            As[buf][Ar[i]][Aq[i] + 1] = f2tf(v.y);                                 \
            As[buf][Ar[i]][Aq[i] + 2] = f2tf(v.z);                                 \
            As[buf][Ar[i]][Aq[i] + 3] = f2tf(v.w);                                 \
        }                                                                          \
        _Pragma("unroll")                                                          \
        for (int i = 0; i < 4; i++) {                                              \
            Bs[buf][Br[i]][Bc[i] + 0] = f2tf(rb[i].x);                             \
            Bs[buf][Br[i]][Bc[i] + 1] = f2tf(rb[i].y);                             \
            Bs[buf][Br[i]][Bc[i] + 2] = f2tf(rb[i].z);                             \
            Bs[buf][Br[i]][Bc[i] + 3] = f2tf(rb[i].w);                             \
        }                                                                          \
    }
#define COMPUTE2(buf)                                                              \
    {                                                                              \
        _Pragma("unroll")                                                          \
        for (int kk = 0; kk < 32; kk += 8) {                                       \
            unsigned a[2][4], b[8][2];                                             \
            int ar = wm * 32 + (lane >> 2);                                        \
            int ak = kk + (lane & 3);                                              \
            a[0][0] = As[buf][ar][ak];          a[0][1] = As[buf][ar + 8][ak];     \
            a[0][2] = As[buf][ar][ak + 4];      a[0][3] = As[buf][ar + 8][ak + 4]; \
            a[1][0] = As[buf][ar + 16][ak];     a[1][1] = As[buf][ar + 24][ak];    \
            a[1][2] = As[buf][ar + 16][ak + 4]; a[1][3] = As[buf][ar + 24][ak + 4];\
            _Pragma("unroll")                                                      \
            for (int j = 0; j < 8; j++) {                                          \
                int col = wn * 64 + j * 8 + (lane >> 2);                           \
                b[j][0] = Bs[buf][kk + (lane & 3)][col];                           \
                b[j][1] = Bs[buf][kk + 4 + (lane & 3)][col];                       \
            }                                                                      \
            _Pragma("unroll")                                                      \
            for (int i = 0; i < 2; i++)                                            \
                _Pragma("unroll")                                                  \
                for (int j = 0; j < 8; j++) mma_tf32(acc[i][j], a[i], b[j]);       \
        }                                                                          \
    }

    LOAD_TILE2(0);
    STORE_TILE2(0, 0);
    __syncthreads();
#pragma unroll
    for (int t = 0; t < 4; t++) {
        if (t < 3) LOAD_TILE2((t + 1) * 32);
        COMPUTE2(t & 1);
        if (t < 3) { STORE_TILE2((t + 1) & 1, (t + 1) * 32); __syncthreads(); }
    }

#pragma unroll
    for (int i = 0; i < 2; i++) {
#pragma unroll
        for (int j = 0; j < 8; j++) {
            int r0 = m0 + wm * 32 + i * 16 + (lane >> 2);
            int cc = wn * 64 + j * 8 + (lane & 3) * 2;
            int c2 = cc & 127;
            if (cc < 128) {   // xl: bf16 packed
                float b0 = bl[c2], b1 = bl[c2 + 1];
                if (r0 < M)
                    XLb[(size_t)r0 * 64 + (c2 >> 1)] = pack_bf2(acc[i][j][0] + b0, acc[i][j][1] + b1);
                if (r0 + 8 < M)
                    XLb[(size_t)(r0 + 8) * 64 + (c2 >> 1)] = pack_bf2(acc[i][j][2] + b0, acc[i][j][3] + b1);
            } else {          // xr: fp32
                float b0 = br[c2], b1 = br[c2 + 1];
                if (r0 < M) {
                    XR[(size_t)r0 * 128 + c2]     = acc[i][j][0] + b0;
                    XR[(size_t)r0 * 128 + c2 + 1] = acc[i][j][1] + b1;
                }
                if (r0 + 8 < M) {
                    XR[(size_t)(r0 + 8) * 128 + c2]     = acc[i][j][2] + b0;
                    XR[(size_t)(r0 + 8) * 128 + c2 + 1] = acc[i][j][3] + b1;
                }
            }
        }
    }
#undef LOAD_TILE2
#undef STORE_TILE2
#undef COMPUTE2
}

// ---------------- block stat reduce (full block, no early exits) -------
__device__ __forceinline__ void accum_stats(float4 o, int lane, int tid, double* slot)
{
    float s  = o.x + o.y + o.z + o.w;
    float sq = o.x * o.x + o.y * o.y + o.z * o.z + o.w * o.w;
#pragma unroll
    for (int off = 16; off > 0; off >>= 1) {
        s  += __shfl_xor_sync(0xffffffffu, s,  off);
        sq += __shfl_xor_sync(0xffffffffu, sq, off);
    }
    __shared__ float bs[2];
    if (tid == 0) { bs[0] = 0.f; bs[1] = 0.f; }
    __syncthreads();
    if (lane == 0) { atomicAdd(&bs[0], s); atomicAdd(&bs[1], sq); }
    __syncthreads();
    if (tid == 0) {
        int sl = blockIdx.x & (NSLOT - 1);
        atomicAdd(&slot[2 * sl],     (double)bs[0]);
        atomicAdd(&slot[2 * sl + 1], (double)bs[1]);
    }
}

// ---------------- GCN gather (bf16 source, pre-scaled by dinv[row]) ----------
__global__ void gcn_gather_kernel(const float* __restrict__ bias,
                                  float* __restrict__ out, double* __restrict__ slot)
{
    int tid  = threadIdx.x;
    int lane = tid & 31;
    int n = (blockIdx.x * blockDim.x + tid) >> 5;   // grid exact: NN/8 blocks
    int c = lane * 4;

    float4 acc = bf4_to_f4(g_xwb[(size_t)n * 32 + lane]);   // self (pre-scaled)

    int e = g_ptr[n], end = g_ptr[n + 1];
    for (; e + 7 < end; e += 8) {
        int s[8];
#pragma unroll
        for (int i = 0; i < 8; i++) s[i] = g_csr_src[e + i];
        uint2 u[8];
#pragma unroll
        for (int i = 0; i < 8; i++) u[i] = g_xwb[(size_t)s[i] * 32 + lane];
#pragma unroll
        for (int i = 0; i < 8; i++) {
            float4 v = bf4_to_f4(u[i]);
            acc.x += v.x; acc.y += v.y; acc.z += v.z; acc.w += v.w;
        }
    }
    for (; e + 3 < end; e += 4) {
        uint2 u0 = g_xwb[(size_t)g_csr_src[e] * 32 + lane];
        uint2 u1 = g_xwb[(size_t)g_csr_src[e + 1] * 32 + lane];
        uint2 u2 = g_xwb[(size_t)g_csr_src[e + 2] * 32 + lane];
        uint2 u3 = g_xwb[(size_t)g_csr_src[e + 3] * 32 + lane];
        float4 v0 = bf4_to_f4(u0), v1 = bf4_to_f4(u1);
        float4 v2 = bf4_to_f4(u2), v3 = bf4_to_f4(u3);
        acc.x += (v0.x + v1.x) + (v2.x + v3.x);
        acc.y += (v0.y + v1.y) + (v2.y + v3.y);
        acc.z += (v0.z + v1.z) + (v2.z + v3.z);
        acc.w += (v0.w + v1.w) + (v2.w + v3.w);
    }
    for (; e < end; e++) {
        float4 v = bf4_to_f4(g_xwb[(size_t)g_csr_src[e] * 32 + lane]);
        acc.x += v.x; acc.y += v.y; acc.z += v.z; acc.w += v.w;
    }
    float dn = g_dinv[n];
    float4 bv = *(const float4*)(bias + c);
    acc.x = acc.x * dn + bv.x;
    acc.y = acc.y * dn + bv.y;
    acc.z = acc.z * dn + bv.z;
    acc.w = acc.w * dn + bv.w;
    *(float4*)(out + (size_t)n * 128 + c) = acc;
    accum_stats(acc, lane, tid, slot);
}

// ---------------- fused GATv2 gather, bf16 xl, batched online softmax ---------
template <int H>
__global__ void gat_gather_kernel(const float* __restrict__ xr,
                                  const float* __restrict__ att, const float* __restrict__ bg,
                                  float* __restrict__ out, double* __restrict__ slot)
{
    int tid  = threadIdx.x;
    int lane = tid & 31;
    int n = (blockIdx.x * blockDim.x + tid) >> 5;
    int c = lane * 4;

    float4 xrd = *(const float4*)(xr + (size_t)n * 128 + c);
    float4 w4  = *(const float4*)(att + c);

    float m = -FLT_MAX, ssum = 0.f;
    float4 acc = make_float4(0.f, 0.f, 0.f, 0.f);

#define GAT_SCORE(v, p)                                                            \
    p = w4.x * lrelu((v).x + xrd.x) + w4.y * lrelu((v).y + xrd.y)                  \
      + w4.z * lrelu((v).z + xrd.z) + w4.w * lrelu((v).w + xrd.w);

#define GAT_PROC1(v)                                                               \
    {                                                                              \
        float p; GAT_SCORE(v, p);                                                  \
        _Pragma("unroll")                                                          \
        for (int off = 1; off < 32 / H; off <<= 1)                                 \
            p += __shfl_xor_sync(0xffffffffu, p, off);                             \
        float mn = fmaxf(m, p);                                                    \
        float sc = __expf(m - mn);                                                 \
        float wg = __expf(p - mn);                                                 \
        ssum = ssum * sc + wg;                                                     \
        acc.x = acc.x * sc + wg * (v).x;                                           \
        acc.y = acc.y * sc + wg * (v).y;                                           \
        acc.z = acc.z * sc + wg * (v).z;                                           \
        acc.w = acc.w * sc + wg * (v).w;                                           \
        m = mn;                                                                    \
    }

    // self loop first
    {
        float4 v = bf4_to_f4(g_xlb[(size_t)n * 32 + lane]);
        GAT_PROC1(v);
    }
    int e = g_ptr[n], end = g_ptr[n + 1];
    for (; e + 3 < end; e += 4) {
        uint2 u0 = g_xlb[(size_t)g_csr_src[e] * 32 + lane];
        uint2 u1 = g_xlb[(size_t)g_csr_src[e + 1] * 32 + lane];
        uint2 u2 = g_xlb[(size_t)g_csr_src[e + 2] * 32 + lane];
        uint2 u3 = g_xlb[(size_t)g_csr_src[e + 3] * 32 + lane];
        float4 v0 = bf4_to_f4(u0), v1 = bf4_to_f4(u1);
        float4 v2 = bf4_to_f4(u2), v3 = bf4_to_f4(u3);
        float p0, p1, p2, p3;
        GAT_SCORE(v0, p0); GAT_SCORE(v1, p1); GAT_SCORE(v2, p2); GAT_SCORE(v3, p3);
#pragma unroll
        for (int off = 1; off < 32 / H; off <<= 1) {
            p0 += __shfl_xor_sync(0xffffffffu, p0, off);
            p1 += __shfl_xor_sync(0xffffffffu, p1, off);
            p2 += __shfl_xor_sync(0xffffffffu, p2, off);
            p3 += __shfl_xor_sync(0xffffffffu, p3, off);
        }
        float bm = fmaxf(fmaxf(p0, p1), fmaxf(p2, p3));
        float mn = fmaxf(m, bm);
        float sc = __expf(m - mn);
        float w0 = __expf(p0 - mn), w1 = __expf(p1 - mn);
        float w2 = __expf(p2 - mn), w3 = __expf(p3 - mn);
        ssum = ssum * sc + ((w0 + w1) + (w2 + w3));
        acc.x = acc.x * sc + (w0 * v0.x + w1 * v1.x) + (w2 * v2.x + w3 * v3.x);
        acc.y = acc.y * sc + (w0 * v0.y + w1 * v1.y) + (w2 * v2.y + w3 * v3.y);
        acc.z = acc.z * sc + (w0 * v0.z + w1 * v1.z) + (w2 * v2.z + w3 * v3.z);
        acc.w = acc.w * sc + (w0 * v0.w + w1 * v1.w) + (w2 * v2.w + w3 * v3.w);
        m = mn;
    }
    for (; e < end; e++) {
        float4 v = bf4_to_f4(g_xlb[(size_t)g_csr_src[e] * 32 + lane]);
        GAT_PROC1(v);
    }
#undef GAT_PROC1
#undef GAT_SCORE

    float inv = 1.f / ssum;
    float4 bv = *(const float4*)(bg + c);
    float4 o;
    o.x = acc.x * inv + bv.x;
    o.y = acc.y * inv + bv.y;
    o.z = acc.z * inv + bv.z;
    o.w = acc.w * inv + bv.w;
    *(float4*)(out + (size_t)n * 128 + c) = o;
    accum_stats(o, lane, tid, slot);
}

// ---------------- final LayerNorm ----------------
__global__ void ln_final_kernel(float* __restrict__ x, const float* __restrict__ g,
                                const float* __restrict__ b, const double* __restrict__ slot)
{
    __shared__ float s_mi[2];
    if (threadIdx.x == 0) stats_from_slots(slot, s_mi);
    __syncthreads();
    float mu = s_mi[0], inv = s_mi[1];
    int i = (blockIdx.x * blockDim.x + threadIdx.x) * 4;
    int c = i & 127;
    float4 v  = *(const float4*)(x + i);
    float4 gv = *(const float4*)(g + c);
    float4 bv = *(const float4*)(b + c);
    v.x = (v.x - mu) * inv * gv.x + bv.x;
    v.y = (v.y - mu) * inv * gv.y + bv.y;
    v.z = (v.z - mu) * inv * gv.z + bv.z;
    v.w = (v.w - mu) * inv * gv.w + bv.w;
    *(float4*)(x + i) = v;
}

// ---------------- host orchestration ----------------
__device__ float g_ones[NN];           // rowscale of 1.0 for GAT-free path safety
__global__ void ones_kernel() {
    int i = blockIdx.x * blockDim.x + threadIdx.x;
    if (i < NN) g_ones[i] = 1.f;
}

extern "C" void kernel_launch(void* const* d_in, const int* in_sizes, int n_in,
                              void* d_out, int out_size)
{
    const float* x    = (const float*)d_in[0];
    const int*   ei   = (const int*)  d_in[1];
    const float* W0   = (const float*)d_in[2];
    const float* b0   = (const float*)d_in[3];
    const float* g0   = (const float*)d_in[4];
    const float* be0  = (const float*)d_in[5];
    const float* Wl1  = (const float*)d_in[6];
    const float* bl1  = (const float*)d_in[7];
    const float* Wr1  = (const float*)d_in[8];
    const float* br1  = (const float*)d_in[9];
    const float* att1 = (const float*)d_in[10];
    const float* bg1  = (const float*)d_in[11];
    const float* g1   = (const float*)d_in[12];
    const float* be1  = (const float*)d_in[13];
    const float* W2   = (const float*)d_in[14];
    const float* b2   = (const float*)d_in[15];
    const float* g2   = (const float*)d_in[16];
    const float* be2  = (const float*)d_in[17];
    const float* Wl3  = (const float*)d_in[18];
    const float* bl3  = (const float*)d_in[19];
    const float* Wr3  = (const float*)d_in[20];
    const float* br3  = (const float*)d_in[21];
    const float* att3 = (const float*)d_in[22];
    const float* bg3  = (const float*)d_in[23];
    const float* g3   = (const float*)d_in[24];
    const float* be3  = (const float*)d_in[25];

    const int* src = ei;
    const int* dst = ei + NE;
    float* out = (float*)d_out;

    float *h1, *h2, *xr, *dinv;
    unsigned *xwb, *xlb;
    double* st;
    cudaGetSymbolAddress((void**)&xwb, g_xwb);
    cudaGetSymbolAddress((void**)&xlb, g_xlb);
    cudaGetSymbolAddress((void**)&h1, g_h1);
    cudaGetSymbolAddress((void**)&h2, g_h2);
    cudaGetSymbolAddress((void**)&xr, g_xr);
    cudaGetSymbolAddress((void**)&dinv, g_dinv);
    cudaGetSymbolAddress((void**)&st, g_stats);
    double* s0 = st;
    double* s1 = st + NSLOT * 2;
    double* s2 = st + NSLOT * 4;
    double* s3 = st + NSLOT * 6;

    cudaFuncSetAttribute(gemm_tf32_kernel,
                         cudaFuncAttributeMaxDynamicSharedMemorySize, GEMM_SMEM);
    cudaFuncSetAttribute(gemm_gat_kernel,
                         cudaFuncAttributeMaxDynamicSharedMemorySize, GEMM2_SMEM);

    const int GEMM_GRID = (NN + 127) / 128;
    const int WARP_GRID = NN / 8;

    // --- CSR build + degrees + zero stats ---
    init_zero_kernel<<<(NN + 255) / 256, 256>>>();
    hist_kernel<<<NE / 256, 256>>>(dst);
    scan_fused_kernel<<<NBLK, 256>>>();
    scatter_kernel<<<NE / 256, 256>>>(src, dst);

    // layer 0: GCN (x raw), xw bf16 pre-scaled by dinv -> stats s0
    gemm_tf32_kernel<<<GEMM_GRID, 256, GEMM_SMEM>>>(x, W0, xwb, NN, nullptr, nullptr, nullptr, dinv);
    gcn_gather_kernel<<<WARP_GRID, 256>>>(b0, h1, s0);

    // layer 1: GATv2 H=8 (norm s0 + relu on A), merged xl(bf16)/xr GEMM -> stats s1
    gemm_gat_kernel<<<GEMM_GRID, 512, GEMM2_SMEM>>>(h1, Wl1, bl1, Wr1, br1, xlb, xr, NN, g0, be0, s0);
    gat_gather_kernel<8><<<WARP_GRID, 256>>>(xr, att1, bg1, h2, s1);

    // layer 2: GCN (norm s1 + relu on A) -> stats s2
    gemm_tf32_kernel<<<GEMM_GRID, 256, GEMM_SMEM>>>(h2, W2, xwb, NN, g1, be1, s1, dinv);
    gcn_gather_kernel<<<WARP_GRID, 256>>>(b2, h1, s2);

    // layer 3: GATv2 H=1 (norm s2 + relu on A) -> stats s3 -> final LN
    gemm_gat_kernel<<<GEMM_GRID, 512, GEMM2_SMEM>>>(h1, Wl3, bl3, Wr3, br3, xlb, xr, NN, g2, be2, s2);
    gat_gather_kernel<1><<<WARP_GRID, 256>>>(xr, att3, bg3, out, s3);
    ln_final_kernel<<<TOTF / 1024, 256>>>(out, g3, be3, s3);
}

// round 8
// speedup vs baseline: 3.4058x; 1.0277x over previous
#include <cuda_runtime.h>
#include <cuda_bf16.h>
#include <math.h>
#include <float.h>

#define NN   50000
#define DD   128
#define NE   800000
#define TOTF (NN * DD)          // 6,400,000
#define NBLK 196                // ceil(NN/256)
#define NSLOT 32

#define GEMM_SMEM  ((2*128*36 + 2*32*132) * 4)   // 70656 bytes
#define GEMM2_SMEM ((2*128*36 + 2*32*260) * 4)   // 103424 bytes

// ---------------- scratch (static device globals only) ----------------
__device__ uint2  g_xwb[TOTF / 4];   // bf16x4: GCN pre-scaled features (gather src)
__device__ uint2  g_xlb[TOTF / 4];   // bf16x4: GAT xl features (gather src)
__device__ uint2  g_h1b[TOTF / 4];   // bf16x4: hidden 1
__device__ uint2  g_h2b[TOTF / 4];   // bf16x4: hidden 2
__device__ uint2  g_xrb[TOTF / 4];   // bf16x4: GAT xr
__device__ float  g_dinv[NN];
__device__ int    g_cnt[NN];
__device__ int    g_ptr[NN + 1];
__device__ int    g_ptr2[NN];
__device__ int    g_csr_src[NE];
__device__ int    g_bsum[NBLK];
__device__ int    g_arrive;
__device__ double g_stats[4][NSLOT * 2];

// ---------------- helpers ----------------
__device__ __forceinline__ float lrelu(float x) { return x > 0.f ? x : 0.2f * x; }

__device__ __forceinline__ unsigned f2tf(float x) {
    unsigned u; asm("cvt.rna.tf32.f32 %0, %1;" : "=r"(u) : "f"(x)); return u;
}

__device__ __forceinline__ unsigned pack_bf2(float a, float b) {
    __nv_bfloat162 h = __floats2bfloat162_rn(a, b);
    return *(unsigned*)&h;
}

__device__ __forceinline__ uint2 pack_bf4(float4 v) {
    return make_uint2(pack_bf2(v.x, v.y), pack_bf2(v.z, v.w));
}

__device__ __forceinline__ float4 bf4_to_f4(uint2 u) {
    __nv_bfloat162 a = *(__nv_bfloat162*)&u.x;
    __nv_bfloat162 b = *(__nv_bfloat162*)&u.y;
    return make_float4(__low2float(a), __high2float(a), __low2float(b), __high2float(b));
}

__device__ __forceinline__ void mma_tf32(float* d, const unsigned* a, const unsigned* b) {
    asm volatile("mma.sync.aligned.m16n8k8.row.col.f32.tf32.tf32.f32 "
                 "{%0,%1,%2,%3}, {%4,%5,%6,%7}, {%8,%9}, {%0,%1,%2,%3};"
                 : "+f"(d[0]), "+f"(d[1]), "+f"(d[2]), "+f"(d[3])
                 : "r"(a[0]), "r"(a[1]), "r"(a[2]), "r"(a[3]),
                   "r"(b[0]), "r"(b[1]));
}

__device__ __forceinline__ void stats_from_slots(const double* slot, float* mi) {
    double s = 0.0, sq = 0.0;
#pragma unroll
    for (int i = 0; i < NSLOT; i++) { s += slot[2 * i]; sq += slot[2 * i + 1]; }
    double m   = s / (double)TOTF;
    double var = sq / (double)TOTF - m * m;
    mi[0] = (float)m;
    mi[1] = 1.f / ((float)sqrt(fmax(var, 0.0)) + 1e-5f);
}

// ---------------- init / CSR ----------------
__global__ void init_zero_kernel() {
    int i = blockIdx.x * blockDim.x + threadIdx.x;
    if (i < NN) g_cnt[i] = 0;
    if (i < 4 * NSLOT * 2) ((double*)g_stats)[i] = 0.0;
    if (i == 0) g_arrive = 0;
}
__global__ void hist_kernel(const int* __restrict__ dst) {
    int e = blockIdx.x * blockDim.x + threadIdx.x;
    if (e < NE) atomicAdd(&g_cnt[dst[e]], 1);
}
__global__ void scan_fused_kernel() {
    __shared__ int sh[256];
    int b = blockIdx.x;
    int i = b * 256 + threadIdx.x;
    int cnt = (i < NN) ? g_cnt[i] : 0;
    sh[threadIdx.x] = cnt;
    __syncthreads();
#pragma unroll
    for (int off = 1; off < 256; off <<= 1) {
        int t = (threadIdx.x >= off) ? sh[threadIdx.x - off] : 0;
        __syncthreads();
        sh[threadIdx.x] += t;
        __syncthreads();
    }
    int incl = sh[threadIdx.x];
    if (threadIdx.x == 0) {
        g_bsum[b] = sh[255];
        __threadfence();
        atomicAdd(&g_arrive, 1);
        while (atomicAdd(&g_arrive, 0) < NBLK) { }
    }
    __syncthreads();
    int p = 0;
    for (int j = threadIdx.x; j < b; j += 256) p += g_bsum[j];
    sh[threadIdx.x] = p;
    __syncthreads();
#pragma unroll
    for (int o = 128; o > 0; o >>= 1) {
        if (threadIdx.x < o) sh[threadIdx.x] += sh[threadIdx.x + o];
        __syncthreads();
    }
    int base = sh[0];
    if (i < NN) {
        int excl = base + incl - cnt;
        g_ptr[i]  = excl;
        g_ptr2[i] = excl;
        g_dinv[i] = rsqrtf((float)(cnt + 1));
    }
    if (i == 0) g_ptr[NN] = NE;
}
__global__ void scatter_kernel(const int* __restrict__ src, const int* __restrict__ dst) {
    int e = blockIdx.x * blockDim.x + threadIdx.x;
    if (e >= NE) return;
    int pos = atomicAdd(&g_ptr2[dst[e]], 1);
    g_csr_src[pos] = src[e];
}

// ---------------- TF32 GEMM N=128 (A fp32 or bf16): Cbf16 = dinv(r)*(nr(A)@W) --
template <int ABF16>
__global__ __launch_bounds__(256, 2)
void gemm_tf32_kernel(const void* __restrict__ Avoid, const float* __restrict__ W,
                      unsigned* __restrict__ Cb, int M,
                      const float* __restrict__ gamma, const float* __restrict__ beta,
                      const double* __restrict__ slot, const float* __restrict__ rowscale)
{
    extern __shared__ unsigned smem_raw[];
    unsigned (*As)[128][36] = (unsigned (*)[128][36])smem_raw;
    unsigned (*Bs)[32][132] = (unsigned (*)[32][132])(smem_raw + 2 * 128 * 36);
    __shared__ float s_mi[2];
    const float* Af = (const float*)Avoid;
    const uint2* Ab = (const uint2*)Avoid;

    int tid  = threadIdx.x;
    int wid  = tid >> 5, lane = tid & 31;
    int wm   = wid & 3, wn = wid >> 2;
    int m0   = blockIdx.x * 128;

    if (tid == 0) {
        if (slot) stats_from_slots(slot, s_mi);
        else { s_mi[0] = 0.f; s_mi[1] = 1.f; }
    }
    __syncthreads();
    float mu = s_mi[0], inv = s_mi[1];
    bool donorm = (slot != nullptr);

    float acc[2][8][4];
#pragma unroll
    for (int i = 0; i < 2; i++)
#pragma unroll
        for (int j = 0; j < 8; j++)
#pragma unroll
            for (int q = 0; q < 4; q++) acc[i][j][q] = 0.f;

    int Ar[4], Aq[4], Br[4], Bq[4];
#pragma unroll
    for (int i = 0; i < 4; i++) {
        int lin = tid + i * 256;
        Ar[i] = lin >> 3;  Aq[i] = (lin & 7) * 4;
        Br[i] = lin >> 5;  Bq[i] = (lin & 31) * 4;
    }
    float4 ra[4], rb[4];

#define LOAD_TILE(k0)                                                              \
    {                                                                              \
        _Pragma("unroll")                                                          \
        for (int i = 0; i < 4; i++) {                                              \
            if (m0 + Ar[i] < M) {                                                  \
                if (ABF16)                                                         \
                    ra[i] = bf4_to_f4(Ab[(size_t)(m0 + Ar[i]) * 32                 \
                                         + (((k0) + Aq[i]) >> 2)]);                \
                else                                                               \
                    ra[i] = *(const float4*)(Af + (size_t)(m0 + Ar[i]) * 128       \
                                             + (k0) + Aq[i]);                      \
            } else ra[i] = make_float4(0.f, 0.f, 0.f, 0.f);                        \
            rb[i] = *(const float4*)(W + (size_t)((k0) + Br[i]) * 128 + Bq[i]);    \
        }                                                                          \
    }
#define STORE_TILE(buf, k0)                                                        \
    {                                                                              \
        _Pragma("unroll")                                                          \
        for (int i = 0; i < 4; i++) {                                              \
            float4 v = ra[i];                                                      \
            if (donorm) {                                                          \
                float4 gv = *(const float4*)(gamma + (k0) + Aq[i]);                \
                float4 bv = *(const float4*)(beta  + (k0) + Aq[i]);                \
                v.x = fmaxf((v.x - mu) * inv * gv.x + bv.x, 0.f);                  \
                v.y = fmaxf((v.y - mu) * inv * gv.y + bv.y, 0.f);                  \
                v.z = fmaxf((v.z - mu) * inv * gv.z + bv.z, 0.f);                  \
                v.w = fmaxf((v.w - mu) * inv * gv.w + bv.w, 0.f);                  \
            }                                                                      \
            As[buf][Ar[i]][Aq[i] + 0] = f2tf(v.x);                                 \
            As[buf][Ar[i]][Aq[i] + 1] = f2tf(v.y);                                 \
            As[buf][Ar[i]][Aq[i] + 2] = f2tf(v.z);                                 \
            As[buf][Ar[i]][Aq[i] + 3] = f2tf(v.w);                                 \
            Bs[buf][Br[i]][Bq[i] + 0] = f2tf(rb[i].x);                             \
            Bs[buf][Br[i]][Bq[i] + 1] = f2tf(rb[i].y);                             \
            Bs[buf][Br[i]][Bq[i] + 2] = f2tf(rb[i].z);                             \
            Bs[buf][Br[i]][Bq[i] + 3] = f2tf(rb[i].w);                             \
        }                                                                          \
    }
#define COMPUTE(buf)                                                               \
    {                                                                              \
        _Pragma("unroll")                                                          \
        for (int kk = 0; kk < 32; kk += 8) {                                       \
            unsigned a[2][4], b[8][2];                                             \
            int ar = wm * 32 + (lane >> 2);                                        \
            int ak = kk + (lane & 3);                                              \
            a[0][0] = As[buf][ar][ak];          a[0][1] = As[buf][ar + 8][ak];     \
            a[0][2] = As[buf][ar][ak + 4];      a[0][3] = As[buf][ar + 8][ak + 4]; \
            a[1][0] = As[buf][ar + 16][ak];     a[1][1] = As[buf][ar + 24][ak];    \
            a[1][2] = As[buf][ar + 16][ak + 4]; a[1][3] = As[buf][ar + 24][ak + 4];\
            _Pragma("unroll")                                                      \
            for (int j = 0; j < 8; j++) {                                          \
                int col = wn * 64 + j * 8 + (lane >> 2);                           \
                b[j][0] = Bs[buf][kk + (lane & 3)][col];                           \
                b[j][1] = Bs[buf][kk + 4 + (lane & 3)][col];                       \
            }                                                                      \
            _Pragma("unroll")                                                      \
            for (int i = 0; i < 2; i++)                                            \
                _Pragma("unroll")                                                  \
                for (int j = 0; j < 8; j++) mma_tf32(acc[i][j], a[i], b[j]);       \
        }                                                                          \
    }

    LOAD_TILE(0);
    STORE_TILE(0, 0);
    __syncthreads();
#pragma unroll
    for (int t = 0; t < 4; t++) {
        if (t < 3) LOAD_TILE((t + 1) * 32);
        COMPUTE(t & 1);
        if (t < 3) { STORE_TILE((t + 1) & 1, (t + 1) * 32); __syncthreads(); }
    }

#pragma unroll
    for (int i = 0; i < 2; i++) {
#pragma unroll
        for (int j = 0; j < 8; j++) {
            int r0 = m0 + wm * 32 + i * 16 + (lane >> 2);
            int cc = wn * 64 + j * 8 + (lane & 3) * 2;
            if (r0 < M) {
                float sc = rowscale[r0];
                Cb[(size_t)r0 * 64 + (cc >> 1)] = pack_bf2(acc[i][j][0] * sc, acc[i][j][1] * sc);
            }
            if (r0 + 8 < M) {
                float sc = rowscale[r0 + 8];
                Cb[(size_t)(r0 + 8) * 64 + (cc >> 1)] = pack_bf2(acc[i][j][2] * sc, acc[i][j][3] * sc);
            }
        }
    }
#undef LOAD_TILE
#undef STORE_TILE
#undef COMPUTE
}

// ---------------- merged GAT GEMM N=256 (A bf16): xl,xr both bf16 --------------
__global__ __launch_bounds__(512, 1)
void gemm_gat_kernel(const uint2* __restrict__ Ab,
                     const float* __restrict__ Wl, const float* __restrict__ bl,
                     const float* __restrict__ Wr, const float* __restrict__ br,
                     unsigned* __restrict__ XLb, unsigned* __restrict__ XRb, int M,
                     const float* __restrict__ gamma, const float* __restrict__ beta,
                     const double* __restrict__ slot)
{
    extern __shared__ unsigned smem_raw[];
    unsigned (*As)[128][36] = (unsigned (*)[128][36])smem_raw;
    unsigned (*Bs)[32][260] = (unsigned (*)[32][260])(smem_raw + 2 * 128 * 36);
    __shared__ float s_mi[2];

    int tid  = threadIdx.x;
    int wid  = tid >> 5, lane = tid & 31;
    int wm   = wid & 3, wn = wid >> 2;      // wn 0..3 over 256 cols
    int m0   = blockIdx.x * 128;

    if (tid == 0) stats_from_slots(slot, s_mi);
    __syncthreads();
    float mu = s_mi[0], inv = s_mi[1];

    float acc[2][8][4];
#pragma unroll
    for (int i = 0; i < 2; i++)
#pragma unroll
        for (int j = 0; j < 8; j++)
#pragma unroll
            for (int q = 0; q < 4; q++) acc[i][j][q] = 0.f;

    int Ar[2], Aq[2], Br[4], Bc[4];
#pragma unroll
    for (int i = 0; i < 2; i++) {
        int lin = tid + i * 512;
        Ar[i] = lin >> 3;  Aq[i] = (lin & 7) * 4;
    }
#pragma unroll
    for (int i = 0; i < 4; i++) {
        int lin = tid + i * 512;
        Br[i] = lin >> 6;  Bc[i] = (lin & 63) * 4;
    }
    float4 ra[2], rb[4];

#define LOAD_TILE2(k0)                                                             \
    {                                                                              \
        _Pragma("unroll")                                                          \
        for (int i = 0; i < 2; i++)                                                \
            ra[i] = (m0 + Ar[i] < M)                                               \
                ? bf4_to_f4(Ab[(size_t)(m0 + Ar[i]) * 32 + (((k0) + Aq[i]) >> 2)]) \
                : make_float4(0.f, 0.f, 0.f, 0.f);                                 \
        _Pragma("unroll")                                                          \
        for (int i = 0; i < 4; i++)                                                \
            rb[i] = (Bc[i] < 128)                                                  \
                ? *(const float4*)(Wl + (size_t)((k0) + Br[i]) * 128 + Bc[i])      \
                : *(const float4*)(Wr + (size_t)((k0) + Br[i]) * 128 + Bc[i] - 128);\
    }
#define STORE_TILE2(buf, k0)                                                       \
    {                                                                              \
        _Pragma("unroll")                                                          \
        for (int i = 0; i < 2; i++) {                                              \
            float4 v = ra[i];                                                      \
            float4 gv = *(const float4*)(gamma + (k0) + Aq[i]);                    \
            float4 bv = *(const float4*)(beta  + (k0) + Aq[i]);                    \
            v.x = fmaxf((v.x - mu) * inv * gv.x + bv.x, 0.f);                      \
            v.y = fmaxf((v.y - mu) * inv * gv.y + bv.y, 0.f);                      \
            v.z = fmaxf((v.z - mu) * inv * gv.z + bv.z, 0.f);                      \
            v.w = fmaxf((v.w - mu) * inv * gv.w + bv.w, 0.f);                      \
            As[buf][Ar[i]][Aq[i] + 0] = f2tf(v.x);                                 \
            As[buf][Ar[i]][Aq[i] + 1] = f2tf(v.y);                                 \
            As[buf][Ar[i]][Aq[i] + 2] = f2tf(v.z);                                 \
            As[buf][Ar[i]][Aq[i] + 3] = f2tf(v.w);                                 \
        }                                                                          \
        _Pragma("unroll")                                                          \
        for (int i = 0; i < 4; i++) {                                              \
            Bs[buf][Br[i]][Bc[i] + 0] = f2tf(rb[i].x);                             \
            Bs[buf][Br[i]][Bc[i] + 1] = f2tf(rb[i].y);                             \
            Bs[buf][Br[i]][Bc[i] + 2] = f2tf(rb[i].z);                             \
            Bs[buf][Br[i]][Bc[i] + 3] = f2tf(rb[i].w);                             \
        }                                                                          \
    }
#define COMPUTE2(buf)                                                              \
    {                                                                              \
        _Pragma("unroll")                                                          \
        for (int kk = 0; kk < 32; kk += 8) {                                       \
            unsigned a[2][4], b[8][2];                                             \
            int ar = wm * 32 + (lane >> 2);                                        \
            int ak = kk + (lane & 3);                                              \
            a[0][0] = As[buf][ar][ak];          a[0][1] = As[buf][ar + 8][ak];     \
            a[0][2] = As[buf][ar][ak + 4];      a[0][3] = As[buf][ar + 8][ak + 4]; \
            a[1][0] = As[buf][ar + 16][ak];     a[1][1] = As[buf][ar + 24][ak];    \
            a[1][2] = As[buf][ar + 16][ak + 4]; a[1][3] = As[buf][ar + 24][ak + 4];\
            _Pragma("unroll")                                                      \
            for (int j = 0; j < 8; j++) {                                          \
                int col = wn * 64 + j * 8 + (lane >> 2);                           \
                b[j][0] = Bs[buf][kk + (lane & 3)][col];                           \
                b[j][1] = Bs[buf][kk + 4 + (lane & 3)][col];                       \
            }                                                                      \
            _Pragma("unroll")                                                      \
            for (int i = 0; i < 2; i++)                                            \
                _Pragma("unroll")                                                  \
                for (int j = 0; j < 8; j++) mma_tf32(acc[i][j], a[i], b[j]);       \
        }                                                                          \
    }

    LOAD_TILE2(0);
    STORE_TILE2(0, 0);
    __syncthreads();
#pragma unroll
    for (int t = 0; t < 4; t++) {
        if (t < 3) LOAD_TILE2((t + 1) * 32);
        COMPUTE2(t & 1);
        if (t < 3) { STORE_TILE2((t + 1) & 1, (t + 1) * 32); __syncthreads(); }
    }

#pragma unroll
    for (int i = 0; i < 2; i++) {
#pragma unroll
        for (int j = 0; j < 8; j++) {
            int r0 = m0 + wm * 32 + i * 16 + (lane >> 2);
            int cc = wn * 64 + j * 8 + (lane & 3) * 2;
            int c2 = cc & 127;
            unsigned* O = (cc < 128) ? XLb : XRb;
            const float* bb = (cc < 128) ? bl : br;
            float b0 = bb[c2], b1 = bb[c2 + 1];
            if (r0 < M)
                O[(size_t)r0 * 64 + (c2 >> 1)] = pack_bf2(acc[i][j][0] + b0, acc[i][j][1] + b1);
            if (r0 + 8 < M)
                O[(size_t)(r0 + 8) * 64 + (c2 >> 1)] = pack_bf2(acc[i][j][2] + b0, acc[i][j][3] + b1);
        }
    }
#undef LOAD_TILE2
#undef STORE_TILE2
#undef COMPUTE2
}

// ---------------- block stat reduce (full block, no early exits) -------
__device__ __forceinline__ void accum_stats(float4 o, int lane, int tid, double* slot)
{
    float s  = o.x + o.y + o.z + o.w;
    float sq = o.x * o.x + o.y * o.y + o.z * o.z + o.w * o.w;
#pragma unroll
    for (int off = 16; off > 0; off >>= 1) {
        s  += __shfl_xor_sync(0xffffffffu, s,  off);
        sq += __shfl_xor_sync(0xffffffffu, sq, off);
    }
    __shared__ float bs[2];
    if (tid == 0) { bs[0] = 0.f; bs[1] = 0.f; }
    __syncthreads();
    if (lane == 0) { atomicAdd(&bs[0], s); atomicAdd(&bs[1], sq); }
    __syncthreads();
    if (tid == 0) {
        int sl = blockIdx.x & (NSLOT - 1);
        atomicAdd(&slot[2 * sl],     (double)bs[0]);
        atomicAdd(&slot[2 * sl + 1], (double)bs[1]);
    }
}

// ---------------- GCN gather (bf16 in, bf16 out) ----------------
__global__ void gcn_gather_kernel(const float* __restrict__ bias,
                                  uint2* __restrict__ outb, double* __restrict__ slot)
{
    int tid  = threadIdx.x;
    int lane = tid & 31;
    int n = (blockIdx.x * blockDim.x + tid) >> 5;   // grid exact: NN/8 blocks
    int c = lane * 4;

    float4 acc = bf4_to_f4(g_xwb[(size_t)n * 32 + lane]);   // self (pre-scaled)

    int e = g_ptr[n], end = g_ptr[n + 1];
    for (; e + 7 < end; e += 8) {
        int s[8];
#pragma unroll
        for (int i = 0; i < 8; i++) s[i] = g_csr_src[e + i];
        uint2 u[8];
#pragma unroll
        for (int i = 0; i < 8; i++) u[i] = g_xwb[(size_t)s[i] * 32 + lane];
#pragma unroll
        for (int i = 0; i < 8; i++) {
            float4 v = bf4_to_f4(u[i]);
            acc.x += v.x; acc.y += v.y; acc.z += v.z; acc.w += v.w;
        }
    }
    for (; e + 3 < end; e += 4) {
        uint2 u0 = g_xwb[(size_t)g_csr_src[e] * 32 + lane];
        uint2 u1 = g_xwb[(size_t)g_csr_src[e + 1] * 32 + lane];
        uint2 u2 = g_xwb[(size_t)g_csr_src[e + 2] * 32 + lane];
        uint2 u3 = g_xwb[(size_t)g_csr_src[e + 3] * 32 + lane];
        float4 v0 = bf4_to_f4(u0), v1 = bf4_to_f4(u1);
        float4 v2 = bf4_to_f4(u2), v3 = bf4_to_f4(u3);
        acc.x += (v0.x + v1.x) + (v2.x + v3.x);
        acc.y += (v0.y + v1.y) + (v2.y + v3.y);
        acc.z += (v0.z + v1.z) + (v2.z + v3.z);
        acc.w += (v0.w + v1.w) + (v2.w + v3.w);
    }
    for (; e < end; e++) {
        float4 v = bf4_to_f4(g_xwb[(size_t)g_csr_src[e] * 32 + lane]);
        acc.x += v.x; acc.y += v.y; acc.z += v.z; acc.w += v.w;
    }
    float dn = g_dinv[n];
    float4 bv = *(const float4*)(bias + c);
    acc.x = acc.x * dn + bv.x;
    acc.y = acc.y * dn + bv.y;
    acc.z = acc.z * dn + bv.z;
    acc.w = acc.w * dn + bv.w;
    outb[(size_t)n * 32 + lane] = pack_bf4(acc);
    accum_stats(acc, lane, tid, slot);
}

// ---------------- fused GATv2 gather; H=8 -> bf16 out, H=1 -> fp32 out --------
template <int H, int OUTF32>
__global__ void gat_gather_kernel(const float* __restrict__ att, const float* __restrict__ bg,
                                  float* __restrict__ outf, uint2* __restrict__ outb,
                                  double* __restrict__ slot)
{
    int tid  = threadIdx.x;
    int lane = tid & 31;
    int n = (blockIdx.x * blockDim.x + tid) >> 5;
    int c = lane * 4;

    float4 xrd = bf4_to_f4(g_xrb[(size_t)n * 32 + lane]);
    float4 w4  = *(const float4*)(att + c);

    float m = -FLT_MAX, ssum = 0.f;
    float4 acc = make_float4(0.f, 0.f, 0.f, 0.f);

#define GAT_SCORE(v, p)                                                            \
    p = w4.x * lrelu((v).x + xrd.x) + w4.y * lrelu((v).y + xrd.y)                  \
      + w4.z * lrelu((v).z + xrd.z) + w4.w * lrelu((v).w + xrd.w);

#define GAT_PROC1(v)                                                               \
    {                                                                              \
        float p; GAT_SCORE(v, p);                                                  \
        _Pragma("unroll")                                                          \
        for (int off = 1; off < 32 / H; off <<= 1)                                 \
            p += __shfl_xor_sync(0xffffffffu, p, off);                             \
        float mn = fmaxf(m, p);                                                    \
        float sc = __expf(m - mn);                                                 \
        float wg = __expf(p - mn);                                                 \
        ssum = ssum * sc + wg;                                                     \
        acc.x = acc.x * sc + wg * (v).x;                                           \
        acc.y = acc.y * sc + wg * (v).y;                                           \
        acc.z = acc.z * sc + wg * (v).z;                                           \
        acc.w = acc.w * sc + wg * (v).w;                                           \
        m = mn;                                                                    \
    }

    {
        float4 v = bf4_to_f4(g_xlb[(size_t)n * 32 + lane]);   // self loop
        GAT_PROC1(v);
    }
    int e = g_ptr[n], end = g_ptr[n + 1];
    for (; e + 3 < end; e += 4) {
        uint2 u0 = g_xlb[(size_t)g_csr_src[e] * 32 + lane];
        uint2 u1 = g_xlb[(size_t)g_csr_src[e + 1] * 32 + lane];
        uint2 u2 = g_xlb[(size_t)g_csr_src[e + 2] * 32 + lane];
        uint2 u3 = g_xlb[(size_t)g_csr_src[e + 3] * 32 + lane];
        float4 v0 = bf4_to_f4(u0), v1 = bf4_to_f4(u1);
        float4 v2 = bf4_to_f4(u2), v3 = bf4_to_f4(u3);
        float p0, p1, p2, p3;
        GAT_SCORE(v0, p0); GAT_SCORE(v1, p1); GAT_SCORE(v2, p2); GAT_SCORE(v3, p3);
#pragma unroll
        for (int off = 1; off < 32 / H; off <<= 1) {
            p0 += __shfl_xor_sync(0xffffffffu, p0, off);
            p1 += __shfl_xor_sync(0xffffffffu, p1, off);
            p2 += __shfl_xor_sync(0xffffffffu, p2, off);
            p3 += __shfl_xor_sync(0xffffffffu, p3, off);
        }
        float bm = fmaxf(fmaxf(p0, p1), fmaxf(p2, p3));
        float mn = fmaxf(m, bm);
        float sc = __expf(m - mn);
        float w0 = __expf(p0 - mn), w1 = __expf(p1 - mn);
        float w2 = __expf(p2 - mn), w3 = __expf(p3 - mn);
        ssum = ssum * sc + ((w0 + w1) + (w2 + w3));
        acc.x = acc.x * sc + (w0 * v0.x + w1 * v1.x) + (w2 * v2.x + w3 * v3.x);
        acc.y = acc.y * sc + (w0 * v0.y + w1 * v1.y) + (w2 * v2.y + w3 * v3.y);
        acc.z = acc.z * sc + (w0 * v0.z + w1 * v1.z) + (w2 * v2.z + w3 * v3.z);
        acc.w = acc.w * sc + (w0 * v0.w + w1 * v1.w) + (w2 * v2.w + w3 * v3.w);
        m = mn;
    }
    for (; e < end; e++) {
        float4 v = bf4_to_f4(g_xlb[(size_t)g_csr_src[e] * 32 + lane]);
        GAT_PROC1(v);
    }
#undef GAT_PROC1
#undef GAT_SCORE

    float inv = 1.f / ssum;
    float4 bv = *(const float4*)(bg + c);
    float4 o;
    o.x = acc.x * inv + bv.x;
    o.y = acc.y * inv + bv.y;
    o.z = acc.z * inv + bv.z;
    o.w = acc.w * inv + bv.w;
    if (OUTF32) *(float4*)(outf + (size_t)n * 128 + c) = o;
    else        outb[(size_t)n * 32 + lane] = pack_bf4(o);
    accum_stats(o, lane, tid, slot);
}

// ---------------- final LayerNorm ----------------
__global__ void ln_final_kernel(float* __restrict__ x, const float* __restrict__ g,
                                const float* __restrict__ b, const double* __restrict__ slot)
{
    __shared__ float s_mi[2];
    if (threadIdx.x == 0) stats_from_slots(slot, s_mi);
    __syncthreads();
    float mu = s_mi[0], inv = s_mi[1];
    int i = (blockIdx.x * blockDim.x + threadIdx.x) * 4;
    int c = i & 127;
    float4 v  = *(const float4*)(x + i);
    float4 gv = *(const float4*)(g + c);
    float4 bv = *(const float4*)(b + c);
    v.x = (v.x - mu) * inv * gv.x + bv.x;
    v.y = (v.y - mu) * inv * gv.y + bv.y;
    v.z = (v.z - mu) * inv * gv.z + bv.z;
    v.w = (v.w - mu) * inv * gv.w + bv.w;
    *(float4*)(x + i) = v;
}

// ---------------- host orchestration ----------------
extern "C" void kernel_launch(void* const* d_in, const int* in_sizes, int n_in,
                              void* d_out, int out_size)
{
    const float* x    = (const float*)d_in[0];
    const int*   ei   = (const int*)  d_in[1];
    const float* W0   = (const float*)d_in[2];
    const float* b0   = (const float*)d_in[3];
    const float* g0   = (const float*)d_in[4];
    const float* be0  = (const float*)d_in[5];
    const float* Wl1  = (const float*)d_in[6];
    const float* bl1  = (const float*)d_in[7];
    const float* Wr1  = (const float*)d_in[8];
    const float* br1  = (const float*)d_in[9];
    const float* att1 = (const float*)d_in[10];
    const float* bg1  = (const float*)d_in[11];
    const float* g1   = (const float*)d_in[12];
    const float* be1  = (const float*)d_in[13];
    const float* W2   = (const float*)d_in[14];
    const float* b2   = (const float*)d_in[15];
    const float* g2   = (const float*)d_in[16];
    const float* be2  = (const float*)d_in[17];
    const float* Wl3  = (const float*)d_in[18];
    const float* bl3  = (const float*)d_in[19];
    const float* Wr3  = (const float*)d_in[20];
    const float* br3  = (const float*)d_in[21];
    const float* att3 = (const float*)d_in[22];
    const float* bg3  = (const float*)d_in[23];
    const float* g3   = (const float*)d_in[24];
    const float* be3  = (const float*)d_in[25];

    const int* src = ei;
    const int* dst = ei + NE;
    float* out = (float*)d_out;

    float *dinv;
    unsigned *xwb, *xlb;
    uint2 *h1b, *h2b, *xrb;
    double* st;
    cudaGetSymbolAddress((void**)&xwb, g_xwb);
    cudaGetSymbolAddress((void**)&xlb, g_xlb);
    cudaGetSymbolAddress((void**)&h1b, g_h1b);
    cudaGetSymbolAddress((void**)&h2b, g_h2b);
    cudaGetSymbolAddress((void**)&xrb, g_xrb);
    cudaGetSymbolAddress((void**)&dinv, g_dinv);
    cudaGetSymbolAddress((void**)&st, g_stats);
    double* s0 = st;
    double* s1 = st + NSLOT * 2;
    double* s2 = st + NSLOT * 4;
    double* s3 = st + NSLOT * 6;

    cudaFuncSetAttribute(gemm_tf32_kernel<0>,
                         cudaFuncAttributeMaxDynamicSharedMemorySize, GEMM_SMEM);
    cudaFuncSetAttribute(gemm_tf32_kernel<1>,
                         cudaFuncAttributeMaxDynamicSharedMemorySize, GEMM_SMEM);
    cudaFuncSetAttribute(gemm_gat_kernel,
                         cudaFuncAttributeMaxDynamicSharedMemorySize, GEMM2_SMEM);

    const int GEMM_GRID = (NN + 127) / 128;
    const int WARP_GRID = NN / 8;

    // --- CSR build + degrees + zero stats ---
    init_zero_kernel<<<(NN + 255) / 256, 256>>>();
    hist_kernel<<<NE / 256, 256>>>(dst);
    scan_fused_kernel<<<NBLK, 256>>>();
    scatter_kernel<<<NE / 256, 256>>>(src, dst);

    // layer 0: GCN (x fp32), xw bf16 pre-scaled by dinv -> h1 bf16, stats s0
    gemm_tf32_kernel<0><<<GEMM_GRID, 256, GEMM_SMEM>>>(x, W0, xwb, NN, nullptr, nullptr, nullptr, dinv);
    gcn_gather_kernel<<<WARP_GRID, 256>>>(b0, h1b, s0);

    // layer 1: GATv2 H=8 (norm s0 + relu), xl/xr bf16 -> h2 bf16, stats s1
    gemm_gat_kernel<<<GEMM_GRID, 512, GEMM2_SMEM>>>(h1b, Wl1, bl1, Wr1, br1,
                                                    (unsigned*)xlb, (unsigned*)xrb, NN, g0, be0, s0);
    gat_gather_kernel<8, 0><<<WARP_GRID, 256>>>(att1, bg1, nullptr, h2b, s1);

    // layer 2: GCN (norm s1 + relu, A bf16) -> h1 bf16, stats s2
    gemm_tf32_kernel<1><<<GEMM_GRID, 256, GEMM_SMEM>>>(h2b, W2, xwb, NN, g1, be1, s1, dinv);
    gcn_gather_kernel<<<WARP_GRID, 256>>>(b2, h1b, s2);

    // layer 3: GATv2 H=1 (norm s2 + relu, A bf16) -> out fp32, stats s3 -> final LN
    gemm_gat_kernel<<<GEMM_GRID, 512, GEMM2_SMEM>>>(h1b, Wl3, bl3, Wr3, br3,
                                                    (unsigned*)xlb, (unsigned*)xrb, NN, g2, be2, s2);
    gat_gather_kernel<1, 1><<<WARP_GRID, 256>>>(att3, bg3, out, nullptr, s3);
    ln_final_kernel<<<TOTF / 1024, 256>>>(out, g3, be3, s3);
}